// round 2
// baseline (speedup 1.0000x reference)
#include <cuda_runtime.h>
#include <math.h>

#define Bb   4
#define Ss   2048
#define Hh   1024
#define Mm   512
#define NHn  16
#define HDd  64
#define HQq  256
#define ROWS   (Bb*Ss)    /* 8192 */
#define KVROWS (Bb*Mm)    /* 2048 */

// ---------------- scratch (device globals; no allocations) ----------------
__device__ float g_Q  [ROWS*Hh];
__device__ float g_K  [KVROWS*Hh];
__device__ float g_V  [KVROWS*Hh];
__device__ float g_att[ROWS*Hh];
__device__ float g_cmb[(size_t)ROWS*2*Hh];
__device__ float g_h1 [ROWS*Hh];
__device__ float g_t2 [ROWS*Hh];
__device__ float g_gg [ROWS*Hh];
__device__ float g_gate[ROWS];

__device__ __forceinline__ float gelu_exact(float x){
    return 0.5f*x*(1.0f + erff(x*0.70710678118654752f));
}

// ---------------- generic fp32 GEMM: C = act(A@W + bias) ----------------
// A: Mr x K row-major, W: K x N row-major, tile 128x128x16, 256 thr, 8x8 micro
__global__ void __launch_bounds__(256,2) sgemm_bias(
    const float* __restrict__ A, const float* __restrict__ Wm,
    const float* __restrict__ bias, float* __restrict__ C,
    int Mr, int K, int N, int act)
{
    __shared__ float As[16][132];
    __shared__ float Bs2[16][128];
    int t = threadIdx.x;
    int bn = blockIdx.x, bm = blockIdx.y;
    int row0 = (t>>4)*8, col0 = (t&15)*8;
    const float* Ab = A + (size_t)bm*128*K;
    const float* Wb = Wm + bn*128;
    float acc[8][8];
#pragma unroll
    for (int i=0;i<8;i++)
#pragma unroll
        for (int j=0;j<8;j++) acc[i][j]=0.f;

    for (int kt=0; kt<K; kt+=16){
#pragma unroll
        for (int i=0;i<8;i++){
            int e = i*256 + t;
            int r = e>>4, kk = e&15;
            As[kk][r] = Ab[(size_t)r*K + kt + kk];
        }
#pragma unroll
        for (int i=0;i<8;i++){
            int e = i*256 + t;
            int kk = e>>7, c = e&127;
            Bs2[kk][c] = Wb[(size_t)(kt+kk)*N + c];
        }
        __syncthreads();
#pragma unroll
        for (int kk=0;kk<16;kk++){
            float a[8], bf[8];
            *(float4*)(a)    = *(const float4*)&As[kk][row0];
            *(float4*)(a+4)  = *(const float4*)&As[kk][row0+4];
            *(float4*)(bf)   = *(const float4*)&Bs2[kk][col0];
            *(float4*)(bf+4) = *(const float4*)&Bs2[kk][col0+4];
#pragma unroll
            for (int i=0;i<8;i++)
#pragma unroll
                for (int j=0;j<8;j++) acc[i][j] = fmaf(a[i], bf[j], acc[i][j]);
        }
        __syncthreads();
    }
#pragma unroll
    for (int i=0;i<8;i++){
        size_t r = (size_t)bm*128 + row0 + i;
#pragma unroll
        for (int j=0;j<8;j++){
            int c = bn*128 + col0 + j;
            float v = acc[i][j] + bias[c];
            if (act==1) v = gelu_exact(v);
            C[r*N + c] = v;
        }
    }
}

// ---------------- attention ----------------
// block = (batch b, 32-query tile). Loops all 16 heads internally so the
// head-mean (mem_attn) accumulates in smem without atomics.
#define ST  32
#define MCH 128
#define ATT_SMEM_FLOATS 51968   /* 207,872 bytes */

__global__ void __launch_bounds__(256,1) attn_kernel(
    const float* __restrict__ Q, const float* __restrict__ Kb, const float* __restrict__ Vb,
    const int* __restrict__ mask, float* __restrict__ att, float* __restrict__ mem_attn)
{
    extern __shared__ float sm[];
    float* qs   = sm;            // [32][64]
    float* kT   = sm + 2048;     // [64][132] transposed K chunk
    float* vs   = sm + 10496;    // [128][64]
    float* lg   = sm + 18688;    // [32][512] logits -> weights
    float* macc = sm + 35072;    // [32][512] head-sum of weights
    int*   msk  = (int*)(sm + 51456);

    int b  = blockIdx.x >> 6;    // S/ST = 64 tiles per batch
    int st = blockIdx.x & 63;
    int s0 = st * ST;
    int t  = threadIdx.x;

    for (int i=t;i<Mm;i+=256)     msk[i] = mask[b*Mm + i];
    for (int i=t;i<ST*Mm;i+=256)  macc[i] = 0.f;

    for (int n=0;n<NHn;n++){
        __syncthreads();
        // load Q tile for head n
        for (int i=t;i<ST*64;i+=256){
            int q=i>>6, d=i&63;
            qs[q*64+d] = Q[((size_t)(b*Ss + s0 + q))*Hh + n*64 + d];
        }
        int qg = t>>5, mg = t&31;
        int q0 = qg*4, m0 = mg*4;
        // logits: 32x512 in 4 chunks of 128 m
        for (int mc=0;mc<4;mc++){
            __syncthreads();
            for (int i=t;i<MCH*64;i+=256){
                int m=i>>6, d=i&63;
                kT[d*132+m] = Kb[((size_t)(b*Mm + mc*MCH + m))*Hh + n*64 + d];
            }
            __syncthreads();
            float acc[4][4];
#pragma unroll
            for (int i=0;i<4;i++)
#pragma unroll
                for (int j=0;j<4;j++) acc[i][j]=0.f;
#pragma unroll 4
            for (int d=0;d<64;d++){
                float4 kv = *(const float4*)&kT[d*132 + m0];
                float q0v = qs[(q0+0)*64+d];
                float q1v = qs[(q0+1)*64+d];
                float q2v = qs[(q0+2)*64+d];
                float q3v = qs[(q0+3)*64+d];
                acc[0][0]=fmaf(q0v,kv.x,acc[0][0]); acc[0][1]=fmaf(q0v,kv.y,acc[0][1]);
                acc[0][2]=fmaf(q0v,kv.z,acc[0][2]); acc[0][3]=fmaf(q0v,kv.w,acc[0][3]);
                acc[1][0]=fmaf(q1v,kv.x,acc[1][0]); acc[1][1]=fmaf(q1v,kv.y,acc[1][1]);
                acc[1][2]=fmaf(q1v,kv.z,acc[1][2]); acc[1][3]=fmaf(q1v,kv.w,acc[1][3]);
                acc[2][0]=fmaf(q2v,kv.x,acc[2][0]); acc[2][1]=fmaf(q2v,kv.y,acc[2][1]);
                acc[2][2]=fmaf(q2v,kv.z,acc[2][2]); acc[2][3]=fmaf(q2v,kv.w,acc[2][3]);
                acc[3][0]=fmaf(q3v,kv.x,acc[3][0]); acc[3][1]=fmaf(q3v,kv.y,acc[3][1]);
                acc[3][2]=fmaf(q3v,kv.z,acc[3][2]); acc[3][3]=fmaf(q3v,kv.w,acc[3][3]);
            }
#pragma unroll
            for (int i=0;i<4;i++)
#pragma unroll
                for (int j=0;j<4;j++)
                    lg[(q0+i)*Mm + mc*MCH + m0 + j] = acc[i][j]*0.125f;  // 1/sqrt(64)
        }
        __syncthreads();
        // masked softmax per row; accumulate head-mean. (surprise branch is an
        // exact algebraic no-op: uniform rescale + renormalize == identity)
        {
            int w = t>>5, lane = t&31;
            for (int q=w; q<ST; q+=8){
                float* row = &lg[q*Mm];
                float mx = -1e30f;
                for (int m=lane;m<Mm;m+=32) if (msk[m]!=0) mx = fmaxf(mx, row[m]);
#pragma unroll
                for (int o=16;o;o>>=1) mx = fmaxf(mx, __shfl_xor_sync(0xffffffffu,mx,o));
                float ssum = 0.f;
                for (int m=lane;m<Mm;m+=32){
                    float wv = (msk[m]!=0) ? expf(row[m]-mx) : 0.f;
                    row[m]=wv; ssum += wv;
                }
#pragma unroll
                for (int o=16;o;o>>=1) ssum += __shfl_xor_sync(0xffffffffu,ssum,o);
                float inv = 1.0f/ssum;
                for (int m=lane;m<Mm;m+=32){
                    float wv = row[m]*inv;
                    row[m]=wv;
                    macc[q*Mm+m] += wv;
                }
            }
        }
        // attended = weights @ V_head : thread owns (q, 8 consecutive d)
        int q  = t>>3;
        int d0 = (t&7)*8;
        float a8[8];
#pragma unroll
        for (int j=0;j<8;j++) a8[j]=0.f;
        for (int mc=0;mc<4;mc++){
            __syncthreads();
            for (int i=t;i<MCH*64;i+=256){
                int m=i>>6, d=i&63;
                vs[m*64+d] = Vb[((size_t)(b*Mm + mc*MCH + m))*Hh + n*64 + d];
            }
            __syncthreads();
            const float* wrow = &lg[q*Mm + mc*MCH];
#pragma unroll 4
            for (int m=0;m<MCH;m++){
                float wv = wrow[m];
                float4 v0 = *(const float4*)&vs[m*64 + d0];
                float4 v1 = *(const float4*)&vs[m*64 + d0 + 4];
                a8[0]=fmaf(wv,v0.x,a8[0]); a8[1]=fmaf(wv,v0.y,a8[1]);
                a8[2]=fmaf(wv,v0.z,a8[2]); a8[3]=fmaf(wv,v0.w,a8[3]);
                a8[4]=fmaf(wv,v1.x,a8[4]); a8[5]=fmaf(wv,v1.y,a8[5]);
                a8[6]=fmaf(wv,v1.z,a8[6]); a8[7]=fmaf(wv,v1.w,a8[7]);
            }
        }
        size_t base = ((size_t)(b*Ss + s0 + q))*Hh + n*64 + d0;
#pragma unroll
        for (int j=0;j<8;j++) att[base+j] = a8[j];
    }
    __syncthreads();
    for (int i=t;i<ST*Mm;i+=256){
        int q = i>>9, m = i&511;
        mem_attn[((size_t)(b*Ss + s0 + q))*Mm + m] = macc[i]*(1.0f/16.0f);
    }
}

// ---------------- concat [hidden | attended] ----------------
__global__ void concat_kernel(const float4* __restrict__ h, const float4* __restrict__ a,
                              float4* __restrict__ c)
{
    int i = blockIdx.x*256 + threadIdx.x;   // ROWS*512 float4 total
    int r = i >> 9;
    int cc = i & 511;
    c[i] = (cc < 256) ? h[(size_t)r*256 + cc] : a[(size_t)r*256 + (cc-256)];
}

// ---------------- gate = sigmoid(gg @ Wg2 + bg2), one warp per row ----------------
__global__ void gate_kernel(const float* __restrict__ gg, const float* __restrict__ Wg2,
                            const float* __restrict__ bg2, float* __restrict__ gate)
{
    int r = blockIdx.x*8 + (threadIdx.x>>5);
    int lane = threadIdx.x & 31;
    const float* row = gg + (size_t)r*Hh;
    float s = 0.f;
    for (int i=lane;i<Hh;i+=32) s = fmaf(row[i], Wg2[i], s);
#pragma unroll
    for (int o=16;o;o>>=1) s += __shfl_xor_sync(0xffffffffu,s,o);
    if (lane==0) gate[r] = 1.0f/(1.0f + expf(-(s + bg2[0])));
}

// ---------------- fused layernorm + gated residual mix ----------------
__global__ void ln_combine_kernel(
    const float* __restrict__ t2, const float* __restrict__ lng, const float* __restrict__ lnb,
    const float* __restrict__ gate, const float* __restrict__ hidden, float* __restrict__ out)
{
    __shared__ float red[8];
    int r = blockIdx.x;
    int t = threadIdx.x;
    const float* row = t2 + (size_t)r*Hh;
    float x[4];
#pragma unroll
    for (int j=0;j<4;j++) x[j] = row[t + 256*j];
    float s = x[0]+x[1]+x[2]+x[3];
#pragma unroll
    for (int o=16;o;o>>=1) s += __shfl_xor_sync(0xffffffffu,s,o);
    if ((t&31)==0) red[t>>5] = s;
    __syncthreads();
    float mu = (red[0]+red[1]+red[2]+red[3]+red[4]+red[5]+red[6]+red[7]) * (1.0f/Hh);
    __syncthreads();
    float s2 = 0.f;
#pragma unroll
    for (int j=0;j<4;j++){ float d = x[j]-mu; s2 = fmaf(d,d,s2); }
#pragma unroll
    for (int o=16;o;o>>=1) s2 += __shfl_xor_sync(0xffffffffu,s2,o);
    if ((t&31)==0) red[t>>5] = s2;
    __syncthreads();
    float var = (red[0]+red[1]+red[2]+red[3]+red[4]+red[5]+red[6]+red[7]) * (1.0f/Hh);
    float rs = rsqrtf(var + 1e-5f);
    float gt = gate[r];
    const float* hrow = hidden + (size_t)r*Hh;
#pragma unroll
    for (int j=0;j<4;j++){
        int idx = t + 256*j;
        float f = (x[j]-mu)*rs*lng[idx] + lnb[idx];
        out[(size_t)r*Hh + idx] = gt*f + (1.0f-gt)*hrow[idx];
    }
}

// ---------------- launch ----------------
extern "C" void kernel_launch(void* const* d_in, const int* in_sizes, int n_in,
                              void* d_out, int out_size)
{
    (void)in_sizes; (void)n_in; (void)out_size;
    const float* hidden = (const float*)d_in[0];
    const float* memory = (const float*)d_in[1];
    const int*   mask   = (const int*)  d_in[2];
    /* d_in[3] surprise_score: provably a no-op (uniform softmax rescale) */
    const float* Wq  = (const float*)d_in[4];
    const float* bq  = (const float*)d_in[5];
    const float* Wk  = (const float*)d_in[6];
    const float* bk  = (const float*)d_in[7];
    const float* Wv  = (const float*)d_in[8];
    const float* bv  = (const float*)d_in[9];
    const float* W1  = (const float*)d_in[10];
    const float* b1  = (const float*)d_in[11];
    const float* W2  = (const float*)d_in[12];
    const float* b2  = (const float*)d_in[13];
    const float* lng = (const float*)d_in[14];
    const float* lnb = (const float*)d_in[15];
    const float* Wg1 = (const float*)d_in[16];
    const float* bg1 = (const float*)d_in[17];
    const float* Wg2 = (const float*)d_in[18];
    const float* bg2 = (const float*)d_in[19];

    float *pQ,*pK,*pV,*pAtt,*pCmb,*pH1,*pT2,*pGG,*pGate;
    cudaGetSymbolAddress((void**)&pQ,   g_Q);
    cudaGetSymbolAddress((void**)&pK,   g_K);
    cudaGetSymbolAddress((void**)&pV,   g_V);
    cudaGetSymbolAddress((void**)&pAtt, g_att);
    cudaGetSymbolAddress((void**)&pCmb, g_cmb);
    cudaGetSymbolAddress((void**)&pH1,  g_h1);
    cudaGetSymbolAddress((void**)&pT2,  g_t2);
    cudaGetSymbolAddress((void**)&pGG,  g_gg);
    cudaGetSymbolAddress((void**)&pGate,g_gate);

    float* out      = (float*)d_out;
    float* mem_attn = out + (size_t)ROWS*Hh;

    dim3 blk(256);

    // projections
    sgemm_bias<<<dim3(8,64), blk>>>(hidden, Wq, bq, pQ, ROWS,   Hh,  Hh, 0);
    sgemm_bias<<<dim3(8,16), blk>>>(memory, Wk, bk, pK, KVROWS, HQq, Hh, 0);
    sgemm_bias<<<dim3(8,16), blk>>>(memory, Wv, bv, pV, KVROWS, HQq, Hh, 0);

    // attention (+ mem_attn written straight to output buffer)
    cudaFuncSetAttribute(attn_kernel, cudaFuncAttributeMaxDynamicSharedMemorySize,
                         ATT_SMEM_FLOATS*4);
    attn_kernel<<<Bb*64, blk, ATT_SMEM_FLOATS*4>>>(pQ, pK, pV, mask, pAtt, mem_attn);

    // MLP path
    concat_kernel<<<16384, blk>>>((const float4*)hidden, (const float4*)pAtt, (float4*)pCmb);
    sgemm_bias<<<dim3(8,64), blk>>>(pCmb, W1,  b1,  pH1, ROWS, 2*Hh, Hh, 1); // gelu fused
    sgemm_bias<<<dim3(8,64), blk>>>(pH1,  W2,  b2,  pT2, ROWS, Hh,   Hh, 0);
    sgemm_bias<<<dim3(8,64), blk>>>(pCmb, Wg1, bg1, pGG, ROWS, 2*Hh, Hh, 1); // gelu fused

    // gate + final layernorm/mix
    gate_kernel<<<1024, blk>>>(pGG, Wg2, bg2, pGate);
    ln_combine_kernel<<<ROWS, blk>>>(pT2, lng, lnb, pGate, hidden, out);
}

// round 4
// speedup vs baseline: 1.4697x; 1.4697x over previous
#include <cuda_runtime.h>
#include <cuda_bf16.h>
#include <math.h>
#include <stdint.h>

#define Bb   4
#define Ss   2048
#define Hh   1024
#define Mm   512
#define NHn  16
#define HDd  64
#define HQq  256
#define ROWS   (Bb*Ss)    /* 8192 */
#define KVROWS (Bb*Mm)    /* 2048 */

// ================= helpers =================
__device__ __forceinline__ uint32_t smem_u32(const void* p){
    uint32_t a;
    asm("{ .reg .u64 t; cvta.to.shared.u64 t, %1; cvt.u32.u64 %0, t; }" : "=r"(a) : "l"(p));
    return a;
}
#define CP_ASYNC16(dst, src) \
    asm volatile("cp.async.cg.shared.global [%0], [%1], 16;" :: "r"(dst), "l"(src))
#define CP_COMMIT() asm volatile("cp.async.commit_group;" ::: "memory")
#define CP_WAIT0()  asm volatile("cp.async.wait_group 0;" ::: "memory")

__device__ __forceinline__ void ldsm_x4(uint32_t* r, uint32_t addr){
    asm volatile("ldmatrix.sync.aligned.m8n8.x4.shared.b16 {%0,%1,%2,%3}, [%4];"
        : "=r"(r[0]),"=r"(r[1]),"=r"(r[2]),"=r"(r[3]) : "r"(addr));
}
__device__ __forceinline__ void mma16816(float* d, const uint32_t* a, const uint32_t* b){
    asm volatile("mma.sync.aligned.m16n8k16.row.col.f32.bf16.bf16.f32 "
        "{%0,%1,%2,%3}, {%4,%5,%6,%7}, {%8,%9}, {%0,%1,%2,%3};"
        : "+f"(d[0]),"+f"(d[1]),"+f"(d[2]),"+f"(d[3])
        : "r"(a[0]),"r"(a[1]),"r"(a[2]),"r"(a[3]), "r"(b[0]),"r"(b[1]));
}

__device__ __forceinline__ float gelu_exact(float x){
    return 0.5f*x*(1.0f + erff(x*0.70710678118654752f));
}

// ================= scratch (device globals) =================
__device__ float g_Q  [ROWS*Hh];
__device__ float g_K  [KVROWS*Hh];
__device__ float g_V  [KVROWS*Hh];
__device__ float g_att[ROWS*Hh];
__device__ float g_h1 [ROWS*Hh];
__device__ float g_t2 [ROWS*Hh];
__device__ float g_gg [ROWS*Hh];
__device__ float g_gate[ROWS];
// transposed+split weights [N][K] bf16
__device__ __nv_bfloat16 g_WqT_h [1024*1024], g_WqT_l [1024*1024];
__device__ __nv_bfloat16 g_WkT_h [1024*256],  g_WkT_l [1024*256];
__device__ __nv_bfloat16 g_WvT_h [1024*256],  g_WvT_l [1024*256];
__device__ __nv_bfloat16 g_W1T_h [1024*2048], g_W1T_l [1024*2048];
__device__ __nv_bfloat16 g_W2T_h [1024*1024], g_W2T_l [1024*1024];
__device__ __nv_bfloat16 g_Wg1T_h[1024*2048], g_Wg1T_l[1024*2048];

// ========== weight transpose + hi/lo split:  W[K][N] -> T[N][K] bf16 x2 ==========
__global__ void wsplitT(const float* __restrict__ W, __nv_bfloat16* __restrict__ Th,
                        __nv_bfloat16* __restrict__ Tl, int K, int N)
{
    __shared__ float s[32][33];
    int n0 = blockIdx.x*32, k0 = blockIdx.y*32;
    int tx = threadIdx.x, ty = threadIdx.y; // 32x8
#pragma unroll
    for (int i=0;i<4;i++)
        s[ty+i*8][tx] = W[(size_t)(k0+ty+i*8)*N + n0+tx];
    __syncthreads();
#pragma unroll
    for (int i=0;i<4;i++){
        int n = ty + i*8;
        float v = s[tx][n];
        __nv_bfloat16 h = __float2bfloat16(v);
        __nv_bfloat16 l = __float2bfloat16(v - __bfloat162float(h));
        size_t o = (size_t)(n0+n)*K + k0 + tx;
        Th[o] = h; Tl[o] = l;
    }
}

// ========== warp-MMA split-bf16 GEMM: C = act(A @ W^T + bias) ==========
// A fp32 (concat A0|A1 at ks along K), W pre-transposed split bf16 [N][K].
// Tile 128x128x32, 8 warps (2x4), warp tile 64x32, double-buffered smem.
// smem buffer: Ah[8K] Al[8K] Bh[8K] Bl[8K] = 32KB x2 + bias
#define AH_OFF 0
#define AL_OFF 8192
#define BH_OFF 16384
#define BL_OFF 24576
#define BUF_SZ 32768
#define GEMM_SMEM (2*BUF_SZ + 512)

// byte offset of element (row, k) in an [128][32] bf16 tile, XOR-swizzled:
//   row*64 + ((k/8) ^ ((row>>1)&3))*16 + (k%8)*2
__device__ __forceinline__ uint32_t swz(int row, int g){
    return (uint32_t)(row*64 + ((g ^ ((row>>1)&3))<<4));
}

__global__ void __launch_bounds__(256,1) gemm_mma(
    const float* __restrict__ A0, int lda0, const float* __restrict__ A1, int lda1, int ks,
    const __nv_bfloat16* __restrict__ Bh, const __nv_bfloat16* __restrict__ Bl,
    const float* __restrict__ bias, float* __restrict__ C, int ldc, int K, int act)
{
    extern __shared__ __align__(128) char smem[];
    uint32_t sb = smem_u32(smem);
    float* bias_s = (float*)(smem + 2*BUF_SZ);

    int t = threadIdx.x, lane = t&31, wid = t>>5;
    int m0 = blockIdx.y*128, n0 = blockIdx.x*128;
    int mbase = (wid>>2)*64, nbase = (wid&3)*32;

    if (t < 128) bias_s[t] = bias[n0 + t];

    int nch = K >> 5;

    // per-thread A staging assignment: row r = t>>1, khalf = (t&1)*16
    int ar_r  = t>>1;
    int ar_kh = (t&1)*16;

    float4 ar[4];
    // ---- prologue: chunk 0 ----
    {
        const float* Ap; int lda;
        if (0 < ks){ Ap = A0; lda = lda0; } else { Ap = A1; lda = lda1; }
        const float4* p = (const float4*)(Ap + (size_t)(m0+ar_r)*lda + ar_kh);
        ar[0]=p[0]; ar[1]=p[1]; ar[2]=p[2]; ar[3]=p[3];
    }

    float acc[4][4][4];
#pragma unroll
    for (int i=0;i<4;i++)
#pragma unroll
        for (int j=0;j<4;j++)
#pragma unroll
            for (int e=0;e<4;e++) acc[i][j][e]=0.f;

    for (int c=0; c<nch; c++){
        int b = c & 1;
        uint32_t sbuf = sb + b*BUF_SZ;
        // ---- store staged A (split), issue cp.async B for this chunk ----
        {
            float f[16] = {ar[0].x,ar[0].y,ar[0].z,ar[0].w, ar[1].x,ar[1].y,ar[1].z,ar[1].w,
                           ar[2].x,ar[2].y,ar[2].z,ar[2].w, ar[3].x,ar[3].y,ar[3].z,ar[3].w};
            uint32_t hp[8], lp[8];
#pragma unroll
            for (int j=0;j<8;j++){
                __nv_bfloat16 h0 = __float2bfloat16(f[2*j]);
                __nv_bfloat16 h1 = __float2bfloat16(f[2*j+1]);
                __nv_bfloat16 l0 = __float2bfloat16(f[2*j]   - __bfloat162float(h0));
                __nv_bfloat16 l1 = __float2bfloat16(f[2*j+1] - __bfloat162float(h1));
                hp[j] = (uint32_t)__bfloat16_as_ushort(h0) | ((uint32_t)__bfloat16_as_ushort(h1)<<16);
                lp[j] = (uint32_t)__bfloat16_as_ushort(l0) | ((uint32_t)__bfloat16_as_ushort(l1)<<16);
            }
            int g0 = ar_kh>>3;
            uint32_t d0 = sbuf + AH_OFF + swz(ar_r, g0);
            uint32_t d1 = sbuf + AH_OFF + swz(ar_r, g0+1);
            *(uint4*)(smem + (d0 - sb)) = make_uint4(hp[0],hp[1],hp[2],hp[3]);
            *(uint4*)(smem + (d1 - sb)) = make_uint4(hp[4],hp[5],hp[6],hp[7]);
            uint32_t e0 = sbuf + AL_OFF + swz(ar_r, g0);
            uint32_t e1 = sbuf + AL_OFF + swz(ar_r, g0+1);
            *(uint4*)(smem + (e0 - sb)) = make_uint4(lp[0],lp[1],lp[2],lp[3]);
            *(uint4*)(smem + (e1 - sb)) = make_uint4(lp[4],lp[5],lp[6],lp[7]);

            int kt = c*32;
            const __nv_bfloat16* srcH = Bh + (size_t)(n0+ar_r)*K + kt + ar_kh;
            const __nv_bfloat16* srcL = Bl + (size_t)(n0+ar_r)*K + kt + ar_kh;
            CP_ASYNC16(sbuf + BH_OFF + swz(ar_r, g0),   srcH);
            CP_ASYNC16(sbuf + BH_OFF + swz(ar_r, g0+1), srcH+8);
            CP_ASYNC16(sbuf + BL_OFF + swz(ar_r, g0),   srcL);
            CP_ASYNC16(sbuf + BL_OFF + swz(ar_r, g0+1), srcL+8);
            CP_COMMIT();
        }
        // ---- prefetch next chunk's A into regs (overlaps with mma) ----
        if (c+1 < nch){
            int kt = (c+1)*32;
            const float* Ap; int lda;
            if (kt < ks){ Ap = A0 + kt; lda = lda0; } else { Ap = A1 + (kt-ks); lda = lda1; }
            const float4* p = (const float4*)(Ap + (size_t)(m0+ar_r)*lda + ar_kh);
            ar[0]=p[0]; ar[1]=p[1]; ar[2]=p[2]; ar[3]=p[3];
        }
        CP_WAIT0();
        __syncthreads();
        // ---- compute on sbuf ----
        int lr = lane&15, lk = lane>>4;
#pragma unroll
        for (int ksI=0; ksI<2; ksI++){
            int gk = ksI*2;
            uint32_t aH[4][4];
#pragma unroll
            for (int mt=0;mt<4;mt++){
                int row = mbase + mt*16 + lr;
                ldsm_x4(aH[mt], sbuf + AH_OFF + swz(row, gk+lk));
            }
            uint32_t bHf[4][2];
#pragma unroll
            for (int j=0;j<2;j++){
                int n = nbase + j*16 + (lane>>4)*8 + (lane&7);
                int g = gk + ((lane>>3)&1);
                uint32_t tmp[4];
                ldsm_x4(tmp, sbuf + BH_OFF + swz(n, g));
                bHf[j*2][0]=tmp[0]; bHf[j*2][1]=tmp[1];
                bHf[j*2+1][0]=tmp[2]; bHf[j*2+1][1]=tmp[3];
            }
#pragma unroll
            for (int mt=0;mt<4;mt++)
#pragma unroll
                for (int nt=0;nt<4;nt++) mma16816(acc[mt][nt], aH[mt], bHf[nt]);
            // Ah * Bl
            uint32_t bLf[4][2];
#pragma unroll
            for (int j=0;j<2;j++){
                int n = nbase + j*16 + (lane>>4)*8 + (lane&7);
                int g = gk + ((lane>>3)&1);
                uint32_t tmp[4];
                ldsm_x4(tmp, sbuf + BL_OFF + swz(n, g));
                bLf[j*2][0]=tmp[0]; bLf[j*2][1]=tmp[1];
                bLf[j*2+1][0]=tmp[2]; bLf[j*2+1][1]=tmp[3];
            }
#pragma unroll
            for (int mt=0;mt<4;mt++)
#pragma unroll
                for (int nt=0;nt<4;nt++) mma16816(acc[mt][nt], aH[mt], bLf[nt]);
            // Al * Bh
            uint32_t aL[4][4];
#pragma unroll
            for (int mt=0;mt<4;mt++){
                int row = mbase + mt*16 + lr;
                ldsm_x4(aL[mt], sbuf + AL_OFF + swz(row, gk+lk));
            }
#pragma unroll
            for (int mt=0;mt<4;mt++)
#pragma unroll
                for (int nt=0;nt<4;nt++) mma16816(acc[mt][nt], aL[mt], bHf[nt]);
        }
        __syncthreads();   // all warps done with sbuf before it is overwritten
    }

    // ---- epilogue: bias + act, write C ----
#pragma unroll
    for (int mt=0;mt<4;mt++){
        int r0 = m0 + mbase + mt*16 + (lane>>2);
#pragma unroll
        for (int nt=0;nt<4;nt++){
            int cc = nbase + nt*8 + (lane&3)*2;
            float b0 = bias_s[cc], b1 = bias_s[cc+1];
            float v0 = acc[mt][nt][0] + b0;
            float v1 = acc[mt][nt][1] + b1;
            float v2 = acc[mt][nt][2] + b0;
            float v3 = acc[mt][nt][3] + b1;
            if (act){ v0=gelu_exact(v0); v1=gelu_exact(v1); v2=gelu_exact(v2); v3=gelu_exact(v3); }
            *(float2*)(C + (size_t)r0*ldc     + n0 + cc) = make_float2(v0,v1);
            *(float2*)(C + (size_t)(r0+8)*ldc + n0 + cc) = make_float2(v2,v3);
        }
    }
}

// ================= attention (fp32, unchanged) =================
#define ST  32
#define MCH 128
#define ATT_SMEM_FLOATS 51968

__global__ void __launch_bounds__(256,1) attn_kernel(
    const float* __restrict__ Q, const float* __restrict__ Kb, const float* __restrict__ Vb,
    const int* __restrict__ mask, float* __restrict__ att, float* __restrict__ mem_attn)
{
    extern __shared__ float sm[];
    float* qs   = sm;            // [32][64]
    float* kT   = sm + 2048;     // [64][132]
    float* vs   = sm + 10496;    // [128][64]
    float* lg   = sm + 18688;    // [32][512]
    float* macc = sm + 35072;    // [32][512]
    int*   msk  = (int*)(sm + 51456);

    int b  = blockIdx.x >> 6;
    int st = blockIdx.x & 63;
    int s0 = st * ST;
    int t  = threadIdx.x;

    for (int i=t;i<Mm;i+=256)     msk[i] = mask[b*Mm + i];
    for (int i=t;i<ST*Mm;i+=256)  macc[i] = 0.f;

    for (int n=0;n<NHn;n++){
        __syncthreads();
        for (int i=t;i<ST*64;i+=256){
            int q=i>>6, d=i&63;
            qs[q*64+d] = Q[((size_t)(b*Ss + s0 + q))*Hh + n*64 + d];
        }
        int qg = t>>5, mg = t&31;
        int q0 = qg*4, m0 = mg*4;
        for (int mc=0;mc<4;mc++){
            __syncthreads();
            for (int i=t;i<MCH*64;i+=256){
                int m=i>>6, d=i&63;
                kT[d*132+m] = Kb[((size_t)(b*Mm + mc*MCH + m))*Hh + n*64 + d];
            }
            __syncthreads();
            float acc[4][4];
#pragma unroll
            for (int i=0;i<4;i++)
#pragma unroll
                for (int j=0;j<4;j++) acc[i][j]=0.f;
#pragma unroll 4
            for (int d=0;d<64;d++){
                float4 kv = *(const float4*)&kT[d*132 + m0];
                float q0v = qs[(q0+0)*64+d];
                float q1v = qs[(q0+1)*64+d];
                float q2v = qs[(q0+2)*64+d];
                float q3v = qs[(q0+3)*64+d];
                acc[0][0]=fmaf(q0v,kv.x,acc[0][0]); acc[0][1]=fmaf(q0v,kv.y,acc[0][1]);
                acc[0][2]=fmaf(q0v,kv.z,acc[0][2]); acc[0][3]=fmaf(q0v,kv.w,acc[0][3]);
                acc[1][0]=fmaf(q1v,kv.x,acc[1][0]); acc[1][1]=fmaf(q1v,kv.y,acc[1][1]);
                acc[1][2]=fmaf(q1v,kv.z,acc[1][2]); acc[1][3]=fmaf(q1v,kv.w,acc[1][3]);
                acc[2][0]=fmaf(q2v,kv.x,acc[2][0]); acc[2][1]=fmaf(q2v,kv.y,acc[2][1]);
                acc[2][2]=fmaf(q2v,kv.z,acc[2][2]); acc[2][3]=fmaf(q2v,kv.w,acc[2][3]);
                acc[3][0]=fmaf(q3v,kv.x,acc[3][0]); acc[3][1]=fmaf(q3v,kv.y,acc[3][1]);
                acc[3][2]=fmaf(q3v,kv.z,acc[3][2]); acc[3][3]=fmaf(q3v,kv.w,acc[3][3]);
            }
#pragma unroll
            for (int i=0;i<4;i++)
#pragma unroll
                for (int j=0;j<4;j++)
                    lg[(q0+i)*Mm + mc*MCH + m0 + j] = acc[i][j]*0.125f;
        }
        __syncthreads();
        {
            int w = t>>5, lane = t&31;
            for (int q=w; q<ST; q+=8){
                float* row = &lg[q*Mm];
                float mx = -1e30f;
                for (int m=lane;m<Mm;m+=32) if (msk[m]!=0) mx = fmaxf(mx, row[m]);
#pragma unroll
                for (int o=16;o;o>>=1) mx = fmaxf(mx, __shfl_xor_sync(0xffffffffu,mx,o));
                float ssum = 0.f;
                for (int m=lane;m<Mm;m+=32){
                    float wv = (msk[m]!=0) ? expf(row[m]-mx) : 0.f;
                    row[m]=wv; ssum += wv;
                }
#pragma unroll
                for (int o=16;o;o>>=1) ssum += __shfl_xor_sync(0xffffffffu,ssum,o);
                float inv = 1.0f/ssum;
                for (int m=lane;m<Mm;m+=32){
                    float wv = row[m]*inv;
                    row[m]=wv;
                    macc[q*Mm+m] += wv;
                }
            }
        }
        int q  = t>>3;
        int d0 = (t&7)*8;
        float a8[8];
#pragma unroll
        for (int j=0;j<8;j++) a8[j]=0.f;
        for (int mc=0;mc<4;mc++){
            __syncthreads();
            for (int i=t;i<MCH*64;i+=256){
                int m=i>>6, d=i&63;
                vs[m*64+d] = Vb[((size_t)(b*Mm + mc*MCH + m))*Hh + n*64 + d];
            }
            __syncthreads();
            const float* wrow = &lg[q*Mm + mc*MCH];
#pragma unroll 4
            for (int m=0;m<MCH;m++){
                float wv = wrow[m];
                float4 v0 = *(const float4*)&vs[m*64 + d0];
                float4 v1 = *(const float4*)&vs[m*64 + d0 + 4];
                a8[0]=fmaf(wv,v0.x,a8[0]); a8[1]=fmaf(wv,v0.y,a8[1]);
                a8[2]=fmaf(wv,v0.z,a8[2]); a8[3]=fmaf(wv,v0.w,a8[3]);
                a8[4]=fmaf(wv,v1.x,a8[4]); a8[5]=fmaf(wv,v1.y,a8[5]);
                a8[6]=fmaf(wv,v1.z,a8[6]); a8[7]=fmaf(wv,v1.w,a8[7]);
            }
        }
        size_t basea = ((size_t)(b*Ss + s0 + q))*Hh + n*64 + d0;
#pragma unroll
        for (int j=0;j<8;j++) att[basea+j] = a8[j];
    }
    __syncthreads();
    for (int i=t;i<ST*Mm;i+=256){
        int q = i>>9, m = i&511;
        mem_attn[((size_t)(b*Ss + s0 + q))*Mm + m] = macc[i]*(1.0f/16.0f);
    }
}

// ================= gate GEMV =================
__global__ void gate_kernel(const float* __restrict__ gg, const float* __restrict__ Wg2,
                            const float* __restrict__ bg2, float* __restrict__ gate)
{
    int r = blockIdx.x*8 + (threadIdx.x>>5);
    int lane = threadIdx.x & 31;
    const float* row = gg + (size_t)r*Hh;
    float s = 0.f;
    for (int i=lane;i<Hh;i+=32) s = fmaf(row[i], Wg2[i], s);
#pragma unroll
    for (int o=16;o;o>>=1) s += __shfl_xor_sync(0xffffffffu,s,o);
    if (lane==0) gate[r] = 1.0f/(1.0f + expf(-(s + bg2[0])));
}

// ================= layernorm + gated residual =================
__global__ void ln_combine_kernel(
    const float* __restrict__ t2, const float* __restrict__ lng, const float* __restrict__ lnb,
    const float* __restrict__ gate, const float* __restrict__ hidden, float* __restrict__ out)
{
    __shared__ float red[8];
    int r = blockIdx.x;
    int t = threadIdx.x;
    const float* row = t2 + (size_t)r*Hh;
    float x[4];
#pragma unroll
    for (int j=0;j<4;j++) x[j] = row[t + 256*j];
    float s = x[0]+x[1]+x[2]+x[3];
#pragma unroll
    for (int o=16;o;o>>=1) s += __shfl_xor_sync(0xffffffffu,s,o);
    if ((t&31)==0) red[t>>5] = s;
    __syncthreads();
    float mu = (red[0]+red[1]+red[2]+red[3]+red[4]+red[5]+red[6]+red[7]) * (1.0f/Hh);
    __syncthreads();
    float s2 = 0.f;
#pragma unroll
    for (int j=0;j<4;j++){ float d = x[j]-mu; s2 = fmaf(d,d,s2); }
#pragma unroll
    for (int o=16;o;o>>=1) s2 += __shfl_xor_sync(0xffffffffu,s2,o);
    if ((t&31)==0) red[t>>5] = s2;
    __syncthreads();
    float var = (red[0]+red[1]+red[2]+red[3]+red[4]+red[5]+red[6]+red[7]) * (1.0f/Hh);
    float rs = rsqrtf(var + 1e-5f);
    float gt = gate[r];
    const float* hrow = hidden + (size_t)r*Hh;
#pragma unroll
    for (int j=0;j<4;j++){
        int idx = t + 256*j;
        float f = (x[j]-mu)*rs*lng[idx] + lnb[idx];
        out[(size_t)r*Hh + idx] = gt*f + (1.0f-gt)*hrow[idx];
    }
}

// ================= launch =================
extern "C" void kernel_launch(void* const* d_in, const int* in_sizes, int n_in,
                              void* d_out, int out_size)
{
    (void)in_sizes; (void)n_in; (void)out_size;
    const float* hidden = (const float*)d_in[0];
    const float* memory = (const float*)d_in[1];
    const int*   mask   = (const int*)  d_in[2];
    /* d_in[3] surprise_score: exact algebraic no-op */
    const float* Wq  = (const float*)d_in[4];
    const float* bq  = (const float*)d_in[5];
    const float* Wk  = (const float*)d_in[6];
    const float* bk  = (const float*)d_in[7];
    const float* Wv  = (const float*)d_in[8];
    const float* bv  = (const float*)d_in[9];
    const float* W1  = (const float*)d_in[10];
    const float* b1  = (const float*)d_in[11];
    const float* W2  = (const float*)d_in[12];
    const float* b2  = (const float*)d_in[13];
    const float* lng = (const float*)d_in[14];
    const float* lnb = (const float*)d_in[15];
    const float* Wg1 = (const float*)d_in[16];
    const float* bg1 = (const float*)d_in[17];
    const float* Wg2 = (const float*)d_in[18];
    const float* bg2 = (const float*)d_in[19];

    float *pQ,*pK,*pV,*pAtt,*pH1,*pT2,*pGG,*pGate;
    cudaGetSymbolAddress((void**)&pQ,   g_Q);
    cudaGetSymbolAddress((void**)&pK,   g_K);
    cudaGetSymbolAddress((void**)&pV,   g_V);
    cudaGetSymbolAddress((void**)&pAtt, g_att);
    cudaGetSymbolAddress((void**)&pH1,  g_h1);
    cudaGetSymbolAddress((void**)&pT2,  g_t2);
    cudaGetSymbolAddress((void**)&pGG,  g_gg);
    cudaGetSymbolAddress((void**)&pGate,g_gate);

    __nv_bfloat16 *qh,*ql,*kh,*kl,*vh,*vl,*w1h,*w1l,*w2h,*w2l,*g1h,*g1l;
    cudaGetSymbolAddress((void**)&qh,  g_WqT_h);  cudaGetSymbolAddress((void**)&ql,  g_WqT_l);
    cudaGetSymbolAddress((void**)&kh,  g_WkT_h);  cudaGetSymbolAddress((void**)&kl,  g_WkT_l);
    cudaGetSymbolAddress((void**)&vh,  g_WvT_h);  cudaGetSymbolAddress((void**)&vl,  g_WvT_l);
    cudaGetSymbolAddress((void**)&w1h, g_W1T_h);  cudaGetSymbolAddress((void**)&w1l, g_W1T_l);
    cudaGetSymbolAddress((void**)&w2h, g_W2T_h);  cudaGetSymbolAddress((void**)&w2l, g_W2T_l);
    cudaGetSymbolAddress((void**)&g1h, g_Wg1T_h); cudaGetSymbolAddress((void**)&g1l, g_Wg1T_l);

    float* out      = (float*)d_out;
    float* mem_attn = out + (size_t)ROWS*Hh;

    cudaFuncSetAttribute(gemm_mma, cudaFuncAttributeMaxDynamicSharedMemorySize, GEMM_SMEM);
    cudaFuncSetAttribute(attn_kernel, cudaFuncAttributeMaxDynamicSharedMemorySize,
                         ATT_SMEM_FLOATS*4);

    dim3 tb(32,8);
    // weight transpose + split
    wsplitT<<<dim3(32,32), tb>>>(Wq,  qh,  ql,  1024, 1024);
    wsplitT<<<dim3(32, 8), tb>>>(Wk,  kh,  kl,   256, 1024);
    wsplitT<<<dim3(32, 8), tb>>>(Wv,  vh,  vl,   256, 1024);
    wsplitT<<<dim3(32,64), tb>>>(W1,  w1h, w1l, 2048, 1024);
    wsplitT<<<dim3(32,32), tb>>>(W2,  w2h, w2l, 1024, 1024);
    wsplitT<<<dim3(32,64), tb>>>(Wg1, g1h, g1l, 2048, 1024);

    const int BIG = 1<<30;
    // projections (tensor cores via warp mma)
    gemm_mma<<<dim3(8,64), 256, GEMM_SMEM>>>(hidden, Hh,  (const float*)0, 0, BIG, qh, ql, bq, pQ, Hh, Hh,  0);
    gemm_mma<<<dim3(8,16), 256, GEMM_SMEM>>>(memory, HQq, (const float*)0, 0, BIG, kh, kl, bk, pK, Hh, HQq, 0);
    gemm_mma<<<dim3(8,16), 256, GEMM_SMEM>>>(memory, HQq, (const float*)0, 0, BIG, vh, vl, bv, pV, Hh, HQq, 0);

    // attention (mem_attn straight to output)
    attn_kernel<<<Bb*64, 256, ATT_SMEM_FLOATS*4>>>(pQ, pK, pV, mask, pAtt, mem_attn);

    // MLP path: A = concat(hidden, att) read in-place (ks = 1024)
    gemm_mma<<<dim3(8,64), 256, GEMM_SMEM>>>(hidden, Hh, pAtt, Hh, Hh, w1h, w1l, b1,  pH1, Hh, 2*Hh, 1);
    gemm_mma<<<dim3(8,64), 256, GEMM_SMEM>>>(hidden, Hh, pAtt, Hh, Hh, g1h, g1l, bg1, pGG, Hh, 2*Hh, 1);
    gemm_mma<<<dim3(8,64), 256, GEMM_SMEM>>>(pH1,    Hh, (const float*)0, 0, BIG, w2h, w2l, b2, pT2, Hh, Hh, 0);

    // gate + final layernorm/mix
    gate_kernel<<<1024, 256>>>(pGG, Wg2, bg2, pGate);
    ln_combine_kernel<<<ROWS, 256>>>(pT2, lng, lnb, pGate, hidden, out);
}

// round 5
// speedup vs baseline: 1.5022x; 1.0221x over previous
#include <cuda_runtime.h>
#include <cuda_bf16.h>
#include <math.h>
#include <stdint.h>

#define Bb   4
#define Ss   2048
#define Hh   1024
#define Mm   512
#define NHn  16
#define HDd  64
#define HQq  256
#define ROWS   (Bb*Ss)    /* 8192 */
#define KVROWS (Bb*Mm)    /* 2048 */

// ================= helpers =================
__device__ __forceinline__ uint32_t smem_u32(const void* p){
    uint32_t a;
    asm("{ .reg .u64 t; cvta.to.shared.u64 t, %1; cvt.u32.u64 %0, t; }" : "=r"(a) : "l"(p));
    return a;
}
#define CP_ASYNC16(dst, src) \
    asm volatile("cp.async.cg.shared.global [%0], [%1], 16;" :: "r"(dst), "l"(src))
#define CP_COMMIT() asm volatile("cp.async.commit_group;" ::: "memory")
#define CP_WAIT0()  asm volatile("cp.async.wait_group 0;" ::: "memory")
#define CP_WAIT1()  asm volatile("cp.async.wait_group 1;" ::: "memory")

__device__ __forceinline__ void ldsm_x4(uint32_t* r, uint32_t addr){
    asm volatile("ldmatrix.sync.aligned.m8n8.x4.shared.b16 {%0,%1,%2,%3}, [%4];"
        : "=r"(r[0]),"=r"(r[1]),"=r"(r[2]),"=r"(r[3]) : "r"(addr));
}
__device__ __forceinline__ void mma16816(float* d, const uint32_t* a, const uint32_t* b){
    asm volatile("mma.sync.aligned.m16n8k16.row.col.f32.bf16.bf16.f32 "
        "{%0,%1,%2,%3}, {%4,%5,%6,%7}, {%8,%9}, {%0,%1,%2,%3};"
        : "+f"(d[0]),"+f"(d[1]),"+f"(d[2]),"+f"(d[3])
        : "r"(a[0]),"r"(a[1]),"r"(a[2]),"r"(a[3]), "r"(b[0]),"r"(b[1]));
}

__device__ __forceinline__ float gelu_exact(float x){
    return 0.5f*x*(1.0f + erff(x*0.70710678118654752f));
}

// ================= scratch (device globals) =================
__device__ float g_Q  [ROWS*Hh];
__device__ float g_K  [KVROWS*Hh];
__device__ float g_V  [KVROWS*Hh];
__device__ float g_att[ROWS*Hh];
__device__ float g_h1 [ROWS*Hh];
__device__ float g_t2 [ROWS*Hh];
__device__ float g_gg [ROWS*Hh];
__device__ float g_gate[ROWS];
// transposed+split weights [N][K] bf16
__device__ __nv_bfloat16 g_WqT_h [1024*1024], g_WqT_l [1024*1024];
__device__ __nv_bfloat16 g_WkT_h [1024*256],  g_WkT_l [1024*256];
__device__ __nv_bfloat16 g_WvT_h [1024*256],  g_WvT_l [1024*256];
__device__ __nv_bfloat16 g_W1T_h [1024*2048], g_W1T_l [1024*2048];
__device__ __nv_bfloat16 g_W2T_h [1024*1024], g_W2T_l [1024*1024];
__device__ __nv_bfloat16 g_Wg1T_h[1024*2048], g_Wg1T_l[1024*2048];

// ========== weight transpose + hi/lo split:  W[K][N] -> T[N][K] bf16 x2 ==========
__global__ void wsplitT(const float* __restrict__ W, __nv_bfloat16* __restrict__ Th,
                        __nv_bfloat16* __restrict__ Tl, int K, int N)
{
    __shared__ float s[32][33];
    int n0 = blockIdx.x*32, k0 = blockIdx.y*32;
    int tx = threadIdx.x, ty = threadIdx.y; // 32x8
#pragma unroll
    for (int i=0;i<4;i++)
        s[ty+i*8][tx] = W[(size_t)(k0+ty+i*8)*N + n0+tx];
    __syncthreads();
#pragma unroll
    for (int i=0;i<4;i++){
        int n = ty + i*8;
        float v = s[tx][n];
        __nv_bfloat16 h = __float2bfloat16(v);
        __nv_bfloat16 l = __float2bfloat16(v - __bfloat162float(h));
        size_t o = (size_t)(n0+n)*K + k0 + tx;
        Th[o] = h; Tl[o] = l;
    }
}

// ========== warp-MMA split-bf16 GEMM: C = act(A @ W^T + bias) ==========
// Tile 128x128x32, 8 warps (2x4), warp tile 64x32, TRUE 2-stage pipeline:
// while computing chunk c (buffer b), chunk c+1 is staged into buffer b^1
// (A split-stores + B cp.async, wait_group 1) and chunk c+2's A is LDG'd.
#define AH_OFF 0
#define AL_OFF 8192
#define BH_OFF 16384
#define BL_OFF 24576
#define BUF_SZ 32768
#define GEMM_SMEM (2*BUF_SZ + 512)

__device__ __forceinline__ uint32_t swz(int row, int g){
    return (uint32_t)(row*64 + ((g ^ ((row>>1)&3))<<4));
}

__global__ void __launch_bounds__(256,1) gemm_mma(
    const float* __restrict__ A0, int lda0, const float* __restrict__ A1, int lda1, int ks,
    const __nv_bfloat16* __restrict__ Bh, const __nv_bfloat16* __restrict__ Bl,
    const float* __restrict__ bias, float* __restrict__ C, int ldc, int K, int act)
{
    extern __shared__ __align__(128) char smem[];
    uint32_t sb = smem_u32(smem);
    float* bias_s = (float*)(smem + 2*BUF_SZ);

    int t = threadIdx.x, lane = t&31, wid = t>>5;
    int m0 = blockIdx.y*128, n0 = blockIdx.x*128;
    int mbase = (wid>>2)*64, nbase = (wid&3)*32;

    if (t < 128) bias_s[t] = bias[n0 + t];

    int nch = K >> 5;

    // per-thread A staging assignment: row r = t>>1, khalf = (t&1)*16
    int ar_r  = t>>1;
    int ar_kh = (t&1)*16;
    int g0    = ar_kh>>3;

    float4 ar[4];

    // ---- stage helpers (lambdas would bloat; inline macros via code blocks) ----
    // LDG chunk kt's A into ar
    auto ldgA = [&](int kt){
        const float* Ap; int lda;
        if (kt < ks){ Ap = A0 + kt; lda = lda0; } else { Ap = A1 + (kt-ks); lda = lda1; }
        const float4* p = (const float4*)(Ap + (size_t)(m0+ar_r)*lda + ar_kh);
        ar[0]=p[0]; ar[1]=p[1]; ar[2]=p[2]; ar[3]=p[3];
    };
    // split ar -> smem buffer, and issue B cp.async for chunk c into same buffer
    auto stage = [&](int c, uint32_t sbuf){
        float f[16] = {ar[0].x,ar[0].y,ar[0].z,ar[0].w, ar[1].x,ar[1].y,ar[1].z,ar[1].w,
                       ar[2].x,ar[2].y,ar[2].z,ar[2].w, ar[3].x,ar[3].y,ar[3].z,ar[3].w};
        uint32_t hp[8], lp[8];
#pragma unroll
        for (int j=0;j<8;j++){
            __nv_bfloat16 h0 = __float2bfloat16(f[2*j]);
            __nv_bfloat16 h1 = __float2bfloat16(f[2*j+1]);
            __nv_bfloat16 l0 = __float2bfloat16(f[2*j]   - __bfloat162float(h0));
            __nv_bfloat16 l1 = __float2bfloat16(f[2*j+1] - __bfloat162float(h1));
            hp[j] = (uint32_t)__bfloat16_as_ushort(h0) | ((uint32_t)__bfloat16_as_ushort(h1)<<16);
            lp[j] = (uint32_t)__bfloat16_as_ushort(l0) | ((uint32_t)__bfloat16_as_ushort(l1)<<16);
        }
        *(uint4*)(smem + (sbuf - sb) + AH_OFF + swz(ar_r, g0))   = make_uint4(hp[0],hp[1],hp[2],hp[3]);
        *(uint4*)(smem + (sbuf - sb) + AH_OFF + swz(ar_r, g0+1)) = make_uint4(hp[4],hp[5],hp[6],hp[7]);
        *(uint4*)(smem + (sbuf - sb) + AL_OFF + swz(ar_r, g0))   = make_uint4(lp[0],lp[1],lp[2],lp[3]);
        *(uint4*)(smem + (sbuf - sb) + AL_OFF + swz(ar_r, g0+1)) = make_uint4(lp[4],lp[5],lp[6],lp[7]);

        int kt = c*32;
        const __nv_bfloat16* srcH = Bh + (size_t)(n0+ar_r)*K + kt + ar_kh;
        const __nv_bfloat16* srcL = Bl + (size_t)(n0+ar_r)*K + kt + ar_kh;
        CP_ASYNC16(sbuf + BH_OFF + swz(ar_r, g0),   srcH);
        CP_ASYNC16(sbuf + BH_OFF + swz(ar_r, g0+1), srcH+8);
        CP_ASYNC16(sbuf + BL_OFF + swz(ar_r, g0),   srcL);
        CP_ASYNC16(sbuf + BL_OFF + swz(ar_r, g0+1), srcL+8);
        CP_COMMIT();
    };

    float acc[4][4][4];
#pragma unroll
    for (int i=0;i<4;i++)
#pragma unroll
        for (int j=0;j<4;j++)
#pragma unroll
            for (int e=0;e<4;e++) acc[i][j][e]=0.f;

    // ---- prologue: stage chunk 0, prefetch chunk 1's A ----
    ldgA(0);
    stage(0, sb);
    if (nch > 1) ldgA(32);

    for (int c=0; c<nch; c++){
        int b = c & 1;
        uint32_t sbuf = sb + b*BUF_SZ;
        if (c+1 < nch){
            stage(c+1, sb + (b^1)*BUF_SZ);   // overlaps with compute below
            if (c+2 < nch) ldgA((c+2)*32);
            CP_WAIT1();                       // chunk c's B complete; c+1 in flight
        } else {
            CP_WAIT0();
        }
        __syncthreads();                      // A stores for chunk c visible

        // ---- compute on sbuf ----
        int lr = lane&15, lk = lane>>4;
#pragma unroll
        for (int ksI=0; ksI<2; ksI++){
            int gk = ksI*2;
            uint32_t aH[4][4];
#pragma unroll
            for (int mt=0;mt<4;mt++){
                int row = mbase + mt*16 + lr;
                ldsm_x4(aH[mt], sbuf + AH_OFF + swz(row, gk+lk));
            }
            uint32_t bHf[4][2];
#pragma unroll
            for (int j=0;j<2;j++){
                int n = nbase + j*16 + (lane>>4)*8 + (lane&7);
                int g = gk + ((lane>>3)&1);
                uint32_t tmp[4];
                ldsm_x4(tmp, sbuf + BH_OFF + swz(n, g));
                bHf[j*2][0]=tmp[0]; bHf[j*2][1]=tmp[1];
                bHf[j*2+1][0]=tmp[2]; bHf[j*2+1][1]=tmp[3];
            }
#pragma unroll
            for (int mt=0;mt<4;mt++)
#pragma unroll
                for (int nt=0;nt<4;nt++) mma16816(acc[mt][nt], aH[mt], bHf[nt]);
            // Ah * Bl
            uint32_t bLf[4][2];
#pragma unroll
            for (int j=0;j<2;j++){
                int n = nbase + j*16 + (lane>>4)*8 + (lane&7);
                int g = gk + ((lane>>3)&1);
                uint32_t tmp[4];
                ldsm_x4(tmp, sbuf + BL_OFF + swz(n, g));
                bLf[j*2][0]=tmp[0]; bLf[j*2][1]=tmp[1];
                bLf[j*2+1][0]=tmp[2]; bLf[j*2+1][1]=tmp[3];
            }
#pragma unroll
            for (int mt=0;mt<4;mt++)
#pragma unroll
                for (int nt=0;nt<4;nt++) mma16816(acc[mt][nt], aH[mt], bLf[nt]);
            // Al * Bh
            uint32_t aL[4][4];
#pragma unroll
            for (int mt=0;mt<4;mt++){
                int row = mbase + mt*16 + lr;
                ldsm_x4(aL[mt], sbuf + AL_OFF + swz(row, gk+lk));
            }
#pragma unroll
            for (int mt=0;mt<4;mt++)
#pragma unroll
                for (int nt=0;nt<4;nt++) mma16816(acc[mt][nt], aL[mt], bHf[nt]);
        }
        __syncthreads();   // all warps done with sbuf before it is restaged
    }

    // ---- epilogue: bias + act, write C ----
#pragma unroll
    for (int mt=0;mt<4;mt++){
        int r0 = m0 + mbase + mt*16 + (lane>>2);
#pragma unroll
        for (int nt=0;nt<4;nt++){
            int cc = nbase + nt*8 + (lane&3)*2;
            float b0 = bias_s[cc], b1 = bias_s[cc+1];
            float v0 = acc[mt][nt][0] + b0;
            float v1 = acc[mt][nt][1] + b1;
            float v2 = acc[mt][nt][2] + b0;
            float v3 = acc[mt][nt][3] + b1;
            if (act){ v0=gelu_exact(v0); v1=gelu_exact(v1); v2=gelu_exact(v2); v3=gelu_exact(v3); }
            *(float2*)(C + (size_t)r0*ldc     + n0 + cc) = make_float2(v0,v1);
            *(float2*)(C + (size_t)(r0+8)*ldc + n0 + cc) = make_float2(v2,v3);
        }
    }
}

// ================= attention (fp32, unchanged) =================
#define ST  32
#define MCH 128
#define ATT_SMEM_FLOATS 51968

__global__ void __launch_bounds__(256,1) attn_kernel(
    const float* __restrict__ Q, const float* __restrict__ Kb, const float* __restrict__ Vb,
    const int* __restrict__ mask, float* __restrict__ att, float* __restrict__ mem_attn)
{
    extern __shared__ float sm[];
    float* qs   = sm;            // [32][64]
    float* kT   = sm + 2048;     // [64][132]
    float* vs   = sm + 10496;    // [128][64]
    float* lg   = sm + 18688;    // [32][512]
    float* macc = sm + 35072;    // [32][512]
    int*   msk  = (int*)(sm + 51456);

    int b  = blockIdx.x >> 6;
    int st = blockIdx.x & 63;
    int s0 = st * ST;
    int t  = threadIdx.x;

    for (int i=t;i<Mm;i+=256)     msk[i] = mask[b*Mm + i];
    for (int i=t;i<ST*Mm;i+=256)  macc[i] = 0.f;

    for (int n=0;n<NHn;n++){
        __syncthreads();
        for (int i=t;i<ST*64;i+=256){
            int q=i>>6, d=i&63;
            qs[q*64+d] = Q[((size_t)(b*Ss + s0 + q))*Hh + n*64 + d];
        }
        int qg = t>>5, mg = t&31;
        int q0 = qg*4, m0 = mg*4;
        for (int mc=0;mc<4;mc++){
            __syncthreads();
            for (int i=t;i<MCH*64;i+=256){
                int m=i>>6, d=i&63;
                kT[d*132+m] = Kb[((size_t)(b*Mm + mc*MCH + m))*Hh + n*64 + d];
            }
            __syncthreads();
            float acc[4][4];
#pragma unroll
            for (int i=0;i<4;i++)
#pragma unroll
                for (int j=0;j<4;j++) acc[i][j]=0.f;
#pragma unroll 4
            for (int d=0;d<64;d++){
                float4 kv = *(const float4*)&kT[d*132 + m0];
                float q0v = qs[(q0+0)*64+d];
                float q1v = qs[(q0+1)*64+d];
                float q2v = qs[(q0+2)*64+d];
                float q3v = qs[(q0+3)*64+d];
                acc[0][0]=fmaf(q0v,kv.x,acc[0][0]); acc[0][1]=fmaf(q0v,kv.y,acc[0][1]);
                acc[0][2]=fmaf(q0v,kv.z,acc[0][2]); acc[0][3]=fmaf(q0v,kv.w,acc[0][3]);
                acc[1][0]=fmaf(q1v,kv.x,acc[1][0]); acc[1][1]=fmaf(q1v,kv.y,acc[1][1]);
                acc[1][2]=fmaf(q1v,kv.z,acc[1][2]); acc[1][3]=fmaf(q1v,kv.w,acc[1][3]);
                acc[2][0]=fmaf(q2v,kv.x,acc[2][0]); acc[2][1]=fmaf(q2v,kv.y,acc[2][1]);
                acc[2][2]=fmaf(q2v,kv.z,acc[2][2]); acc[2][3]=fmaf(q2v,kv.w,acc[2][3]);
                acc[3][0]=fmaf(q3v,kv.x,acc[3][0]); acc[3][1]=fmaf(q3v,kv.y,acc[3][1]);
                acc[3][2]=fmaf(q3v,kv.z,acc[3][2]); acc[3][3]=fmaf(q3v,kv.w,acc[3][3]);
            }
#pragma unroll
            for (int i=0;i<4;i++)
#pragma unroll
                for (int j=0;j<4;j++)
                    lg[(q0+i)*Mm + mc*MCH + m0 + j] = acc[i][j]*0.125f;
        }
        __syncthreads();
        {
            int w = t>>5, lane = t&31;
            for (int q=w; q<ST; q+=8){
                float* row = &lg[q*Mm];
                float mx = -1e30f;
                for (int m=lane;m<Mm;m+=32) if (msk[m]!=0) mx = fmaxf(mx, row[m]);
#pragma unroll
                for (int o=16;o;o>>=1) mx = fmaxf(mx, __shfl_xor_sync(0xffffffffu,mx,o));
                float ssum = 0.f;
                for (int m=lane;m<Mm;m+=32){
                    float wv = (msk[m]!=0) ? expf(row[m]-mx) : 0.f;
                    row[m]=wv; ssum += wv;
                }
#pragma unroll
                for (int o=16;o;o>>=1) ssum += __shfl_xor_sync(0xffffffffu,ssum,o);
                float inv = 1.0f/ssum;
                for (int m=lane;m<Mm;m+=32){
                    float wv = row[m]*inv;
                    row[m]=wv;
                    macc[q*Mm+m] += wv;
                }
            }
        }
        int q  = t>>3;
        int d0 = (t&7)*8;
        float a8[8];
#pragma unroll
        for (int j=0;j<8;j++) a8[j]=0.f;
        for (int mc=0;mc<4;mc++){
            __syncthreads();
            for (int i=t;i<MCH*64;i+=256){
                int m=i>>6, d=i&63;
                vs[m*64+d] = Vb[((size_t)(b*Mm + mc*MCH + m))*Hh + n*64 + d];
            }
            __syncthreads();
            const float* wrow = &lg[q*Mm + mc*MCH];
#pragma unroll 4
            for (int m=0;m<MCH;m++){
                float wv = wrow[m];
                float4 v0 = *(const float4*)&vs[m*64 + d0];
                float4 v1 = *(const float4*)&vs[m*64 + d0 + 4];
                a8[0]=fmaf(wv,v0.x,a8[0]); a8[1]=fmaf(wv,v0.y,a8[1]);
                a8[2]=fmaf(wv,v0.z,a8[2]); a8[3]=fmaf(wv,v0.w,a8[3]);
                a8[4]=fmaf(wv,v1.x,a8[4]); a8[5]=fmaf(wv,v1.y,a8[5]);
                a8[6]=fmaf(wv,v1.z,a8[6]); a8[7]=fmaf(wv,v1.w,a8[7]);
            }
        }
        size_t basea = ((size_t)(b*Ss + s0 + q))*Hh + n*64 + d0;
#pragma unroll
        for (int j=0;j<8;j++) att[basea+j] = a8[j];
    }
    __syncthreads();
    for (int i=t;i<ST*Mm;i+=256){
        int q = i>>9, m = i&511;
        mem_attn[((size_t)(b*Ss + s0 + q))*Mm + m] = macc[i]*(1.0f/16.0f);
    }
}

// ================= gate GEMV =================
__global__ void gate_kernel(const float* __restrict__ gg, const float* __restrict__ Wg2,
                            const float* __restrict__ bg2, float* __restrict__ gate)
{
    int r = blockIdx.x*8 + (threadIdx.x>>5);
    int lane = threadIdx.x & 31;
    const float* row = gg + (size_t)r*Hh;
    float s = 0.f;
    for (int i=lane;i<Hh;i+=32) s = fmaf(row[i], Wg2[i], s);
#pragma unroll
    for (int o=16;o;o>>=1) s += __shfl_xor_sync(0xffffffffu,s,o);
    if (lane==0) gate[r] = 1.0f/(1.0f + expf(-(s + bg2[0])));
}

// ================= layernorm + gated residual =================
__global__ void ln_combine_kernel(
    const float* __restrict__ t2, const float* __restrict__ lng, const float* __restrict__ lnb,
    const float* __restrict__ gate, const float* __restrict__ hidden, float* __restrict__ out)
{
    __shared__ float red[8];
    int r = blockIdx.x;
    int t = threadIdx.x;
    const float* row = t2 + (size_t)r*Hh;
    float x[4];
#pragma unroll
    for (int j=0;j<4;j++) x[j] = row[t + 256*j];
    float s = x[0]+x[1]+x[2]+x[3];
#pragma unroll
    for (int o=16;o;o>>=1) s += __shfl_xor_sync(0xffffffffu,s,o);
    if ((t&31)==0) red[t>>5] = s;
    __syncthreads();
    float mu = (red[0]+red[1]+red[2]+red[3]+red[4]+red[5]+red[6]+red[7]) * (1.0f/Hh);
    __syncthreads();
    float s2 = 0.f;
#pragma unroll
    for (int j=0;j<4;j++){ float d = x[j]-mu; s2 = fmaf(d,d,s2); }
#pragma unroll
    for (int o=16;o;o>>=1) s2 += __shfl_xor_sync(0xffffffffu,s2,o);
    if ((t&31)==0) red[t>>5] = s2;
    __syncthreads();
    float var = (red[0]+red[1]+red[2]+red[3]+red[4]+red[5]+red[6]+red[7]) * (1.0f/Hh);
    float rs = rsqrtf(var + 1e-5f);
    float gt = gate[r];
    const float* hrow = hidden + (size_t)r*Hh;
#pragma unroll
    for (int j=0;j<4;j++){
        int idx = t + 256*j;
        float f = (x[j]-mu)*rs*lng[idx] + lnb[idx];
        out[(size_t)r*Hh + idx] = gt*f + (1.0f-gt)*hrow[idx];
    }
}

// ================= launch =================
extern "C" void kernel_launch(void* const* d_in, const int* in_sizes, int n_in,
                              void* d_out, int out_size)
{
    (void)in_sizes; (void)n_in; (void)out_size;
    const float* hidden = (const float*)d_in[0];
    const float* memory = (const float*)d_in[1];
    const int*   mask   = (const int*)  d_in[2];
    /* d_in[3] surprise_score: exact algebraic no-op */
    const float* Wq  = (const float*)d_in[4];
    const float* bq  = (const float*)d_in[5];
    const float* Wk  = (const float*)d_in[6];
    const float* bk  = (const float*)d_in[7];
    const float* Wv  = (const float*)d_in[8];
    const float* bv  = (const float*)d_in[9];
    const float* W1  = (const float*)d_in[10];
    const float* b1  = (const float*)d_in[11];
    const float* W2  = (const float*)d_in[12];
    const float* b2  = (const float*)d_in[13];
    const float* lng = (const float*)d_in[14];
    const float* lnb = (const float*)d_in[15];
    const float* Wg1 = (const float*)d_in[16];
    const float* bg1 = (const float*)d_in[17];
    const float* Wg2 = (const float*)d_in[18];
    const float* bg2 = (const float*)d_in[19];

    float *pQ,*pK,*pV,*pAtt,*pH1,*pT2,*pGG,*pGate;
    cudaGetSymbolAddress((void**)&pQ,   g_Q);
    cudaGetSymbolAddress((void**)&pK,   g_K);
    cudaGetSymbolAddress((void**)&pV,   g_V);
    cudaGetSymbolAddress((void**)&pAtt, g_att);
    cudaGetSymbolAddress((void**)&pH1,  g_h1);
    cudaGetSymbolAddress((void**)&pT2,  g_t2);
    cudaGetSymbolAddress((void**)&pGG,  g_gg);
    cudaGetSymbolAddress((void**)&pGate,g_gate);

    __nv_bfloat16 *qh,*ql,*kh,*kl,*vh,*vl,*w1h,*w1l,*w2h,*w2l,*g1h,*g1l;
    cudaGetSymbolAddress((void**)&qh,  g_WqT_h);  cudaGetSymbolAddress((void**)&ql,  g_WqT_l);
    cudaGetSymbolAddress((void**)&kh,  g_WkT_h);  cudaGetSymbolAddress((void**)&kl,  g_WkT_l);
    cudaGetSymbolAddress((void**)&vh,  g_WvT_h);  cudaGetSymbolAddress((void**)&vl,  g_WvT_l);
    cudaGetSymbolAddress((void**)&w1h, g_W1T_h);  cudaGetSymbolAddress((void**)&w1l, g_W1T_l);
    cudaGetSymbolAddress((void**)&w2h, g_W2T_h);  cudaGetSymbolAddress((void**)&w2l, g_W2T_l);
    cudaGetSymbolAddress((void**)&g1h, g_Wg1T_h); cudaGetSymbolAddress((void**)&g1l, g_Wg1T_l);

    float* out      = (float*)d_out;
    float* mem_attn = out + (size_t)ROWS*Hh;

    cudaFuncSetAttribute(gemm_mma, cudaFuncAttributeMaxDynamicSharedMemorySize, GEMM_SMEM);
    cudaFuncSetAttribute(attn_kernel, cudaFuncAttributeMaxDynamicSharedMemorySize,
                         ATT_SMEM_FLOATS*4);

    dim3 tb(32,8);
    // weight transpose + split
    wsplitT<<<dim3(32,32), tb>>>(Wq,  qh,  ql,  1024, 1024);
    wsplitT<<<dim3(32, 8), tb>>>(Wk,  kh,  kl,   256, 1024);
    wsplitT<<<dim3(32, 8), tb>>>(Wv,  vh,  vl,   256, 1024);
    wsplitT<<<dim3(32,64), tb>>>(W1,  w1h, w1l, 2048, 1024);
    wsplitT<<<dim3(32,32), tb>>>(W2,  w2h, w2l, 1024, 1024);
    wsplitT<<<dim3(32,64), tb>>>(Wg1, g1h, g1l, 2048, 1024);

    const int BIG = 1<<30;
    // projections (tensor cores via warp mma)
    gemm_mma<<<dim3(8,64), 256, GEMM_SMEM>>>(hidden, Hh,  (const float*)0, 0, BIG, qh, ql, bq, pQ, Hh, Hh,  0);
    gemm_mma<<<dim3(8,16), 256, GEMM_SMEM>>>(memory, HQq, (const float*)0, 0, BIG, kh, kl, bk, pK, Hh, HQq, 0);
    gemm_mma<<<dim3(8,16), 256, GEMM_SMEM>>>(memory, HQq, (const float*)0, 0, BIG, vh, vl, bv, pV, Hh, HQq, 0);

    // attention (mem_attn straight to output)
    attn_kernel<<<Bb*64, 256, ATT_SMEM_FLOATS*4>>>(pQ, pK, pV, mask, pAtt, mem_attn);

    // MLP path: A = concat(hidden, att) read in-place (ks = 1024)
    gemm_mma<<<dim3(8,64), 256, GEMM_SMEM>>>(hidden, Hh, pAtt, Hh, Hh, w1h, w1l, b1,  pH1, Hh, 2*Hh, 1);
    gemm_mma<<<dim3(8,64), 256, GEMM_SMEM>>>(hidden, Hh, pAtt, Hh, Hh, g1h, g1l, bg1, pGG, Hh, 2*Hh, 1);
    gemm_mma<<<dim3(8,64), 256, GEMM_SMEM>>>(pH1,    Hh, (const float*)0, 0, BIG, w2h, w2l, b2, pT2, Hh, Hh, 0);

    // gate + final layernorm/mix
    gate_kernel<<<1024, 256>>>(pGG, Wg2, bg2, pGate);
    ln_combine_kernel<<<ROWS, 256>>>(pT2, lng, lnb, pGate, hidden, out);
}

// round 6
// speedup vs baseline: 2.7856x; 1.8544x over previous
#include <cuda_runtime.h>
#include <cuda_bf16.h>
#include <math.h>
#include <stdint.h>

#define Bb   4
#define Ss   2048
#define Hh   1024
#define Mm   512
#define NHn  16
#define HDd  64
#define HQq  256
#define ROWS   (Bb*Ss)    /* 8192 */
#define KVROWS (Bb*Mm)    /* 2048 */

// ================= helpers =================
__device__ __forceinline__ uint32_t smem_u32(const void* p){
    uint32_t a;
    asm("{ .reg .u64 t; cvta.to.shared.u64 t, %1; cvt.u32.u64 %0, t; }" : "=r"(a) : "l"(p));
    return a;
}
#define CP_ASYNC16(dst, src) \
    asm volatile("cp.async.cg.shared.global [%0], [%1], 16;" :: "r"(dst), "l"(src))
#define CP_COMMIT() asm volatile("cp.async.commit_group;" ::: "memory")
#define CP_WAIT0()  asm volatile("cp.async.wait_group 0;" ::: "memory")
#define CP_WAIT1()  asm volatile("cp.async.wait_group 1;" ::: "memory")

__device__ __forceinline__ void ldsm_x4(uint32_t* r, uint32_t addr){
    asm volatile("ldmatrix.sync.aligned.m8n8.x4.shared.b16 {%0,%1,%2,%3}, [%4];"
        : "=r"(r[0]),"=r"(r[1]),"=r"(r[2]),"=r"(r[3]) : "r"(addr));
}
__device__ __forceinline__ void mma16816(float* d, const uint32_t* a, const uint32_t* b){
    asm volatile("mma.sync.aligned.m16n8k16.row.col.f32.bf16.bf16.f32 "
        "{%0,%1,%2,%3}, {%4,%5,%6,%7}, {%8,%9}, {%0,%1,%2,%3};"
        : "+f"(d[0]),"+f"(d[1]),"+f"(d[2]),"+f"(d[3])
        : "r"(a[0]),"r"(a[1]),"r"(a[2]),"r"(a[3]), "r"(b[0]),"r"(b[1]));
}

__device__ __forceinline__ float gelu_exact(float x){
    return 0.5f*x*(1.0f + erff(x*0.70710678118654752f));
}

__device__ __forceinline__ void split8(float4 x0, float4 x1, uint4& hq, uint4& lq){
    float f[8] = {x0.x,x0.y,x0.z,x0.w,x1.x,x1.y,x1.z,x1.w};
    uint32_t hs[8], ls[8];
#pragma unroll
    for (int j=0;j<8;j++){
        __nv_bfloat16 h = __float2bfloat16(f[j]);
        float hf = __bfloat162float(h);
        __nv_bfloat16 l = __float2bfloat16(f[j]-hf);
        hs[j] = (uint32_t)__bfloat16_as_ushort(h);
        ls[j] = (uint32_t)__bfloat16_as_ushort(l);
    }
    hq = make_uint4(hs[0]|(hs[1]<<16), hs[2]|(hs[3]<<16), hs[4]|(hs[5]<<16), hs[6]|(hs[7]<<16));
    lq = make_uint4(ls[0]|(ls[1]<<16), ls[2]|(ls[3]<<16), ls[4]|(ls[5]<<16), ls[6]|(ls[7]<<16));
}

// ================= scratch (device globals) =================
__device__ float g_att[ROWS*Hh];
__device__ float g_h1 [ROWS*Hh];
__device__ float g_t2 [ROWS*Hh];
__device__ float g_gg [ROWS*Hh];
__device__ float g_gate[ROWS];
// split activations
__device__ __nv_bfloat16 g_Qh [ROWS*Hh],   g_Ql [ROWS*Hh];
__device__ __nv_bfloat16 g_Kh [KVROWS*Hh], g_Kl [KVROWS*Hh];
__device__ __nv_bfloat16 g_VTh[Bb*Hh*Mm],  g_VTl[Bb*Hh*Mm];
// transposed+split weights [N][K] bf16
__device__ __nv_bfloat16 g_WqT_h [1024*1024], g_WqT_l [1024*1024];
__device__ __nv_bfloat16 g_WkT_h [1024*256],  g_WkT_l [1024*256];
__device__ __nv_bfloat16 g_WvT_h [1024*256],  g_WvT_l [1024*256];
__device__ __nv_bfloat16 g_W1T_h [1024*2048], g_W1T_l [1024*2048];
__device__ __nv_bfloat16 g_W2T_h [1024*1024], g_W2T_l [1024*1024];
__device__ __nv_bfloat16 g_Wg1T_h[1024*2048], g_Wg1T_l[1024*2048];

// ========== weight transpose + hi/lo split ==========
__global__ void wsplitT(const float* __restrict__ W, __nv_bfloat16* __restrict__ Th,
                        __nv_bfloat16* __restrict__ Tl, int K, int N)
{
    __shared__ float s[32][33];
    int n0 = blockIdx.x*32, k0 = blockIdx.y*32;
    int tx = threadIdx.x, ty = threadIdx.y; // 32x8
#pragma unroll
    for (int i=0;i<4;i++)
        s[ty+i*8][tx] = W[(size_t)(k0+ty+i*8)*N + n0+tx];
    __syncthreads();
#pragma unroll
    for (int i=0;i<4;i++){
        int n = ty + i*8;
        float v = s[tx][n];
        __nv_bfloat16 h = __float2bfloat16(v);
        __nv_bfloat16 l = __float2bfloat16(v - __bfloat162float(h));
        size_t o = (size_t)(n0+n)*K + k0 + tx;
        Th[o] = h; Tl[o] = l;
    }
}

// ========== warp-MMA split-bf16 GEMM ==========
// mode: 0 = fp32 C; 1 = fp32 gelu C; 2 = split bf16 row-major (Ch/Cl, ldc cols);
//       3 = split bf16 transposed per 512-row batch: VT[b][col][m]
#define AH_OFF 0
#define AL_OFF 8192
#define BH_OFF 16384
#define BL_OFF 24576
#define BUF_SZ 32768
#define GEMM_SMEM (2*BUF_SZ + 512)

__device__ __forceinline__ uint32_t swz(int row, int g){
    return (uint32_t)(row*64 + ((g ^ ((row>>1)&3))<<4));
}

__global__ void __launch_bounds__(256,1) gemm_mma(
    const float* __restrict__ A0, int lda0, const float* __restrict__ A1, int lda1, int ks,
    const __nv_bfloat16* __restrict__ Bh, const __nv_bfloat16* __restrict__ Bl,
    const float* __restrict__ bias, float* __restrict__ C,
    __nv_bfloat16* __restrict__ Ch, __nv_bfloat16* __restrict__ Cl,
    int ldc, int K, int mode)
{
    extern __shared__ __align__(128) char smem[];
    uint32_t sb = smem_u32(smem);
    float* bias_s = (float*)(smem + 2*BUF_SZ);

    int t = threadIdx.x, lane = t&31, wid = t>>5;
    int m0 = blockIdx.y*128, n0 = blockIdx.x*128;
    int mbase = (wid>>2)*64, nbase = (wid&3)*32;

    if (t < 128) bias_s[t] = bias[n0 + t];

    int nch = K >> 5;
    int ar_r  = t>>1;
    int ar_kh = (t&1)*16;
    int g0    = ar_kh>>3;

    float4 ar[4];
    auto ldgA = [&](int kt){
        const float* Ap; int lda;
        if (kt < ks){ Ap = A0 + kt; lda = lda0; } else { Ap = A1 + (kt-ks); lda = lda1; }
        const float4* p = (const float4*)(Ap + (size_t)(m0+ar_r)*lda + ar_kh);
        ar[0]=p[0]; ar[1]=p[1]; ar[2]=p[2]; ar[3]=p[3];
    };
    auto stage = [&](int c, uint32_t sbuf){
        uint4 h0,l0,h1,l1;
        split8(ar[0], ar[1], h0, l0);
        split8(ar[2], ar[3], h1, l1);
        *(uint4*)(smem + (sbuf - sb) + AH_OFF + swz(ar_r, g0))   = h0;
        *(uint4*)(smem + (sbuf - sb) + AH_OFF + swz(ar_r, g0+1)) = h1;
        *(uint4*)(smem + (sbuf - sb) + AL_OFF + swz(ar_r, g0))   = l0;
        *(uint4*)(smem + (sbuf - sb) + AL_OFF + swz(ar_r, g0+1)) = l1;
        int kt = c*32;
        const __nv_bfloat16* srcH = Bh + (size_t)(n0+ar_r)*K + kt + ar_kh;
        const __nv_bfloat16* srcL = Bl + (size_t)(n0+ar_r)*K + kt + ar_kh;
        CP_ASYNC16(sbuf + BH_OFF + swz(ar_r, g0),   srcH);
        CP_ASYNC16(sbuf + BH_OFF + swz(ar_r, g0+1), srcH+8);
        CP_ASYNC16(sbuf + BL_OFF + swz(ar_r, g0),   srcL);
        CP_ASYNC16(sbuf + BL_OFF + swz(ar_r, g0+1), srcL+8);
        CP_COMMIT();
    };

    float acc[4][4][4];
#pragma unroll
    for (int i=0;i<4;i++)
#pragma unroll
        for (int j=0;j<4;j++)
#pragma unroll
            for (int e=0;e<4;e++) acc[i][j][e]=0.f;

    ldgA(0);
    stage(0, sb);
    if (nch > 1) ldgA(32);

    for (int c=0; c<nch; c++){
        int b = c & 1;
        uint32_t sbuf = sb + b*BUF_SZ;
        if (c+1 < nch){
            stage(c+1, sb + (b^1)*BUF_SZ);
            if (c+2 < nch) ldgA((c+2)*32);
            CP_WAIT1();
        } else {
            CP_WAIT0();
        }
        __syncthreads();

        int lr = lane&15, lk = lane>>4;
#pragma unroll
        for (int ksI=0; ksI<2; ksI++){
            int gk = ksI*2;
            uint32_t aH[4][4];
#pragma unroll
            for (int mt=0;mt<4;mt++){
                int row = mbase + mt*16 + lr;
                ldsm_x4(aH[mt], sbuf + AH_OFF + swz(row, gk+lk));
            }
            uint32_t bHf[4][2];
#pragma unroll
            for (int j=0;j<2;j++){
                int n = nbase + j*16 + (lane>>4)*8 + (lane&7);
                int g = gk + ((lane>>3)&1);
                uint32_t tmp[4];
                ldsm_x4(tmp, sbuf + BH_OFF + swz(n, g));
                bHf[j*2][0]=tmp[0]; bHf[j*2][1]=tmp[1];
                bHf[j*2+1][0]=tmp[2]; bHf[j*2+1][1]=tmp[3];
            }
#pragma unroll
            for (int mt=0;mt<4;mt++)
#pragma unroll
                for (int nt=0;nt<4;nt++) mma16816(acc[mt][nt], aH[mt], bHf[nt]);
            uint32_t bLf[4][2];
#pragma unroll
            for (int j=0;j<2;j++){
                int n = nbase + j*16 + (lane>>4)*8 + (lane&7);
                int g = gk + ((lane>>3)&1);
                uint32_t tmp[4];
                ldsm_x4(tmp, sbuf + BL_OFF + swz(n, g));
                bLf[j*2][0]=tmp[0]; bLf[j*2][1]=tmp[1];
                bLf[j*2+1][0]=tmp[2]; bLf[j*2+1][1]=tmp[3];
            }
#pragma unroll
            for (int mt=0;mt<4;mt++)
#pragma unroll
                for (int nt=0;nt<4;nt++) mma16816(acc[mt][nt], aH[mt], bLf[nt]);
            uint32_t aL[4][4];
#pragma unroll
            for (int mt=0;mt<4;mt++){
                int row = mbase + mt*16 + lr;
                ldsm_x4(aL[mt], sbuf + AL_OFF + swz(row, gk+lk));
            }
#pragma unroll
            for (int mt=0;mt<4;mt++)
#pragma unroll
                for (int nt=0;nt<4;nt++) mma16816(acc[mt][nt], aL[mt], bHf[nt]);
        }
        __syncthreads();
    }

    // ---- epilogue ----
#pragma unroll
    for (int mt=0;mt<4;mt++){
        int r0 = m0 + mbase + mt*16 + (lane>>2);
#pragma unroll
        for (int nt=0;nt<4;nt++){
            int cc = nbase + nt*8 + (lane&3)*2;
            float b0 = bias_s[cc], b1 = bias_s[cc+1];
            float v0 = acc[mt][nt][0] + b0;
            float v1 = acc[mt][nt][1] + b1;
            float v2 = acc[mt][nt][2] + b0;
            float v3 = acc[mt][nt][3] + b1;
            if (mode == 1){ v0=gelu_exact(v0); v1=gelu_exact(v1); v2=gelu_exact(v2); v3=gelu_exact(v3); }
            if (mode <= 1){
                *(float2*)(C + (size_t)r0*ldc     + n0 + cc) = make_float2(v0,v1);
                *(float2*)(C + (size_t)(r0+8)*ldc + n0 + cc) = make_float2(v2,v3);
            } else {
                __nv_bfloat16 h0=__float2bfloat16(v0), h1=__float2bfloat16(v1);
                __nv_bfloat16 h2=__float2bfloat16(v2), h3=__float2bfloat16(v3);
                __nv_bfloat16 l0=__float2bfloat16(v0-__bfloat162float(h0));
                __nv_bfloat16 l1=__float2bfloat16(v1-__bfloat162float(h1));
                __nv_bfloat16 l2=__float2bfloat16(v2-__bfloat162float(h2));
                __nv_bfloat16 l3=__float2bfloat16(v3-__bfloat162float(h3));
                if (mode == 2){
                    *(__nv_bfloat162*)(Ch + (size_t)r0*ldc + n0+cc)     = __nv_bfloat162(h0,h1);
                    *(__nv_bfloat162*)(Ch + (size_t)(r0+8)*ldc + n0+cc) = __nv_bfloat162(h2,h3);
                    *(__nv_bfloat162*)(Cl + (size_t)r0*ldc + n0+cc)     = __nv_bfloat162(l0,l1);
                    *(__nv_bfloat162*)(Cl + (size_t)(r0+8)*ldc + n0+cc) = __nv_bfloat162(l2,l3);
                } else { // mode 3: VT[b][col][m]
                    int bb = r0>>9, m = r0&511, col = n0+cc;
                    Ch[((size_t)bb*Hh + col  )*Mm + m  ] = h0;
                    Ch[((size_t)bb*Hh + col+1)*Mm + m  ] = h1;
                    Ch[((size_t)bb*Hh + col  )*Mm + m+8] = h2;
                    Ch[((size_t)bb*Hh + col+1)*Mm + m+8] = h3;
                    Cl[((size_t)bb*Hh + col  )*Mm + m  ] = l0;
                    Cl[((size_t)bb*Hh + col+1)*Mm + m  ] = l1;
                    Cl[((size_t)bb*Hh + col  )*Mm + m+8] = l2;
                    Cl[((size_t)bb*Hh + col+1)*Mm + m+8] = l3;
                }
            }
        }
    }
}

// ================= MMA attention =================
// block = (batch, 32-query tile); 8 warps; loops 16 heads.
// smem byte offsets:
#define SA_LG   0          /* float [32][512]  65536 */
#define SA_MACC 65536      /* float [32][512]  65536 */
#define SA_MSK  131072     /* int [512]        2048  */
#define SA_Q    133120     /* Qh0,Qh1,Ql0,Ql1 [32][32]bf16 x4 = 8192 */
#define SA_K    141312     /* 2 bufs x {Kh0,Kh1,Kl0,Kl1 [128][32]} = 2x32768 */
#define SA_VT   206848     /* 2 bufs x {VTh,VTl [64][32]} = 2x8192 */
#define SA_P    223232     /* Ph,Pl [32][32] = 4096 */
#define ATT_SMEM 227328

__global__ void __launch_bounds__(256,1) attn_mma(
    const __nv_bfloat16* __restrict__ Qh, const __nv_bfloat16* __restrict__ Ql,
    const __nv_bfloat16* __restrict__ Kh, const __nv_bfloat16* __restrict__ Kl,
    const __nv_bfloat16* __restrict__ VTh, const __nv_bfloat16* __restrict__ VTl,
    const int* __restrict__ mask, float* __restrict__ att, float* __restrict__ mem_attn)
{
    extern __shared__ __align__(128) char sm8[];
    uint32_t sb = smem_u32(sm8);
    float* lg   = (float*)(sm8 + SA_LG);
    float* macc = (float*)(sm8 + SA_MACC);
    int*   msk  = (int*)  (sm8 + SA_MSK);

    int b  = blockIdx.x >> 6;
    int s0 = (blockIdx.x & 63) * 32;
    int t  = threadIdx.x, lane = t&31, wid = t>>5;
    int q0 = (wid>>2)*16;          // warp query-row base (0 or 16)
    int nbase = (wid&3)*32;        // QK: warp m-col base within 128-chunk
    int d0 = (wid&3)*16;           // PV: warp d-col base
    int lr = lane&15, lk = lane>>4;

    for (int i=t;i<Mm;i+=256)     msk[i] = mask[b*Mm + i];
    for (int i=t;i<32*Mm;i+=256)  macc[i] = 0.f;

    auto loadK = [&](int head, int mc, int kb){
        uint32_t base = sb + SA_K + kb*32768;
#pragma unroll
        for (int i=0;i<8;i++){
            int j = t + i*256;          // 2048 jobs
            int tile = j>>9, rem = j&511;
            int row = rem>>2, g = rem&3;
            const __nv_bfloat16* src = (tile<2 ? Kh : Kl)
                + (size_t)(b*Mm + mc*128 + row)*Hh + head*64 + (tile&1)*32 + g*8;
            CP_ASYNC16(base + tile*8192 + swz(row,g), src);
        }
        CP_COMMIT();
    };
    auto loadVT = [&](int head, int mc, int vb){
        uint32_t base = sb + SA_VT + vb*8192;
#pragma unroll
        for (int i=0;i<2;i++){
            int j = t + i*256;          // 512 jobs
            int tile = j>>8, rem = j&255;
            int row = rem>>2, g = rem&3;
            const __nv_bfloat16* src = (tile ? VTl : VTh)
                + ((size_t)b*Hh + head*64 + row)*Mm + mc*32 + g*8;
            CP_ASYNC16(base + tile*4096 + swz(row,g), src);
        }
        CP_COMMIT();
    };

    for (int head=0; head<NHn; head++){
        __syncthreads();   // prev head fully done (Q/K/VT/P buffers free)
        // Q tiles for this head
#pragma unroll
        for (int i=0;i<2;i++){
            int j = t + i*256;          // 512 jobs
            int tile = j>>7, rem = j&127;
            int row = rem>>2, g = rem&3;
            const __nv_bfloat16* src = (tile<2 ? Qh : Ql)
                + (size_t)(b*Ss + s0 + row)*Hh + head*64 + (tile&1)*32 + g*8;
            CP_ASYNC16(sb + SA_Q + tile*2048 + swz(row,g), src);
        }
        CP_COMMIT();
        loadK(head, 0, 0);
        int kb = 0;
        // ---- QK^T: 4 chunks of 128 m ----
        for (int mc=0; mc<4; mc++){
            if (mc < 3){ loadK(head, mc+1, kb^1); CP_WAIT1(); } else { CP_WAIT0(); }
            __syncthreads();
            float acc[4][4];
#pragma unroll
            for (int i=0;i<4;i++)
#pragma unroll
                for (int e=0;e<4;e++) acc[i][e]=0.f;
            uint32_t kbase = sb + SA_K + kb*32768;
#pragma unroll
            for (int dc=0; dc<2; dc++){
                uint32_t Qhb = sb + SA_Q + dc*2048;
                uint32_t Qlb = sb + SA_Q + 4096 + dc*2048;
                uint32_t Khb = kbase + dc*8192;
                uint32_t Klb = kbase + 16384 + dc*8192;
#pragma unroll
                for (int ksI=0; ksI<2; ksI++){
                    int gk = ksI*2;
                    uint32_t aH[4];
                    ldsm_x4(aH, Qhb + swz(q0+lr, gk+lk));
                    uint32_t bHf[4][2];
#pragma unroll
                    for (int j=0;j<2;j++){
                        int n = nbase + j*16 + (lane>>4)*8 + (lane&7);
                        int g = gk + ((lane>>3)&1);
                        uint32_t tmp[4];
                        ldsm_x4(tmp, Khb + swz(n, g));
                        bHf[j*2][0]=tmp[0]; bHf[j*2][1]=tmp[1];
                        bHf[j*2+1][0]=tmp[2]; bHf[j*2+1][1]=tmp[3];
                    }
#pragma unroll
                    for (int nt=0;nt<4;nt++) mma16816(acc[nt], aH, bHf[nt]);
                    uint32_t bLf[4][2];
#pragma unroll
                    for (int j=0;j<2;j++){
                        int n = nbase + j*16 + (lane>>4)*8 + (lane&7);
                        int g = gk + ((lane>>3)&1);
                        uint32_t tmp[4];
                        ldsm_x4(tmp, Klb + swz(n, g));
                        bLf[j*2][0]=tmp[0]; bLf[j*2][1]=tmp[1];
                        bLf[j*2+1][0]=tmp[2]; bLf[j*2+1][1]=tmp[3];
                    }
#pragma unroll
                    for (int nt=0;nt<4;nt++) mma16816(acc[nt], aH, bLf[nt]);
                    uint32_t aL[4];
                    ldsm_x4(aL, Qlb + swz(q0+lr, gk+lk));
#pragma unroll
                    for (int nt=0;nt<4;nt++) mma16816(acc[nt], aL, bHf[nt]);
                }
            }
            // write logits (scale 1/sqrt(64))
            {
                int row = q0 + (lane>>2);
#pragma unroll
                for (int nt=0;nt<4;nt++){
                    int col = mc*128 + nbase + nt*8 + (lane&3)*2;
                    lg[row*Mm + col]       = acc[nt][0]*0.125f;
                    lg[row*Mm + col+1]     = acc[nt][1]*0.125f;
                    lg[(row+8)*Mm + col]   = acc[nt][2]*0.125f;
                    lg[(row+8)*Mm + col+1] = acc[nt][3]*0.125f;
                }
            }
            kb ^= 1;
            __syncthreads();
        }
        // ---- masked softmax + head-mean accumulate ----
        {
            int w = wid, ln2 = lane;
            for (int q=w; q<32; q+=8){
                float* row = &lg[q*Mm];
                float mx = -1e30f;
                for (int m=ln2;m<Mm;m+=32) if (msk[m]!=0) mx = fmaxf(mx, row[m]);
#pragma unroll
                for (int o=16;o;o>>=1) mx = fmaxf(mx, __shfl_xor_sync(0xffffffffu,mx,o));
                float ssum = 0.f;
                for (int m=ln2;m<Mm;m+=32){
                    float wv = (msk[m]!=0) ? expf(row[m]-mx) : 0.f;
                    row[m]=wv; ssum += wv;
                }
#pragma unroll
                for (int o=16;o;o>>=1) ssum += __shfl_xor_sync(0xffffffffu,ssum,o);
                float inv = 1.0f/ssum;
                for (int m=ln2;m<Mm;m+=32){
                    float wv = row[m]*inv;
                    row[m]=wv;
                    macc[q*Mm+m] += wv;
                }
            }
        }
        __syncthreads();
        // ---- P @ V: 16 chunks of 32 m ----
        float acc2[2][4];
#pragma unroll
        for (int i=0;i<2;i++)
#pragma unroll
            for (int e=0;e<4;e++) acc2[i][e]=0.f;
        loadVT(head, 0, 0);
        int vb = 0;
        for (int mc=0; mc<16; mc++){
            // stage P chunk (smem->smem; prev compute done via trailing sync)
            if (t < 128){
                int row = t>>2, g = t&3;
                const float* pl = &lg[row*Mm + mc*32 + g*8];
                float4 x0 = *(const float4*)pl, x1 = *(const float4*)(pl+4);
                uint4 hq, lq; split8(x0, x1, hq, lq);
                *(uint4*)(sm8 + SA_P + swz(row,g))        = hq;
                *(uint4*)(sm8 + SA_P + 2048 + swz(row,g)) = lq;
            }
            if (mc < 15){ loadVT(head, mc+1, vb^1); CP_WAIT1(); } else { CP_WAIT0(); }
            __syncthreads();
            uint32_t VThb = sb + SA_VT + vb*8192;
            uint32_t VTlb = VThb + 4096;
#pragma unroll
            for (int ksI=0; ksI<2; ksI++){
                int gk = ksI*2;
                uint32_t aH[4];
                ldsm_x4(aH, sb + SA_P + swz(q0+lr, gk+lk));
                uint32_t bHf[2][2];
                {
                    int n = d0 + (lane>>4)*8 + (lane&7);
                    int g = gk + ((lane>>3)&1);
                    uint32_t tmp[4];
                    ldsm_x4(tmp, VThb + swz(n, g));
                    bHf[0][0]=tmp[0]; bHf[0][1]=tmp[1];
                    bHf[1][0]=tmp[2]; bHf[1][1]=tmp[3];
                }
#pragma unroll
                for (int nt=0;nt<2;nt++) mma16816(acc2[nt], aH, bHf[nt]);
                uint32_t bLf[2][2];
                {
                    int n = d0 + (lane>>4)*8 + (lane&7);
                    int g = gk + ((lane>>3)&1);
                    uint32_t tmp[4];
                    ldsm_x4(tmp, VTlb + swz(n, g));
                    bLf[0][0]=tmp[0]; bLf[0][1]=tmp[1];
                    bLf[1][0]=tmp[2]; bLf[1][1]=tmp[3];
                }
#pragma unroll
                for (int nt=0;nt<2;nt++) mma16816(acc2[nt], aH, bLf[nt]);
                uint32_t aL[4];
                ldsm_x4(aL, sb + SA_P + 2048 + swz(q0+lr, gk+lk));
#pragma unroll
                for (int nt=0;nt<2;nt++) mma16816(acc2[nt], aL, bHf[nt]);
            }
            vb ^= 1;
            __syncthreads();
        }
        // write attended (fp32) for this head
        {
            int row = q0 + (lane>>2);
#pragma unroll
            for (int nt=0;nt<2;nt++){
                int col = d0 + nt*8 + (lane&3)*2;
                *(float2*)(att + (size_t)(b*Ss + s0 + row)*Hh + head*64 + col)
                    = make_float2(acc2[nt][0], acc2[nt][1]);
                *(float2*)(att + (size_t)(b*Ss + s0 + row + 8)*Hh + head*64 + col)
                    = make_float2(acc2[nt][2], acc2[nt][3]);
            }
        }
    }
    __syncthreads();
    for (int i=t;i<32*Mm;i+=256){
        int q = i>>9, m = i&511;
        mem_attn[((size_t)(b*Ss + s0 + q))*Mm + m] = macc[i]*(1.0f/16.0f);
    }
}

// ================= gate GEMV =================
__global__ void gate_kernel(const float* __restrict__ gg, const float* __restrict__ Wg2,
                            const float* __restrict__ bg2, float* __restrict__ gate)
{
    int r = blockIdx.x*8 + (threadIdx.x>>5);
    int lane = threadIdx.x & 31;
    const float* row = gg + (size_t)r*Hh;
    float s = 0.f;
    for (int i=lane;i<Hh;i+=32) s = fmaf(row[i], Wg2[i], s);
#pragma unroll
    for (int o=16;o;o>>=1) s += __shfl_xor_sync(0xffffffffu,s,o);
    if (lane==0) gate[r] = 1.0f/(1.0f + expf(-(s + bg2[0])));
}

// ================= layernorm + gated residual =================
__global__ void ln_combine_kernel(
    const float* __restrict__ t2, const float* __restrict__ lng, const float* __restrict__ lnb,
    const float* __restrict__ gate, const float* __restrict__ hidden, float* __restrict__ out)
{
    __shared__ float red[8];
    int r = blockIdx.x;
    int t = threadIdx.x;
    const float* row = t2 + (size_t)r*Hh;
    float x[4];
#pragma unroll
    for (int j=0;j<4;j++) x[j] = row[t + 256*j];
    float s = x[0]+x[1]+x[2]+x[3];
#pragma unroll
    for (int o=16;o;o>>=1) s += __shfl_xor_sync(0xffffffffu,s,o);
    if ((t&31)==0) red[t>>5] = s;
    __syncthreads();
    float mu = (red[0]+red[1]+red[2]+red[3]+red[4]+red[5]+red[6]+red[7]) * (1.0f/Hh);
    __syncthreads();
    float s2 = 0.f;
#pragma unroll
    for (int j=0;j<4;j++){ float d = x[j]-mu; s2 = fmaf(d,d,s2); }
#pragma unroll
    for (int o=16;o;o>>=1) s2 += __shfl_xor_sync(0xffffffffu,s2,o);
    if ((t&31)==0) red[t>>5] = s2;
    __syncthreads();
    float var = (red[0]+red[1]+red[2]+red[3]+red[4]+red[5]+red[6]+red[7]) * (1.0f/Hh);
    float rs = rsqrtf(var + 1e-5f);
    float gt = gate[r];
    const float* hrow = hidden + (size_t)r*Hh;
#pragma unroll
    for (int j=0;j<4;j++){
        int idx = t + 256*j;
        float f = (x[j]-mu)*rs*lng[idx] + lnb[idx];
        out[(size_t)r*Hh + idx] = gt*f + (1.0f-gt)*hrow[idx];
    }
}

// ================= launch =================
extern "C" void kernel_launch(void* const* d_in, const int* in_sizes, int n_in,
                              void* d_out, int out_size)
{
    (void)in_sizes; (void)n_in; (void)out_size;
    const float* hidden = (const float*)d_in[0];
    const float* memory = (const float*)d_in[1];
    const int*   mask   = (const int*)  d_in[2];
    /* d_in[3] surprise_score: exact algebraic no-op */
    const float* Wq  = (const float*)d_in[4];
    const float* bq  = (const float*)d_in[5];
    const float* Wk  = (const float*)d_in[6];
    const float* bk  = (const float*)d_in[7];
    const float* Wv  = (const float*)d_in[8];
    const float* bv  = (const float*)d_in[9];
    const float* W1  = (const float*)d_in[10];
    const float* b1  = (const float*)d_in[11];
    const float* W2  = (const float*)d_in[12];
    const float* b2  = (const float*)d_in[13];
    const float* lng = (const float*)d_in[14];
    const float* lnb = (const float*)d_in[15];
    const float* Wg1 = (const float*)d_in[16];
    const float* bg1 = (const float*)d_in[17];
    const float* Wg2 = (const float*)d_in[18];
    const float* bg2 = (const float*)d_in[19];

    float *pAtt,*pH1,*pT2,*pGG,*pGate;
    cudaGetSymbolAddress((void**)&pAtt, g_att);
    cudaGetSymbolAddress((void**)&pH1,  g_h1);
    cudaGetSymbolAddress((void**)&pT2,  g_t2);
    cudaGetSymbolAddress((void**)&pGG,  g_gg);
    cudaGetSymbolAddress((void**)&pGate,g_gate);

    __nv_bfloat16 *pQh,*pQl,*pKh,*pKl,*pVTh,*pVTl;
    cudaGetSymbolAddress((void**)&pQh,  g_Qh);  cudaGetSymbolAddress((void**)&pQl,  g_Ql);
    cudaGetSymbolAddress((void**)&pKh,  g_Kh);  cudaGetSymbolAddress((void**)&pKl,  g_Kl);
    cudaGetSymbolAddress((void**)&pVTh, g_VTh); cudaGetSymbolAddress((void**)&pVTl, g_VTl);

    __nv_bfloat16 *wqh,*wql,*wkh,*wkl,*wvh,*wvl,*w1h,*w1l,*w2h,*w2l,*wg1h,*wg1l;
    cudaGetSymbolAddress((void**)&wqh,  g_WqT_h);  cudaGetSymbolAddress((void**)&wql,  g_WqT_l);
    cudaGetSymbolAddress((void**)&wkh,  g_WkT_h);  cudaGetSymbolAddress((void**)&wkl,  g_WkT_l);
    cudaGetSymbolAddress((void**)&wvh,  g_WvT_h);  cudaGetSymbolAddress((void**)&wvl,  g_WvT_l);
    cudaGetSymbolAddress((void**)&w1h,  g_W1T_h);  cudaGetSymbolAddress((void**)&w1l,  g_W1T_l);
    cudaGetSymbolAddress((void**)&w2h,  g_W2T_h);  cudaGetSymbolAddress((void**)&w2l,  g_W2T_l);
    cudaGetSymbolAddress((void**)&wg1h, g_Wg1T_h); cudaGetSymbolAddress((void**)&wg1l, g_Wg1T_l);

    float* out      = (float*)d_out;
    float* mem_attn = out + (size_t)ROWS*Hh;

    cudaFuncSetAttribute(gemm_mma, cudaFuncAttributeMaxDynamicSharedMemorySize, GEMM_SMEM);
    cudaFuncSetAttribute(attn_mma, cudaFuncAttributeMaxDynamicSharedMemorySize, ATT_SMEM);

    dim3 tb(32,8);
    wsplitT<<<dim3(32,32), tb>>>(Wq,  wqh,  wql,  1024, 1024);
    wsplitT<<<dim3(32, 8), tb>>>(Wk,  wkh,  wkl,   256, 1024);
    wsplitT<<<dim3(32, 8), tb>>>(Wv,  wvh,  wvl,   256, 1024);
    wsplitT<<<dim3(32,64), tb>>>(W1,  w1h,  w1l,  2048, 1024);
    wsplitT<<<dim3(32,32), tb>>>(W2,  w2h,  w2l,  1024, 1024);
    wsplitT<<<dim3(32,64), tb>>>(Wg1, wg1h, wg1l, 2048, 1024);

    const int BIG = 1<<30;
    // projections -> split bf16 (Q,K row-major; V transposed per batch)
    gemm_mma<<<dim3(8,64), 256, GEMM_SMEM>>>(hidden, Hh,  (const float*)0, 0, BIG,
        wqh, wql, bq, (float*)0, pQh, pQl, Hh, Hh, 2);
    gemm_mma<<<dim3(8,16), 256, GEMM_SMEM>>>(memory, HQq, (const float*)0, 0, BIG,
        wkh, wkl, bk, (float*)0, pKh, pKl, Hh, HQq, 2);
    gemm_mma<<<dim3(8,16), 256, GEMM_SMEM>>>(memory, HQq, (const float*)0, 0, BIG,
        wvh, wvl, bv, (float*)0, pVTh, pVTl, Hh, HQq, 3);

    // MMA attention (mem_attn straight to output)
    attn_mma<<<Bb*64, 256, ATT_SMEM>>>(pQh, pQl, pKh, pKl, pVTh, pVTl, mask, pAtt, mem_attn);

    // MLP path: A = concat(hidden, att) read in-place (ks = 1024)
    gemm_mma<<<dim3(8,64), 256, GEMM_SMEM>>>(hidden, Hh, pAtt, Hh, Hh,
        w1h, w1l, b1,  pH1, (__nv_bfloat16*)0, (__nv_bfloat16*)0, Hh, 2*Hh, 1);
    gemm_mma<<<dim3(8,64), 256, GEMM_SMEM>>>(hidden, Hh, pAtt, Hh, Hh,
        wg1h, wg1l, bg1, pGG, (__nv_bfloat16*)0, (__nv_bfloat16*)0, Hh, 2*Hh, 1);
    gemm_mma<<<dim3(8,64), 256, GEMM_SMEM>>>(pH1, Hh, (const float*)0, 0, BIG,
        w2h, w2l, b2, pT2, (__nv_bfloat16*)0, (__nv_bfloat16*)0, Hh, Hh, 0);

    // gate + final layernorm/mix
    gate_kernel<<<1024, 256>>>(pGG, Wg2, bg2, pGate);
    ln_combine_kernel<<<ROWS, 256>>>(pT2, lng, lnb, pGate, hidden, out);
}

// round 7
// speedup vs baseline: 2.9401x; 1.0555x over previous
#include <cuda_runtime.h>
#include <cuda_bf16.h>
#include <math.h>
#include <stdint.h>

#define Bb   4
#define Ss   2048
#define Hh   1024
#define Mm   512
#define NHn  16
#define HDd  64
#define HQq  256
#define ROWS   (Bb*Ss)    /* 8192 */
#define KVROWS (Bb*Mm)    /* 2048 */

// ================= helpers =================
__device__ __forceinline__ uint32_t smem_u32(const void* p){
    uint32_t a;
    asm("{ .reg .u64 t; cvta.to.shared.u64 t, %1; cvt.u32.u64 %0, t; }" : "=r"(a) : "l"(p));
    return a;
}
#define CP_ASYNC16(dst, src) \
    asm volatile("cp.async.cg.shared.global [%0], [%1], 16;" :: "r"(dst), "l"(src))
#define CP_COMMIT() asm volatile("cp.async.commit_group;" ::: "memory")
#define CP_WAIT0()  asm volatile("cp.async.wait_group 0;" ::: "memory")
#define CP_WAIT1()  asm volatile("cp.async.wait_group 1;" ::: "memory")

__device__ __forceinline__ void ldsm_x4(uint32_t* r, uint32_t addr){
    asm volatile("ldmatrix.sync.aligned.m8n8.x4.shared.b16 {%0,%1,%2,%3}, [%4];"
        : "=r"(r[0]),"=r"(r[1]),"=r"(r[2]),"=r"(r[3]) : "r"(addr));
}
__device__ __forceinline__ void mma16816(float* d, const uint32_t* a, const uint32_t* b){
    asm volatile("mma.sync.aligned.m16n8k16.row.col.f32.bf16.bf16.f32 "
        "{%0,%1,%2,%3}, {%4,%5,%6,%7}, {%8,%9}, {%0,%1,%2,%3};"
        : "+f"(d[0]),"+f"(d[1]),"+f"(d[2]),"+f"(d[3])
        : "r"(a[0]),"r"(a[1]),"r"(a[2]),"r"(a[3]), "r"(b[0]),"r"(b[1]));
}

__device__ __forceinline__ float gelu_exact(float x){
    return 0.5f*x*(1.0f + erff(x*0.70710678118654752f));
}

__device__ __forceinline__ void split8(float4 x0, float4 x1, uint4& hq, uint4& lq){
    float f[8] = {x0.x,x0.y,x0.z,x0.w,x1.x,x1.y,x1.z,x1.w};
    uint32_t hs[8], ls[8];
#pragma unroll
    for (int j=0;j<8;j++){
        __nv_bfloat16 h = __float2bfloat16(f[j]);
        float hf = __bfloat162float(h);
        __nv_bfloat16 l = __float2bfloat16(f[j]-hf);
        hs[j] = (uint32_t)__bfloat16_as_ushort(h);
        ls[j] = (uint32_t)__bfloat16_as_ushort(l);
    }
    hq = make_uint4(hs[0]|(hs[1]<<16), hs[2]|(hs[3]<<16), hs[4]|(hs[5]<<16), hs[6]|(hs[7]<<16));
    lq = make_uint4(ls[0]|(ls[1]<<16), ls[2]|(ls[3]<<16), ls[4]|(ls[5]<<16), ls[6]|(ls[7]<<16));
}

// ================= scratch (device globals) =================
__device__ float g_t2 [ROWS*Hh];
__device__ float g_gg [ROWS*Hh];
__device__ float g_gate[ROWS];
// pre-split activations (hi/lo bf16)
__device__ __nv_bfloat16 g_Hsh[ROWS*Hh],    g_Hsl[ROWS*Hh];     // hidden
__device__ __nv_bfloat16 g_Msh[KVROWS*HQq], g_Msl[KVROWS*HQq];  // memory
__device__ __nv_bfloat16 g_Qh [ROWS*Hh],    g_Ql [ROWS*Hh];
__device__ __nv_bfloat16 g_Kh [KVROWS*Hh],  g_Kl [KVROWS*Hh];
__device__ __nv_bfloat16 g_VTh[Bb*Hh*Mm],   g_VTl[Bb*Hh*Mm];
__device__ __nv_bfloat16 g_ATTh[ROWS*Hh],   g_ATTl[ROWS*Hh];
__device__ __nv_bfloat16 g_H1h[ROWS*Hh],    g_H1l[ROWS*Hh];
// transposed+split weights [N][K] bf16
__device__ __nv_bfloat16 g_WqT_h [1024*1024], g_WqT_l [1024*1024];
__device__ __nv_bfloat16 g_WkT_h [1024*256],  g_WkT_l [1024*256];
__device__ __nv_bfloat16 g_WvT_h [1024*256],  g_WvT_l [1024*256];
__device__ __nv_bfloat16 g_W1T_h [1024*2048], g_W1T_l [1024*2048];
__device__ __nv_bfloat16 g_W2T_h [1024*1024], g_W2T_l [1024*1024];
__device__ __nv_bfloat16 g_Wg1T_h[1024*2048], g_Wg1T_l[1024*2048];

// ========== activation hi/lo split (row-major preserved) ==========
__global__ void asplit(const float4* __restrict__ X, __nv_bfloat16* __restrict__ Xh,
                       __nv_bfloat16* __restrict__ Xl)
{
    size_t i = (size_t)blockIdx.x*256 + threadIdx.x;   // one float8 per thread
    float4 x0 = X[2*i], x1 = X[2*i+1];
    uint4 hq, lq; split8(x0, x1, hq, lq);
    *(uint4*)(Xh + 8*i) = hq;
    *(uint4*)(Xl + 8*i) = lq;
}

// ========== weight transpose + hi/lo split ==========
__global__ void wsplitT(const float* __restrict__ W, __nv_bfloat16* __restrict__ Th,
                        __nv_bfloat16* __restrict__ Tl, int K, int N)
{
    __shared__ float s[32][33];
    int n0 = blockIdx.x*32, k0 = blockIdx.y*32;
    int tx = threadIdx.x, ty = threadIdx.y; // 32x8
#pragma unroll
    for (int i=0;i<4;i++)
        s[ty+i*8][tx] = W[(size_t)(k0+ty+i*8)*N + n0+tx];
    __syncthreads();
#pragma unroll
    for (int i=0;i<4;i++){
        int n = ty + i*8;
        float v = s[tx][n];
        __nv_bfloat16 h = __float2bfloat16(v);
        __nv_bfloat16 l = __float2bfloat16(v - __bfloat162float(h));
        size_t o = (size_t)(n0+n)*K + k0 + tx;
        Th[o] = h; Tl[o] = l;
    }
}

// ========== warp-MMA split-bf16 GEMM (pre-split A) ==========
// modes: 0 fp32 C; 1 fp32+gelu C; 2 split bf16 C; 3 split bf16 VT[b][col][m]; 4 gelu + split bf16 C
#define AH_OFF 0
#define AL_OFF 8192
#define BH_OFF 16384
#define BL_OFF 24576
#define BUF_SZ 32768
#define GEMM_SMEM (2*BUF_SZ + 512)

__device__ __forceinline__ uint32_t swz(int row, int g){
    return (uint32_t)(row*64 + ((g ^ ((row>>1)&3))<<4));
}

__global__ void __launch_bounds__(256,1) gemm_mma(
    const __nv_bfloat16* __restrict__ A0h, const __nv_bfloat16* __restrict__ A0l, int lda0,
    const __nv_bfloat16* __restrict__ A1h, const __nv_bfloat16* __restrict__ A1l, int lda1, int ks,
    const __nv_bfloat16* __restrict__ Bh, const __nv_bfloat16* __restrict__ Bl,
    const float* __restrict__ bias, float* __restrict__ C,
    __nv_bfloat16* __restrict__ Ch, __nv_bfloat16* __restrict__ Cl,
    int ldc, int K, int mode)
{
    extern __shared__ __align__(128) char smem[];
    uint32_t sb = smem_u32(smem);
    float* bias_s = (float*)(smem + 2*BUF_SZ);

    int t = threadIdx.x, lane = t&31, wid = t>>5;
    int m0 = blockIdx.y*128, n0 = blockIdx.x*128;
    int mbase = (wid>>2)*64, nbase = (wid&3)*32;

    if (t < 128) bias_s[t] = bias[n0 + t];

    int nch = K >> 5;
    int ar_r  = t>>1;
    int ar_kh = (t&1)*16;
    int g0    = ar_kh>>3;

    auto stage = [&](int c, uint32_t sbuf){
        int kt = c*32;
        const __nv_bfloat16 *Ah, *Al; int lda, ko;
        if (kt < ks){ Ah = A0h; Al = A0l; lda = lda0; ko = kt; }
        else        { Ah = A1h; Al = A1l; lda = lda1; ko = kt - ks; }
        const __nv_bfloat16* aH = Ah + (size_t)(m0+ar_r)*lda + ko + ar_kh;
        const __nv_bfloat16* aL = Al + (size_t)(m0+ar_r)*lda + ko + ar_kh;
        const __nv_bfloat16* bH = Bh + (size_t)(n0+ar_r)*K + kt + ar_kh;
        const __nv_bfloat16* bL = Bl + (size_t)(n0+ar_r)*K + kt + ar_kh;
        CP_ASYNC16(sbuf + AH_OFF + swz(ar_r, g0),   aH);
        CP_ASYNC16(sbuf + AH_OFF + swz(ar_r, g0+1), aH+8);
        CP_ASYNC16(sbuf + AL_OFF + swz(ar_r, g0),   aL);
        CP_ASYNC16(sbuf + AL_OFF + swz(ar_r, g0+1), aL+8);
        CP_ASYNC16(sbuf + BH_OFF + swz(ar_r, g0),   bH);
        CP_ASYNC16(sbuf + BH_OFF + swz(ar_r, g0+1), bH+8);
        CP_ASYNC16(sbuf + BL_OFF + swz(ar_r, g0),   bL);
        CP_ASYNC16(sbuf + BL_OFF + swz(ar_r, g0+1), bL+8);
        CP_COMMIT();
    };

    float acc[4][4][4];
#pragma unroll
    for (int i=0;i<4;i++)
#pragma unroll
        for (int j=0;j<4;j++)
#pragma unroll
            for (int e=0;e<4;e++) acc[i][j][e]=0.f;

    stage(0, sb);

    for (int c=0; c<nch; c++){
        int b = c & 1;
        uint32_t sbuf = sb + b*BUF_SZ;
        if (c+1 < nch){ stage(c+1, sb + (b^1)*BUF_SZ); CP_WAIT1(); }
        else          { CP_WAIT0(); }
        __syncthreads();

        int lr = lane&15, lk = lane>>4;
#pragma unroll
        for (int ksI=0; ksI<2; ksI++){
            int gk = ksI*2;
            uint32_t aH[4][4];
#pragma unroll
            for (int mt=0;mt<4;mt++){
                int row = mbase + mt*16 + lr;
                ldsm_x4(aH[mt], sbuf + AH_OFF + swz(row, gk+lk));
            }
            uint32_t bHf[4][2];
#pragma unroll
            for (int j=0;j<2;j++){
                int n = nbase + j*16 + (lane>>4)*8 + (lane&7);
                int g = gk + ((lane>>3)&1);
                uint32_t tmp[4];
                ldsm_x4(tmp, sbuf + BH_OFF + swz(n, g));
                bHf[j*2][0]=tmp[0]; bHf[j*2][1]=tmp[1];
                bHf[j*2+1][0]=tmp[2]; bHf[j*2+1][1]=tmp[3];
            }
#pragma unroll
            for (int mt=0;mt<4;mt++)
#pragma unroll
                for (int nt=0;nt<4;nt++) mma16816(acc[mt][nt], aH[mt], bHf[nt]);
            uint32_t bLf[4][2];
#pragma unroll
            for (int j=0;j<2;j++){
                int n = nbase + j*16 + (lane>>4)*8 + (lane&7);
                int g = gk + ((lane>>3)&1);
                uint32_t tmp[4];
                ldsm_x4(tmp, sbuf + BL_OFF + swz(n, g));
                bLf[j*2][0]=tmp[0]; bLf[j*2][1]=tmp[1];
                bLf[j*2+1][0]=tmp[2]; bLf[j*2+1][1]=tmp[3];
            }
#pragma unroll
            for (int mt=0;mt<4;mt++)
#pragma unroll
                for (int nt=0;nt<4;nt++) mma16816(acc[mt][nt], aH[mt], bLf[nt]);
            uint32_t aL[4][4];
#pragma unroll
            for (int mt=0;mt<4;mt++){
                int row = mbase + mt*16 + lr;
                ldsm_x4(aL[mt], sbuf + AL_OFF + swz(row, gk+lk));
            }
#pragma unroll
            for (int mt=0;mt<4;mt++)
#pragma unroll
                for (int nt=0;nt<4;nt++) mma16816(acc[mt][nt], aL[mt], bHf[nt]);
        }
        __syncthreads();
    }

    // ---- epilogue ----
    int actv = (mode==1 || mode==4);
#pragma unroll
    for (int mt=0;mt<4;mt++){
        int r0 = m0 + mbase + mt*16 + (lane>>2);
#pragma unroll
        for (int nt=0;nt<4;nt++){
            int cc = nbase + nt*8 + (lane&3)*2;
            float b0 = bias_s[cc], b1 = bias_s[cc+1];
            float v0 = acc[mt][nt][0] + b0;
            float v1 = acc[mt][nt][1] + b1;
            float v2 = acc[mt][nt][2] + b0;
            float v3 = acc[mt][nt][3] + b1;
            if (actv){ v0=gelu_exact(v0); v1=gelu_exact(v1); v2=gelu_exact(v2); v3=gelu_exact(v3); }
            if (mode <= 1){
                *(float2*)(C + (size_t)r0*ldc     + n0 + cc) = make_float2(v0,v1);
                *(float2*)(C + (size_t)(r0+8)*ldc + n0 + cc) = make_float2(v2,v3);
            } else {
                __nv_bfloat16 h0=__float2bfloat16(v0), h1=__float2bfloat16(v1);
                __nv_bfloat16 h2=__float2bfloat16(v2), h3=__float2bfloat16(v3);
                __nv_bfloat16 l0=__float2bfloat16(v0-__bfloat162float(h0));
                __nv_bfloat16 l1=__float2bfloat16(v1-__bfloat162float(h1));
                __nv_bfloat16 l2=__float2bfloat16(v2-__bfloat162float(h2));
                __nv_bfloat16 l3=__float2bfloat16(v3-__bfloat162float(h3));
                if (mode != 3){
                    *(__nv_bfloat162*)(Ch + (size_t)r0*ldc + n0+cc)     = __nv_bfloat162(h0,h1);
                    *(__nv_bfloat162*)(Ch + (size_t)(r0+8)*ldc + n0+cc) = __nv_bfloat162(h2,h3);
                    *(__nv_bfloat162*)(Cl + (size_t)r0*ldc + n0+cc)     = __nv_bfloat162(l0,l1);
                    *(__nv_bfloat162*)(Cl + (size_t)(r0+8)*ldc + n0+cc) = __nv_bfloat162(l2,l3);
                } else { // VT[b][col][m]
                    int bb = r0>>9, m = r0&511, col = n0+cc;
                    Ch[((size_t)bb*Hh + col  )*Mm + m  ] = h0;
                    Ch[((size_t)bb*Hh + col+1)*Mm + m  ] = h1;
                    Ch[((size_t)bb*Hh + col  )*Mm + m+8] = h2;
                    Ch[((size_t)bb*Hh + col+1)*Mm + m+8] = h3;
                    Cl[((size_t)bb*Hh + col  )*Mm + m  ] = l0;
                    Cl[((size_t)bb*Hh + col+1)*Mm + m  ] = l1;
                    Cl[((size_t)bb*Hh + col  )*Mm + m+8] = l2;
                    Cl[((size_t)bb*Hh + col+1)*Mm + m+8] = l3;
                }
            }
        }
    }
}

// ================= MMA attention =================
#define SA_LG   0          /* float [32][512]  65536 */
#define SA_MACC 65536      /* float [32][512]  65536 */
#define SA_MSK  131072     /* int [512]        2048  */
#define SA_Q    133120     /* Qh0,Qh1,Ql0,Ql1 [32][32]bf16 x4 = 8192 */
#define SA_K    141312     /* 2 bufs x {Kh0,Kh1,Kl0,Kl1 [128][32]} = 2x32768 */
#define SA_VT   206848     /* 2 bufs x {VTh,VTl [64][32]} = 2x8192 */
#define SA_P    223232     /* Ph,Pl [32][32] = 4096 */
#define ATT_SMEM 227328

__global__ void __launch_bounds__(256,1) attn_mma(
    const __nv_bfloat16* __restrict__ Qh, const __nv_bfloat16* __restrict__ Ql,
    const __nv_bfloat16* __restrict__ Kh, const __nv_bfloat16* __restrict__ Kl,
    const __nv_bfloat16* __restrict__ VTh, const __nv_bfloat16* __restrict__ VTl,
    const int* __restrict__ mask,
    __nv_bfloat16* __restrict__ ATTh, __nv_bfloat16* __restrict__ ATTl,
    float* __restrict__ mem_attn)
{
    extern __shared__ __align__(128) char sm8[];
    uint32_t sb = smem_u32(sm8);
    float* lg   = (float*)(sm8 + SA_LG);
    float* macc = (float*)(sm8 + SA_MACC);
    int*   msk  = (int*)  (sm8 + SA_MSK);

    int b  = blockIdx.x >> 6;
    int s0 = (blockIdx.x & 63) * 32;
    int t  = threadIdx.x, lane = t&31, wid = t>>5;
    int q0 = (wid>>2)*16;
    int nbase = (wid&3)*32;
    int d0 = (wid&3)*16;
    int lr = lane&15, lk = lane>>4;

    for (int i=t;i<Mm;i+=256)     msk[i] = mask[b*Mm + i];
    for (int i=t;i<32*Mm;i+=256)  macc[i] = 0.f;

    auto loadK = [&](int head, int mc, int kb){
        uint32_t base = sb + SA_K + kb*32768;
#pragma unroll
        for (int i=0;i<8;i++){
            int j = t + i*256;
            int tile = j>>9, rem = j&511;
            int row = rem>>2, g = rem&3;
            const __nv_bfloat16* src = (tile<2 ? Kh : Kl)
                + (size_t)(b*Mm + mc*128 + row)*Hh + head*64 + (tile&1)*32 + g*8;
            CP_ASYNC16(base + tile*8192 + swz(row,g), src);
        }
        CP_COMMIT();
    };
    auto loadVT = [&](int head, int mc, int vb){
        uint32_t base = sb + SA_VT + vb*8192;
#pragma unroll
        for (int i=0;i<2;i++){
            int j = t + i*256;
            int tile = j>>8, rem = j&255;
            int row = rem>>2, g = rem&3;
            const __nv_bfloat16* src = (tile ? VTl : VTh)
                + ((size_t)b*Hh + head*64 + row)*Mm + mc*32 + g*8;
            CP_ASYNC16(base + tile*4096 + swz(row,g), src);
        }
        CP_COMMIT();
    };

    for (int head=0; head<NHn; head++){
        __syncthreads();
#pragma unroll
        for (int i=0;i<2;i++){
            int j = t + i*256;
            int tile = j>>7, rem = j&127;
            int row = rem>>2, g = rem&3;
            const __nv_bfloat16* src = (tile<2 ? Qh : Ql)
                + (size_t)(b*Ss + s0 + row)*Hh + head*64 + (tile&1)*32 + g*8;
            CP_ASYNC16(sb + SA_Q + tile*2048 + swz(row,g), src);
        }
        CP_COMMIT();
        loadK(head, 0, 0);
        int kb = 0;
        for (int mc=0; mc<4; mc++){
            if (mc < 3){ loadK(head, mc+1, kb^1); CP_WAIT1(); } else { CP_WAIT0(); }
            __syncthreads();
            float acc[4][4];
#pragma unroll
            for (int i=0;i<4;i++)
#pragma unroll
                for (int e=0;e<4;e++) acc[i][e]=0.f;
            uint32_t kbase = sb + SA_K + kb*32768;
#pragma unroll
            for (int dc=0; dc<2; dc++){
                uint32_t Qhb = sb + SA_Q + dc*2048;
                uint32_t Qlb = sb + SA_Q + 4096 + dc*2048;
                uint32_t Khb = kbase + dc*8192;
                uint32_t Klb = kbase + 16384 + dc*8192;
#pragma unroll
                for (int ksI=0; ksI<2; ksI++){
                    int gk = ksI*2;
                    uint32_t aH[4];
                    ldsm_x4(aH, Qhb + swz(q0+lr, gk+lk));
                    uint32_t bHf[4][2];
#pragma unroll
                    for (int j=0;j<2;j++){
                        int n = nbase + j*16 + (lane>>4)*8 + (lane&7);
                        int g = gk + ((lane>>3)&1);
                        uint32_t tmp[4];
                        ldsm_x4(tmp, Khb + swz(n, g));
                        bHf[j*2][0]=tmp[0]; bHf[j*2][1]=tmp[1];
                        bHf[j*2+1][0]=tmp[2]; bHf[j*2+1][1]=tmp[3];
                    }
#pragma unroll
                    for (int nt=0;nt<4;nt++) mma16816(acc[nt], aH, bHf[nt]);
                    uint32_t bLf[4][2];
#pragma unroll
                    for (int j=0;j<2;j++){
                        int n = nbase + j*16 + (lane>>4)*8 + (lane&7);
                        int g = gk + ((lane>>3)&1);
                        uint32_t tmp[4];
                        ldsm_x4(tmp, Klb + swz(n, g));
                        bLf[j*2][0]=tmp[0]; bLf[j*2][1]=tmp[1];
                        bLf[j*2+1][0]=tmp[2]; bLf[j*2+1][1]=tmp[3];
                    }
#pragma unroll
                    for (int nt=0;nt<4;nt++) mma16816(acc[nt], aH, bLf[nt]);
                    uint32_t aL[4];
                    ldsm_x4(aL, Qlb + swz(q0+lr, gk+lk));
#pragma unroll
                    for (int nt=0;nt<4;nt++) mma16816(acc[nt], aL, bHf[nt]);
                }
            }
            {
                int row = q0 + (lane>>2);
#pragma unroll
                for (int nt=0;nt<4;nt++){
                    int col = mc*128 + nbase + nt*8 + (lane&3)*2;
                    lg[row*Mm + col]       = acc[nt][0]*0.125f;
                    lg[row*Mm + col+1]     = acc[nt][1]*0.125f;
                    lg[(row+8)*Mm + col]   = acc[nt][2]*0.125f;
                    lg[(row+8)*Mm + col+1] = acc[nt][3]*0.125f;
                }
            }
            kb ^= 1;
            __syncthreads();
        }
        // ---- masked softmax + head-mean ----
        {
            for (int q=wid; q<32; q+=8){
                float* row = &lg[q*Mm];
                float mx = -1e30f;
                for (int m=lane;m<Mm;m+=32) if (msk[m]!=0) mx = fmaxf(mx, row[m]);
#pragma unroll
                for (int o=16;o;o>>=1) mx = fmaxf(mx, __shfl_xor_sync(0xffffffffu,mx,o));
                float ssum = 0.f;
                for (int m=lane;m<Mm;m+=32){
                    float wv = (msk[m]!=0) ? expf(row[m]-mx) : 0.f;
                    row[m]=wv; ssum += wv;
                }
#pragma unroll
                for (int o=16;o;o>>=1) ssum += __shfl_xor_sync(0xffffffffu,ssum,o);
                float inv = 1.0f/ssum;
                for (int m=lane;m<Mm;m+=32){
                    float wv = row[m]*inv;
                    row[m]=wv;
                    macc[q*Mm+m] += wv;
                }
            }
        }
        __syncthreads();
        // ---- P @ V ----
        float acc2[2][4];
#pragma unroll
        for (int i=0;i<2;i++)
#pragma unroll
            for (int e=0;e<4;e++) acc2[i][e]=0.f;
        loadVT(head, 0, 0);
        int vb = 0;
        for (int mc=0; mc<16; mc++){
            if (t < 128){
                int row = t>>2, g = t&3;
                const float* pl = &lg[row*Mm + mc*32 + g*8];
                float4 x0 = *(const float4*)pl, x1 = *(const float4*)(pl+4);
                uint4 hq, lq; split8(x0, x1, hq, lq);
                *(uint4*)(sm8 + SA_P + swz(row,g))        = hq;
                *(uint4*)(sm8 + SA_P + 2048 + swz(row,g)) = lq;
            }
            if (mc < 15){ loadVT(head, mc+1, vb^1); CP_WAIT1(); } else { CP_WAIT0(); }
            __syncthreads();
            uint32_t VThb = sb + SA_VT + vb*8192;
            uint32_t VTlb = VThb + 4096;
#pragma unroll
            for (int ksI=0; ksI<2; ksI++){
                int gk = ksI*2;
                uint32_t aH[4];
                ldsm_x4(aH, sb + SA_P + swz(q0+lr, gk+lk));
                uint32_t bHf[2][2];
                {
                    int n = d0 + (lane>>4)*8 + (lane&7);
                    int g = gk + ((lane>>3)&1);
                    uint32_t tmp[4];
                    ldsm_x4(tmp, VThb + swz(n, g));
                    bHf[0][0]=tmp[0]; bHf[0][1]=tmp[1];
                    bHf[1][0]=tmp[2]; bHf[1][1]=tmp[3];
                }
#pragma unroll
                for (int nt=0;nt<2;nt++) mma16816(acc2[nt], aH, bHf[nt]);
                uint32_t bLf[2][2];
                {
                    int n = d0 + (lane>>4)*8 + (lane&7);
                    int g = gk + ((lane>>3)&1);
                    uint32_t tmp[4];
                    ldsm_x4(tmp, VTlb + swz(n, g));
                    bLf[0][0]=tmp[0]; bLf[0][1]=tmp[1];
                    bLf[1][0]=tmp[2]; bLf[1][1]=tmp[3];
                }
#pragma unroll
                for (int nt=0;nt<2;nt++) mma16816(acc2[nt], aH, bLf[nt]);
                uint32_t aL[4];
                ldsm_x4(aL, sb + SA_P + 2048 + swz(q0+lr, gk+lk));
#pragma unroll
                for (int nt=0;nt<2;nt++) mma16816(acc2[nt], aL, bHf[nt]);
            }
            vb ^= 1;
            __syncthreads();
        }
        // write attended as split bf16
        {
            int row = q0 + (lane>>2);
#pragma unroll
            for (int nt=0;nt<2;nt++){
                int col = d0 + nt*8 + (lane&3)*2;
                float v0=acc2[nt][0], v1=acc2[nt][1], v2=acc2[nt][2], v3=acc2[nt][3];
                __nv_bfloat16 h0=__float2bfloat16(v0), h1=__float2bfloat16(v1);
                __nv_bfloat16 h2=__float2bfloat16(v2), h3=__float2bfloat16(v3);
                __nv_bfloat16 l0=__float2bfloat16(v0-__bfloat162float(h0));
                __nv_bfloat16 l1=__float2bfloat16(v1-__bfloat162float(h1));
                __nv_bfloat16 l2=__float2bfloat16(v2-__bfloat162float(h2));
                __nv_bfloat16 l3=__float2bfloat16(v3-__bfloat162float(h3));
                size_t o0 = (size_t)(b*Ss + s0 + row)*Hh + head*64 + col;
                size_t o1 = (size_t)(b*Ss + s0 + row + 8)*Hh + head*64 + col;
                *(__nv_bfloat162*)(ATTh + o0) = __nv_bfloat162(h0,h1);
                *(__nv_bfloat162*)(ATTh + o1) = __nv_bfloat162(h2,h3);
                *(__nv_bfloat162*)(ATTl + o0) = __nv_bfloat162(l0,l1);
                *(__nv_bfloat162*)(ATTl + o1) = __nv_bfloat162(l2,l3);
            }
        }
    }
    __syncthreads();
    for (int i=t;i<32*Mm;i+=256){
        int q = i>>9, m = i&511;
        mem_attn[((size_t)(b*Ss + s0 + q))*Mm + m] = macc[i]*(1.0f/16.0f);
    }
}

// ================= gate GEMV =================
__global__ void gate_kernel(const float* __restrict__ gg, const float* __restrict__ Wg2,
                            const float* __restrict__ bg2, float* __restrict__ gate)
{
    int r = blockIdx.x*8 + (threadIdx.x>>5);
    int lane = threadIdx.x & 31;
    const float* row = gg + (size_t)r*Hh;
    float s = 0.f;
    for (int i=lane;i<Hh;i+=32) s = fmaf(row[i], Wg2[i], s);
#pragma unroll
    for (int o=16;o;o>>=1) s += __shfl_xor_sync(0xffffffffu,s,o);
    if (lane==0) gate[r] = 1.0f/(1.0f + expf(-(s + bg2[0])));
}

// ================= layernorm + gated residual =================
__global__ void ln_combine_kernel(
    const float* __restrict__ t2, const float* __restrict__ lng, const float* __restrict__ lnb,
    const float* __restrict__ gate, const float* __restrict__ hidden, float* __restrict__ out)
{
    __shared__ float red[8];
    int r = blockIdx.x;
    int t = threadIdx.x;
    const float* row = t2 + (size_t)r*Hh;
    float x[4];
#pragma unroll
    for (int j=0;j<4;j++) x[j] = row[t + 256*j];
    float s = x[0]+x[1]+x[2]+x[3];
#pragma unroll
    for (int o=16;o;o>>=1) s += __shfl_xor_sync(0xffffffffu,s,o);
    if ((t&31)==0) red[t>>5] = s;
    __syncthreads();
    float mu = (red[0]+red[1]+red[2]+red[3]+red[4]+red[5]+red[6]+red[7]) * (1.0f/Hh);
    __syncthreads();
    float s2 = 0.f;
#pragma unroll
    for (int j=0;j<4;j++){ float d = x[j]-mu; s2 = fmaf(d,d,s2); }
#pragma unroll
    for (int o=16;o;o>>=1) s2 += __shfl_xor_sync(0xffffffffu,s2,o);
    if ((t&31)==0) red[t>>5] = s2;
    __syncthreads();
    float var = (red[0]+red[1]+red[2]+red[3]+red[4]+red[5]+red[6]+red[7]) * (1.0f/Hh);
    float rs = rsqrtf(var + 1e-5f);
    float gt = gate[r];
    const float* hrow = hidden + (size_t)r*Hh;
#pragma unroll
    for (int j=0;j<4;j++){
        int idx = t + 256*j;
        float f = (x[j]-mu)*rs*lng[idx] + lnb[idx];
        out[(size_t)r*Hh + idx] = gt*f + (1.0f-gt)*hrow[idx];
    }
}

// ================= launch =================
extern "C" void kernel_launch(void* const* d_in, const int* in_sizes, int n_in,
                              void* d_out, int out_size)
{
    (void)in_sizes; (void)n_in; (void)out_size;
    const float* hidden = (const float*)d_in[0];
    const float* memory = (const float*)d_in[1];
    const int*   mask   = (const int*)  d_in[2];
    /* d_in[3] surprise_score: exact algebraic no-op */
    const float* Wq  = (const float*)d_in[4];
    const float* bq  = (const float*)d_in[5];
    const float* Wk  = (const float*)d_in[6];
    const float* bk  = (const float*)d_in[7];
    const float* Wv  = (const float*)d_in[8];
    const float* bv  = (const float*)d_in[9];
    const float* W1  = (const float*)d_in[10];
    const float* b1  = (const float*)d_in[11];
    const float* W2  = (const float*)d_in[12];
    const float* b2  = (const float*)d_in[13];
    const float* lng = (const float*)d_in[14];
    const float* lnb = (const float*)d_in[15];
    const float* Wg1 = (const float*)d_in[16];
    const float* bg1 = (const float*)d_in[17];
    const float* Wg2 = (const float*)d_in[18];
    const float* bg2 = (const float*)d_in[19];

    float *pT2,*pGG,*pGate;
    cudaGetSymbolAddress((void**)&pT2,  g_t2);
    cudaGetSymbolAddress((void**)&pGG,  g_gg);
    cudaGetSymbolAddress((void**)&pGate,g_gate);

    __nv_bfloat16 *pHsh,*pHsl,*pMsh,*pMsl,*pQh,*pQl,*pKh,*pKl,*pVTh,*pVTl,*pATTh,*pATTl,*pH1h,*pH1l;
    cudaGetSymbolAddress((void**)&pHsh, g_Hsh); cudaGetSymbolAddress((void**)&pHsl, g_Hsl);
    cudaGetSymbolAddress((void**)&pMsh, g_Msh); cudaGetSymbolAddress((void**)&pMsl, g_Msl);
    cudaGetSymbolAddress((void**)&pQh,  g_Qh);  cudaGetSymbolAddress((void**)&pQl,  g_Ql);
    cudaGetSymbolAddress((void**)&pKh,  g_Kh);  cudaGetSymbolAddress((void**)&pKl,  g_Kl);
    cudaGetSymbolAddress((void**)&pVTh, g_VTh); cudaGetSymbolAddress((void**)&pVTl, g_VTl);
    cudaGetSymbolAddress((void**)&pATTh,g_ATTh);cudaGetSymbolAddress((void**)&pATTl,g_ATTl);
    cudaGetSymbolAddress((void**)&pH1h, g_H1h); cudaGetSymbolAddress((void**)&pH1l, g_H1l);

    __nv_bfloat16 *wqh,*wql,*wkh,*wkl,*wvh,*wvl,*w1h,*w1l,*w2h,*w2l,*wg1h,*wg1l;
    cudaGetSymbolAddress((void**)&wqh,  g_WqT_h);  cudaGetSymbolAddress((void**)&wql,  g_WqT_l);
    cudaGetSymbolAddress((void**)&wkh,  g_WkT_h);  cudaGetSymbolAddress((void**)&wkl,  g_WkT_l);
    cudaGetSymbolAddress((void**)&wvh,  g_WvT_h);  cudaGetSymbolAddress((void**)&wvl,  g_WvT_l);
    cudaGetSymbolAddress((void**)&w1h,  g_W1T_h);  cudaGetSymbolAddress((void**)&w1l,  g_W1T_l);
    cudaGetSymbolAddress((void**)&w2h,  g_W2T_h);  cudaGetSymbolAddress((void**)&w2l,  g_W2T_l);
    cudaGetSymbolAddress((void**)&wg1h, g_Wg1T_h); cudaGetSymbolAddress((void**)&wg1l, g_Wg1T_l);

    float* out      = (float*)d_out;
    float* mem_attn = out + (size_t)ROWS*Hh;

    cudaFuncSetAttribute(gemm_mma, cudaFuncAttributeMaxDynamicSharedMemorySize, GEMM_SMEM);
    cudaFuncSetAttribute(attn_mma, cudaFuncAttributeMaxDynamicSharedMemorySize, ATT_SMEM);

    dim3 tb(32,8);
    // activation + weight splits
    asplit<<<ROWS*Hh/2048, 256>>>((const float4*)hidden, pHsh, pHsl);
    asplit<<<KVROWS*HQq/2048, 256>>>((const float4*)memory, pMsh, pMsl);
    wsplitT<<<dim3(32,32), tb>>>(Wq,  wqh,  wql,  1024, 1024);
    wsplitT<<<dim3(32, 8), tb>>>(Wk,  wkh,  wkl,   256, 1024);
    wsplitT<<<dim3(32, 8), tb>>>(Wv,  wvh,  wvl,   256, 1024);
    wsplitT<<<dim3(32,64), tb>>>(W1,  w1h,  w1l,  2048, 1024);
    wsplitT<<<dim3(32,32), tb>>>(W2,  w2h,  w2l,  1024, 1024);
    wsplitT<<<dim3(32,64), tb>>>(Wg1, wg1h, wg1l, 2048, 1024);

    const int BIG = 1<<30;
    // projections
    gemm_mma<<<dim3(8,64), 256, GEMM_SMEM>>>(pHsh, pHsl, Hh, (const __nv_bfloat16*)0,(const __nv_bfloat16*)0, 0, BIG,
        wqh, wql, bq, (float*)0, pQh, pQl, Hh, Hh, 2);
    gemm_mma<<<dim3(8,16), 256, GEMM_SMEM>>>(pMsh, pMsl, HQq, (const __nv_bfloat16*)0,(const __nv_bfloat16*)0, 0, BIG,
        wkh, wkl, bk, (float*)0, pKh, pKl, Hh, HQq, 2);
    gemm_mma<<<dim3(8,16), 256, GEMM_SMEM>>>(pMsh, pMsl, HQq, (const __nv_bfloat16*)0,(const __nv_bfloat16*)0, 0, BIG,
        wvh, wvl, bv, (float*)0, pVTh, pVTl, Hh, HQq, 3);

    // MMA attention -> split attended + mem_attn
    attn_mma<<<Bb*64, 256, ATT_SMEM>>>(pQh, pQl, pKh, pKl, pVTh, pVTl, mask, pATTh, pATTl, mem_attn);

    // MLP: A = concat(hidden, att), all pre-split
    gemm_mma<<<dim3(8,64), 256, GEMM_SMEM>>>(pHsh, pHsl, Hh, pATTh, pATTl, Hh, Hh,
        w1h, w1l, b1, (float*)0, pH1h, pH1l, Hh, 2*Hh, 4);
    gemm_mma<<<dim3(8,64), 256, GEMM_SMEM>>>(pHsh, pHsl, Hh, pATTh, pATTl, Hh, Hh,
        wg1h, wg1l, bg1, pGG, (__nv_bfloat16*)0, (__nv_bfloat16*)0, Hh, 2*Hh, 1);
    gemm_mma<<<dim3(8,64), 256, GEMM_SMEM>>>(pH1h, pH1l, Hh, (const __nv_bfloat16*)0,(const __nv_bfloat16*)0, 0, BIG,
        w2h, w2l, b2, pT2, (__nv_bfloat16*)0, (__nv_bfloat16*)0, Hh, Hh, 0);

    // gate + final layernorm/mix
    gate_kernel<<<1024, 256>>>(pGG, Wg2, bg2, pGate);
    ln_combine_kernel<<<ROWS, 256>>>(pT2, lng, lnb, pGate, hidden, out);
}

// round 8
// speedup vs baseline: 4.8212x; 1.6398x over previous
#include <cuda_runtime.h>
#include <cuda_fp16.h>
#include <math.h>
#include <stdint.h>

#define Bb   4
#define Ss   2048
#define Hh   1024
#define Mm   512
#define NHn  16
#define HDd  64
#define HQq  256
#define ROWS   (Bb*Ss)    /* 8192 */
#define KVROWS (Bb*Mm)    /* 2048 */

// ================= helpers =================
__device__ __forceinline__ uint32_t smem_u32(const void* p){
    uint32_t a;
    asm("{ .reg .u64 t; cvta.to.shared.u64 t, %1; cvt.u32.u64 %0, t; }" : "=r"(a) : "l"(p));
    return a;
}
#define CP_ASYNC16(dst, src) \
    asm volatile("cp.async.cg.shared.global [%0], [%1], 16;" :: "r"(dst), "l"(src))
#define CP_COMMIT() asm volatile("cp.async.commit_group;" ::: "memory")
#define CP_WAIT0()  asm volatile("cp.async.wait_group 0;" ::: "memory")
#define CP_WAIT1()  asm volatile("cp.async.wait_group 1;" ::: "memory")

__device__ __forceinline__ void ldsm_x4(uint32_t* r, uint32_t addr){
    asm volatile("ldmatrix.sync.aligned.m8n8.x4.shared.b16 {%0,%1,%2,%3}, [%4];"
        : "=r"(r[0]),"=r"(r[1]),"=r"(r[2]),"=r"(r[3]) : "r"(addr));
}
__device__ __forceinline__ void mma16816(float* d, const uint32_t* a, const uint32_t* b){
    asm volatile("mma.sync.aligned.m16n8k16.row.col.f32.f16.f16.f32 "
        "{%0,%1,%2,%3}, {%4,%5,%6,%7}, {%8,%9}, {%0,%1,%2,%3};"
        : "+f"(d[0]),"+f"(d[1]),"+f"(d[2]),"+f"(d[3])
        : "r"(a[0]),"r"(a[1]),"r"(a[2]),"r"(a[3]), "r"(b[0]),"r"(b[1]));
}

__device__ __forceinline__ float gelu_exact(float x){
    return 0.5f*x*(1.0f + erff(x*0.70710678118654752f));
}

// pack 8 fp32 -> 8 fp16 in a uint4
__device__ __forceinline__ uint4 cvt8(float4 x0, float4 x1){
    float f[8] = {x0.x,x0.y,x0.z,x0.w,x1.x,x1.y,x1.z,x1.w};
    uint32_t h[8];
#pragma unroll
    for (int j=0;j<8;j++) h[j] = (uint32_t)__half_as_ushort(__float2half(f[j]));
    return make_uint4(h[0]|(h[1]<<16), h[2]|(h[3]<<16), h[4]|(h[5]<<16), h[6]|(h[7]<<16));
}

// ================= scratch (device globals) =================
__device__ float g_t2 [ROWS*Hh];
__device__ float g_gg [ROWS*Hh];
__device__ float g_gate[ROWS];
__device__ __half g_Hs [ROWS*Hh];       // hidden fp16
__device__ __half g_Ms [KVROWS*HQq];    // memory fp16
__device__ __half g_Q  [ROWS*Hh];
__device__ __half g_K  [KVROWS*Hh];
__device__ __half g_VT [Bb*Hh*Mm];
__device__ __half g_ATT[ROWS*Hh];
__device__ __half g_H1 [ROWS*Hh];
// transposed weights [N][K] fp16
__device__ __half g_WqT [1024*1024];
__device__ __half g_WkT [1024*256];
__device__ __half g_WvT [1024*256];
__device__ __half g_W1T [1024*2048];
__device__ __half g_W2T [1024*1024];
__device__ __half g_Wg1T[1024*2048];

// ========== activation fp32 -> fp16 convert ==========
__global__ void aconv(const float4* __restrict__ X, __half* __restrict__ Xh)
{
    size_t i = (size_t)blockIdx.x*256 + threadIdx.x;   // one float8 per thread
    *(uint4*)(Xh + 8*i) = cvt8(X[2*i], X[2*i+1]);
}

// ========== weight transpose to fp16: W[K][N] -> T[N][K] ==========
__global__ void wconvT(const float* __restrict__ W, __half* __restrict__ Th, int K, int N)
{
    __shared__ float s[32][33];
    int n0 = blockIdx.x*32, k0 = blockIdx.y*32;
    int tx = threadIdx.x, ty = threadIdx.y; // 32x8
#pragma unroll
    for (int i=0;i<4;i++)
        s[ty+i*8][tx] = W[(size_t)(k0+ty+i*8)*N + n0+tx];
    __syncthreads();
#pragma unroll
    for (int i=0;i<4;i++){
        int n = ty + i*8;
        Th[(size_t)(n0+n)*K + k0 + tx] = __float2half(s[tx][n]);
    }
}

// ========== warp-MMA fp16 GEMM: C = act(A @ W^T + bias) ==========
// modes: 0 fp32 C; 1 fp32+gelu C; 2 fp16 C; 3 fp16 VT[b][col][m]; 4 gelu + fp16 C
#define AH_OFF 0
#define BH_OFF 8192
#define BUF_SZ 16384
#define GEMM_SMEM (2*BUF_SZ + 512)

__device__ __forceinline__ uint32_t swz(int row, int g){
    return (uint32_t)(row*64 + ((g ^ ((row>>1)&3))<<4));
}

__global__ void __launch_bounds__(256,1) gemm_mma(
    const __half* __restrict__ A0, int lda0,
    const __half* __restrict__ A1, int lda1, int ks,
    const __half* __restrict__ Bm,
    const float* __restrict__ bias, float* __restrict__ C,
    __half* __restrict__ Ch, int ldc, int K, int mode)
{
    extern __shared__ __align__(128) char smem[];
    uint32_t sb = smem_u32(smem);
    float* bias_s = (float*)(smem + 2*BUF_SZ);

    int t = threadIdx.x, lane = t&31, wid = t>>5;
    int m0 = blockIdx.y*128, n0 = blockIdx.x*128;
    int mbase = (wid>>2)*64, nbase = (wid&3)*32;

    if (t < 128) bias_s[t] = bias[n0 + t];

    int nch = K >> 5;
    int ar_r  = t>>1;
    int ar_kh = (t&1)*16;
    int g0    = ar_kh>>3;

    auto stage = [&](int c, uint32_t sbuf){
        int kt = c*32;
        const __half* Ap; int lda, ko;
        if (kt < ks){ Ap = A0; lda = lda0; ko = kt; }
        else        { Ap = A1; lda = lda1; ko = kt - ks; }
        const __half* aH = Ap + (size_t)(m0+ar_r)*lda + ko + ar_kh;
        const __half* bH = Bm + (size_t)(n0+ar_r)*K + kt + ar_kh;
        CP_ASYNC16(sbuf + AH_OFF + swz(ar_r, g0),   aH);
        CP_ASYNC16(sbuf + AH_OFF + swz(ar_r, g0+1), aH+8);
        CP_ASYNC16(sbuf + BH_OFF + swz(ar_r, g0),   bH);
        CP_ASYNC16(sbuf + BH_OFF + swz(ar_r, g0+1), bH+8);
        CP_COMMIT();
    };

    float acc[4][4][4];
#pragma unroll
    for (int i=0;i<4;i++)
#pragma unroll
        for (int j=0;j<4;j++)
#pragma unroll
            for (int e=0;e<4;e++) acc[i][j][e]=0.f;

    stage(0, sb);

    for (int c=0; c<nch; c++){
        int b = c & 1;
        uint32_t sbuf = sb + b*BUF_SZ;
        if (c+1 < nch){ stage(c+1, sb + (b^1)*BUF_SZ); CP_WAIT1(); }
        else          { CP_WAIT0(); }
        __syncthreads();

        int lr = lane&15, lk = lane>>4;
#pragma unroll
        for (int ksI=0; ksI<2; ksI++){
            int gk = ksI*2;
            uint32_t aH[4][4];
#pragma unroll
            for (int mt=0;mt<4;mt++){
                int row = mbase + mt*16 + lr;
                ldsm_x4(aH[mt], sbuf + AH_OFF + swz(row, gk+lk));
            }
            uint32_t bHf[4][2];
#pragma unroll
            for (int j=0;j<2;j++){
                int n = nbase + j*16 + (lane>>4)*8 + (lane&7);
                int g = gk + ((lane>>3)&1);
                uint32_t tmp[4];
                ldsm_x4(tmp, sbuf + BH_OFF + swz(n, g));
                bHf[j*2][0]=tmp[0]; bHf[j*2][1]=tmp[1];
                bHf[j*2+1][0]=tmp[2]; bHf[j*2+1][1]=tmp[3];
            }
#pragma unroll
            for (int mt=0;mt<4;mt++)
#pragma unroll
                for (int nt=0;nt<4;nt++) mma16816(acc[mt][nt], aH[mt], bHf[nt]);
        }
        __syncthreads();
    }

    // ---- epilogue ----
    int actv = (mode==1 || mode==4);
#pragma unroll
    for (int mt=0;mt<4;mt++){
        int r0 = m0 + mbase + mt*16 + (lane>>2);
#pragma unroll
        for (int nt=0;nt<4;nt++){
            int cc = nbase + nt*8 + (lane&3)*2;
            float b0 = bias_s[cc], b1 = bias_s[cc+1];
            float v0 = acc[mt][nt][0] + b0;
            float v1 = acc[mt][nt][1] + b1;
            float v2 = acc[mt][nt][2] + b0;
            float v3 = acc[mt][nt][3] + b1;
            if (actv){ v0=gelu_exact(v0); v1=gelu_exact(v1); v2=gelu_exact(v2); v3=gelu_exact(v3); }
            if (mode <= 1){
                *(float2*)(C + (size_t)r0*ldc     + n0 + cc) = make_float2(v0,v1);
                *(float2*)(C + (size_t)(r0+8)*ldc + n0 + cc) = make_float2(v2,v3);
            } else {
                __half h0=__float2half(v0), h1=__float2half(v1);
                __half h2=__float2half(v2), h3=__float2half(v3);
                if (mode != 3){
                    *(__half2*)(Ch + (size_t)r0*ldc + n0+cc)     = __half2(h0,h1);
                    *(__half2*)(Ch + (size_t)(r0+8)*ldc + n0+cc) = __half2(h2,h3);
                } else { // VT[b][col][m]
                    int bb = r0>>9, m = r0&511, col = n0+cc;
                    Ch[((size_t)bb*Hh + col  )*Mm + m  ] = h0;
                    Ch[((size_t)bb*Hh + col+1)*Mm + m  ] = h1;
                    Ch[((size_t)bb*Hh + col  )*Mm + m+8] = h2;
                    Ch[((size_t)bb*Hh + col+1)*Mm + m+8] = h3;
                }
            }
        }
    }
}

// ================= MMA attention (fp16 single-product) =================
#define SA_LG   0          /* float [32][512]  65536 */
#define SA_MACC 65536      /* float [32][512]  65536 */
#define SA_MSK  131072     /* int [512]        2048  */
#define SA_Q    133120     /* 2 tiles [32][32] fp16 = 4096 */
#define SA_K    137216     /* 2 bufs x {2 tiles [128][32] fp16} = 2x16384 */
#define SA_VT   169984     /* 2 bufs x [64][32] fp16 = 2x4096 */
#define SA_P    178176     /* [32][32] fp16 = 2048 */
#define ATT_SMEM 180224

__global__ void __launch_bounds__(256,1) attn_mma(
    const __half* __restrict__ Qm, const __half* __restrict__ Km,
    const __half* __restrict__ VTm, const int* __restrict__ mask,
    __half* __restrict__ ATT, float* __restrict__ mem_attn)
{
    extern __shared__ __align__(128) char sm8[];
    uint32_t sb = smem_u32(sm8);
    float* lg   = (float*)(sm8 + SA_LG);
    float* macc = (float*)(sm8 + SA_MACC);
    int*   msk  = (int*)  (sm8 + SA_MSK);

    int b  = blockIdx.x >> 6;
    int s0 = (blockIdx.x & 63) * 32;
    int t  = threadIdx.x, lane = t&31, wid = t>>5;
    int q0 = (wid>>2)*16;
    int nbase = (wid&3)*32;
    int d0 = (wid&3)*16;
    int lr = lane&15, lk = lane>>4;

    for (int i=t;i<Mm;i+=256)     msk[i] = mask[b*Mm + i];
    for (int i=t;i<32*Mm;i+=256)  macc[i] = 0.f;

    auto loadK = [&](int head, int mc, int kb){
        uint32_t base = sb + SA_K + kb*16384;
#pragma unroll
        for (int i=0;i<4;i++){
            int j = t + i*256;          // 1024 jobs: 2 tiles x 128 rows x 4 groups
            int tile = j>>9, rem = j&511;
            int row = rem>>2, g = rem&3;
            const __half* src = Km
                + (size_t)(b*Mm + mc*128 + row)*Hh + head*64 + tile*32 + g*8;
            CP_ASYNC16(base + tile*8192 + swz(row,g), src);
        }
        CP_COMMIT();
    };
    auto loadVT = [&](int head, int mc, int vb){
        uint32_t base = sb + SA_VT + vb*4096;
        {
            int row = t>>2, g = t&3;    // 256 jobs: 64 rows x 4 groups
            const __half* src = VTm
                + ((size_t)b*Hh + head*64 + row)*Mm + mc*32 + g*8;
            CP_ASYNC16(base + swz(row,g), src);
        }
        CP_COMMIT();
    };

    for (int head=0; head<NHn; head++){
        __syncthreads();
        // Q tiles: 2 tiles x 32 rows x 4 groups = 256 jobs
        {
            int tile = t>>7, rem = t&127;
            int row = rem>>2, g = rem&3;
            const __half* src = Qm
                + (size_t)(b*Ss + s0 + row)*Hh + head*64 + tile*32 + g*8;
            CP_ASYNC16(sb + SA_Q + tile*2048 + swz(row,g), src);
        }
        CP_COMMIT();
        loadK(head, 0, 0);
        int kb = 0;
        for (int mc=0; mc<4; mc++){
            if (mc < 3){ loadK(head, mc+1, kb^1); CP_WAIT1(); } else { CP_WAIT0(); }
            __syncthreads();
            float acc[4][4];
#pragma unroll
            for (int i=0;i<4;i++)
#pragma unroll
                for (int e=0;e<4;e++) acc[i][e]=0.f;
            uint32_t kbase = sb + SA_K + kb*16384;
#pragma unroll
            for (int dc=0; dc<2; dc++){
                uint32_t Qhb = sb + SA_Q + dc*2048;
                uint32_t Khb = kbase + dc*8192;
#pragma unroll
                for (int ksI=0; ksI<2; ksI++){
                    int gk = ksI*2;
                    uint32_t aH[4];
                    ldsm_x4(aH, Qhb + swz(q0+lr, gk+lk));
                    uint32_t bHf[4][2];
#pragma unroll
                    for (int j=0;j<2;j++){
                        int n = nbase + j*16 + (lane>>4)*8 + (lane&7);
                        int g = gk + ((lane>>3)&1);
                        uint32_t tmp[4];
                        ldsm_x4(tmp, Khb + swz(n, g));
                        bHf[j*2][0]=tmp[0]; bHf[j*2][1]=tmp[1];
                        bHf[j*2+1][0]=tmp[2]; bHf[j*2+1][1]=tmp[3];
                    }
#pragma unroll
                    for (int nt=0;nt<4;nt++) mma16816(acc[nt], aH, bHf[nt]);
                }
            }
            {
                int row = q0 + (lane>>2);
#pragma unroll
                for (int nt=0;nt<4;nt++){
                    int col = mc*128 + nbase + nt*8 + (lane&3)*2;
                    lg[row*Mm + col]       = acc[nt][0]*0.125f;
                    lg[row*Mm + col+1]     = acc[nt][1]*0.125f;
                    lg[(row+8)*Mm + col]   = acc[nt][2]*0.125f;
                    lg[(row+8)*Mm + col+1] = acc[nt][3]*0.125f;
                }
            }
            kb ^= 1;
            __syncthreads();
        }
        // ---- masked softmax + head-mean ----
        {
            for (int q=wid; q<32; q+=8){
                float* row = &lg[q*Mm];
                float mx = -1e30f;
                for (int m=lane;m<Mm;m+=32) if (msk[m]!=0) mx = fmaxf(mx, row[m]);
#pragma unroll
                for (int o=16;o;o>>=1) mx = fmaxf(mx, __shfl_xor_sync(0xffffffffu,mx,o));
                float ssum = 0.f;
                for (int m=lane;m<Mm;m+=32){
                    float wv = (msk[m]!=0) ? expf(row[m]-mx) : 0.f;
                    row[m]=wv; ssum += wv;
                }
#pragma unroll
                for (int o=16;o;o>>=1) ssum += __shfl_xor_sync(0xffffffffu,ssum,o);
                float inv = 1.0f/ssum;
                for (int m=lane;m<Mm;m+=32){
                    float wv = row[m]*inv;
                    row[m]=wv;
                    macc[q*Mm+m] += wv;
                }
            }
        }
        __syncthreads();
        // ---- P @ V ----
        float acc2[2][4];
#pragma unroll
        for (int i=0;i<2;i++)
#pragma unroll
            for (int e=0;e<4;e++) acc2[i][e]=0.f;
        loadVT(head, 0, 0);
        int vb = 0;
        for (int mc=0; mc<16; mc++){
            if (t < 128){
                int row = t>>2, g = t&3;
                const float* pl = &lg[row*Mm + mc*32 + g*8];
                float4 x0 = *(const float4*)pl, x1 = *(const float4*)(pl+4);
                *(uint4*)(sm8 + SA_P + swz(row,g)) = cvt8(x0, x1);
            }
            if (mc < 15){ loadVT(head, mc+1, vb^1); CP_WAIT1(); } else { CP_WAIT0(); }
            __syncthreads();
            uint32_t VThb = sb + SA_VT + vb*4096;
#pragma unroll
            for (int ksI=0; ksI<2; ksI++){
                int gk = ksI*2;
                uint32_t aH[4];
                ldsm_x4(aH, sb + SA_P + swz(q0+lr, gk+lk));
                uint32_t bHf[2][2];
                {
                    int n = d0 + (lane>>4)*8 + (lane&7);
                    int g = gk + ((lane>>3)&1);
                    uint32_t tmp[4];
                    ldsm_x4(tmp, VThb + swz(n, g));
                    bHf[0][0]=tmp[0]; bHf[0][1]=tmp[1];
                    bHf[1][0]=tmp[2]; bHf[1][1]=tmp[3];
                }
#pragma unroll
                for (int nt=0;nt<2;nt++) mma16816(acc2[nt], aH, bHf[nt]);
            }
            vb ^= 1;
            __syncthreads();
        }
        // write attended (fp16)
        {
            int row = q0 + (lane>>2);
#pragma unroll
            for (int nt=0;nt<2;nt++){
                int col = d0 + nt*8 + (lane&3)*2;
                size_t o0 = (size_t)(b*Ss + s0 + row)*Hh + head*64 + col;
                size_t o1 = (size_t)(b*Ss + s0 + row + 8)*Hh + head*64 + col;
                *(__half2*)(ATT + o0) = __half2(__float2half(acc2[nt][0]), __float2half(acc2[nt][1]));
                *(__half2*)(ATT + o1) = __half2(__float2half(acc2[nt][2]), __float2half(acc2[nt][3]));
            }
        }
    }
    __syncthreads();
    for (int i=t;i<32*Mm;i+=256){
        int q = i>>9, m = i&511;
        mem_attn[((size_t)(b*Ss + s0 + q))*Mm + m] = macc[i]*(1.0f/16.0f);
    }
}

// ================= gate GEMV =================
__global__ void gate_kernel(const float* __restrict__ gg, const float* __restrict__ Wg2,
                            const float* __restrict__ bg2, float* __restrict__ gate)
{
    int r = blockIdx.x*8 + (threadIdx.x>>5);
    int lane = threadIdx.x & 31;
    const float* row = gg + (size_t)r*Hh;
    float s = 0.f;
    for (int i=lane;i<Hh;i+=32) s = fmaf(row[i], Wg2[i], s);
#pragma unroll
    for (int o=16;o;o>>=1) s += __shfl_xor_sync(0xffffffffu,s,o);
    if (lane==0) gate[r] = 1.0f/(1.0f + expf(-(s + bg2[0])));
}

// ================= layernorm + gated residual =================
__global__ void ln_combine_kernel(
    const float* __restrict__ t2, const float* __restrict__ lng, const float* __restrict__ lnb,
    const float* __restrict__ gate, const float* __restrict__ hidden, float* __restrict__ out)
{
    __shared__ float red[8];
    int r = blockIdx.x;
    int t = threadIdx.x;
    const float* row = t2 + (size_t)r*Hh;
    float x[4];
#pragma unroll
    for (int j=0;j<4;j++) x[j] = row[t + 256*j];
    float s = x[0]+x[1]+x[2]+x[3];
#pragma unroll
    for (int o=16;o;o>>=1) s += __shfl_xor_sync(0xffffffffu,s,o);
    if ((t&31)==0) red[t>>5] = s;
    __syncthreads();
    float mu = (red[0]+red[1]+red[2]+red[3]+red[4]+red[5]+red[6]+red[7]) * (1.0f/Hh);
    __syncthreads();
    float s2 = 0.f;
#pragma unroll
    for (int j=0;j<4;j++){ float d = x[j]-mu; s2 = fmaf(d,d,s2); }
#pragma unroll
    for (int o=16;o;o>>=1) s2 += __shfl_xor_sync(0xffffffffu,s2,o);
    if ((t&31)==0) red[t>>5] = s2;
    __syncthreads();
    float var = (red[0]+red[1]+red[2]+red[3]+red[4]+red[5]+red[6]+red[7]) * (1.0f/Hh);
    float rs = rsqrtf(var + 1e-5f);
    float gt = gate[r];
    const float* hrow = hidden + (size_t)r*Hh;
#pragma unroll
    for (int j=0;j<4;j++){
        int idx = t + 256*j;
        float f = (x[j]-mu)*rs*lng[idx] + lnb[idx];
        out[(size_t)r*Hh + idx] = gt*f + (1.0f-gt)*hrow[idx];
    }
}

// ================= launch =================
extern "C" void kernel_launch(void* const* d_in, const int* in_sizes, int n_in,
                              void* d_out, int out_size)
{
    (void)in_sizes; (void)n_in; (void)out_size;
    const float* hidden = (const float*)d_in[0];
    const float* memory = (const float*)d_in[1];
    const int*   mask   = (const int*)  d_in[2];
    /* d_in[3] surprise_score: exact algebraic no-op */
    const float* Wq  = (const float*)d_in[4];
    const float* bq  = (const float*)d_in[5];
    const float* Wk  = (const float*)d_in[6];
    const float* bk  = (const float*)d_in[7];
    const float* Wv  = (const float*)d_in[8];
    const float* bv  = (const float*)d_in[9];
    const float* W1  = (const float*)d_in[10];
    const float* b1  = (const float*)d_in[11];
    const float* W2  = (const float*)d_in[12];
    const float* b2  = (const float*)d_in[13];
    const float* lng = (const float*)d_in[14];
    const float* lnb = (const float*)d_in[15];
    const float* Wg1 = (const float*)d_in[16];
    const float* bg1 = (const float*)d_in[17];
    const float* Wg2 = (const float*)d_in[18];
    const float* bg2 = (const float*)d_in[19];

    float *pT2,*pGG,*pGate;
    cudaGetSymbolAddress((void**)&pT2,  g_t2);
    cudaGetSymbolAddress((void**)&pGG,  g_gg);
    cudaGetSymbolAddress((void**)&pGate,g_gate);

    __half *pHs,*pMs,*pQ,*pK,*pVT,*pATT,*pH1;
    cudaGetSymbolAddress((void**)&pHs,  g_Hs);
    cudaGetSymbolAddress((void**)&pMs,  g_Ms);
    cudaGetSymbolAddress((void**)&pQ,   g_Q);
    cudaGetSymbolAddress((void**)&pK,   g_K);
    cudaGetSymbolAddress((void**)&pVT,  g_VT);
    cudaGetSymbolAddress((void**)&pATT, g_ATT);
    cudaGetSymbolAddress((void**)&pH1,  g_H1);

    __half *wq,*wk,*wv,*w1,*w2,*wg1;
    cudaGetSymbolAddress((void**)&wq,  g_WqT);
    cudaGetSymbolAddress((void**)&wk,  g_WkT);
    cudaGetSymbolAddress((void**)&wv,  g_WvT);
    cudaGetSymbolAddress((void**)&w1,  g_W1T);
    cudaGetSymbolAddress((void**)&w2,  g_W2T);
    cudaGetSymbolAddress((void**)&wg1, g_Wg1T);

    float* out      = (float*)d_out;
    float* mem_attn = out + (size_t)ROWS*Hh;

    cudaFuncSetAttribute(gemm_mma, cudaFuncAttributeMaxDynamicSharedMemorySize, GEMM_SMEM);
    cudaFuncSetAttribute(attn_mma, cudaFuncAttributeMaxDynamicSharedMemorySize, ATT_SMEM);

    dim3 tb(32,8);
    // converts
    aconv<<<ROWS*Hh/2048, 256>>>((const float4*)hidden, pHs);
    aconv<<<KVROWS*HQq/2048, 256>>>((const float4*)memory, pMs);
    wconvT<<<dim3(32,32), tb>>>(Wq,  wq,  1024, 1024);
    wconvT<<<dim3(32, 8), tb>>>(Wk,  wk,   256, 1024);
    wconvT<<<dim3(32, 8), tb>>>(Wv,  wv,   256, 1024);
    wconvT<<<dim3(32,64), tb>>>(W1,  w1,  2048, 1024);
    wconvT<<<dim3(32,32), tb>>>(W2,  w2,  1024, 1024);
    wconvT<<<dim3(32,64), tb>>>(Wg1, wg1, 2048, 1024);

    const int BIG = 1<<30;
    // projections
    gemm_mma<<<dim3(8,64), 256, GEMM_SMEM>>>(pHs, Hh, (const __half*)0, 0, BIG,
        wq, bq, (float*)0, pQ, Hh, Hh, 2);
    gemm_mma<<<dim3(8,16), 256, GEMM_SMEM>>>(pMs, HQq, (const __half*)0, 0, BIG,
        wk, bk, (float*)0, pK, Hh, HQq, 2);
    gemm_mma<<<dim3(8,16), 256, GEMM_SMEM>>>(pMs, HQq, (const __half*)0, 0, BIG,
        wv, bv, (float*)0, pVT, Hh, HQq, 3);

    // MMA attention -> fp16 attended + mem_attn
    attn_mma<<<Bb*64, 256, ATT_SMEM>>>(pQ, pK, pVT, mask, pATT, mem_attn);

    // MLP: A = concat(hidden, att), pre-converted fp16
    gemm_mma<<<dim3(8,64), 256, GEMM_SMEM>>>(pHs, Hh, pATT, Hh, Hh,
        w1, b1, (float*)0, pH1, Hh, 2*Hh, 4);
    gemm_mma<<<dim3(8,64), 256, GEMM_SMEM>>>(pHs, Hh, pATT, Hh, Hh,
        wg1, bg1, pGG, (__half*)0, Hh, 2*Hh, 1);
    gemm_mma<<<dim3(8,64), 256, GEMM_SMEM>>>(pH1, Hh, (const __half*)0, 0, BIG,
        w2, b2, pT2, (__half*)0, Hh, Hh, 0);

    // gate + final layernorm/mix
    gate_kernel<<<1024, 256>>>(pGG, Wg2, bg2, pGate);
    ln_combine_kernel<<<ROWS, 256>>>(pT2, lng, lnb, pGate, hidden, out);
}

// round 11
// speedup vs baseline: 5.6751x; 1.1771x over previous
#include <cuda_runtime.h>
#include <cuda_fp16.h>
#include <math.h>
#include <stdint.h>

#define Bb   4
#define Ss   2048
#define Hh   1024
#define Mm   512
#define NHn  16
#define HDd  64
#define HQq  256
#define ROWS   (Bb*Ss)    /* 8192 */
#define KVROWS (Bb*Mm)    /* 2048 */

// ================= helpers =================
__device__ __forceinline__ uint32_t smem_u32(const void* p){
    uint32_t a;
    asm("{ .reg .u64 t; cvta.to.shared.u64 t, %1; cvt.u32.u64 %0, t; }" : "=r"(a) : "l"(p));
    return a;
}
#define CP_ASYNC16(dst, src) \
    asm volatile("cp.async.cg.shared.global [%0], [%1], 16;" :: "r"(dst), "l"(src))
#define CP_COMMIT() asm volatile("cp.async.commit_group;" ::: "memory")
#define CP_WAIT0()  asm volatile("cp.async.wait_group 0;" ::: "memory")
#define CP_WAIT1()  asm volatile("cp.async.wait_group 1;" ::: "memory")

__device__ __forceinline__ void ldsm_x4(uint32_t* r, uint32_t addr){
    asm volatile("ldmatrix.sync.aligned.m8n8.x4.shared.b16 {%0,%1,%2,%3}, [%4];"
        : "=r"(r[0]),"=r"(r[1]),"=r"(r[2]),"=r"(r[3]) : "r"(addr));
}
__device__ __forceinline__ void mma16816(float* d, const uint32_t* a, const uint32_t* b){
    asm volatile("mma.sync.aligned.m16n8k16.row.col.f32.f16.f16.f32 "
        "{%0,%1,%2,%3}, {%4,%5,%6,%7}, {%8,%9}, {%0,%1,%2,%3};"
        : "+f"(d[0]),"+f"(d[1]),"+f"(d[2]),"+f"(d[3])
        : "r"(a[0]),"r"(a[1]),"r"(a[2]),"r"(a[3]), "r"(b[0]),"r"(b[1]));
}

__device__ __forceinline__ float gelu_exact(float x){
    return 0.5f*x*(1.0f + erff(x*0.70710678118654752f));
}

// pack 8 fp32 -> 8 fp16 in a uint4
__device__ __forceinline__ uint4 cvt8(float4 x0, float4 x1){
    float f[8] = {x0.x,x0.y,x0.z,x0.w,x1.x,x1.y,x1.z,x1.w};
    uint32_t h[8];
#pragma unroll
    for (int j=0;j<8;j++) h[j] = (uint32_t)__half_as_ushort(__float2half(f[j]));
    return make_uint4(h[0]|(h[1]<<16), h[2]|(h[3]<<16), h[4]|(h[5]<<16), h[6]|(h[7]<<16));
}

// ================= scratch (device globals) =================
__device__ float g_t2 [ROWS*Hh];
__device__ float g_gg [ROWS*Hh];
__device__ float g_gate[ROWS];
__device__ __half g_Hs [ROWS*Hh];       // hidden fp16
__device__ __half g_Ms [KVROWS*HQq];    // memory fp16
__device__ __half g_Q  [ROWS*Hh];
__device__ __half g_K  [KVROWS*Hh];
__device__ __half g_VT [Bb*Hh*Mm];
__device__ __half g_ATT[ROWS*Hh];
__device__ __half g_H1 [ROWS*Hh];
// transposed weights [N][K] fp16
__device__ __half g_WqT [1024*1024];
__device__ __half g_WkT [1024*256];
__device__ __half g_WvT [1024*256];
__device__ __half g_W1T [1024*2048];
__device__ __half g_W2T [1024*1024];
__device__ __half g_Wg1T[1024*2048];

// ========== activation fp32 -> fp16 convert ==========
__global__ void aconv(const float4* __restrict__ X, __half* __restrict__ Xh)
{
    size_t i = (size_t)blockIdx.x*256 + threadIdx.x;
    *(uint4*)(Xh + 8*i) = cvt8(X[2*i], X[2*i+1]);
}

// ========== weight transpose to fp16: W[K][N] -> T[N][K] ==========
__global__ void wconvT(const float* __restrict__ W, __half* __restrict__ Th, int K, int N)
{
    __shared__ float s[32][33];
    int n0 = blockIdx.x*32, k0 = blockIdx.y*32;
    int tx = threadIdx.x, ty = threadIdx.y; // 32x8
#pragma unroll
    for (int i=0;i<4;i++)
        s[ty+i*8][tx] = W[(size_t)(k0+ty+i*8)*N + n0+tx];
    __syncthreads();
#pragma unroll
    for (int i=0;i<4;i++){
        int n = ty + i*8;
        Th[(size_t)(n0+n)*K + k0 + tx] = __float2half(s[tx][n]);
    }
}

// ========== warp-MMA fp16 GEMM: C = act(A @ W^T + bias), 2 CTAs/SM ==========
// modes: 0 fp32 C; 1 fp32+gelu C; 2 fp16 C; 3 fp16 VT[b][col][m]; 4 gelu + fp16 C
#define AH_OFF 0
#define BH_OFF 8192
#define BUF_SZ 16384
#define GEMM_SMEM (2*BUF_SZ + 512)

__device__ __forceinline__ uint32_t swz(int row, int g){
    return (uint32_t)(row*64 + ((g ^ ((row>>1)&3))<<4));
}

__global__ void __launch_bounds__(256,2) gemm_mma(
    const __half* __restrict__ A0, int lda0,
    const __half* __restrict__ A1, int lda1, int ks,
    const __half* __restrict__ Bm,
    const float* __restrict__ bias, float* __restrict__ C,
    __half* __restrict__ Ch, int ldc, int K, int mode)
{
    extern __shared__ __align__(128) char smem[];
    uint32_t sb = smem_u32(smem);
    float* bias_s = (float*)(smem + 2*BUF_SZ);

    int t = threadIdx.x, lane = t&31, wid = t>>5;
    int m0 = blockIdx.y*128, n0 = blockIdx.x*128;
    int mbase = (wid>>2)*64, nbase = (wid&3)*32;

    if (t < 128) bias_s[t] = bias[n0 + t];

    int nch = K >> 5;
    int ar_r  = t>>1;
    int ar_kh = (t&1)*16;
    int g0    = ar_kh>>3;

    auto stage = [&](int c, uint32_t sbuf){
        int kt = c*32;
        const __half* Ap; int lda, ko;
        if (kt < ks){ Ap = A0; lda = lda0; ko = kt; }
        else        { Ap = A1; lda = lda1; ko = kt - ks; }
        const __half* aH = Ap + (size_t)(m0+ar_r)*lda + ko + ar_kh;
        const __half* bH = Bm + (size_t)(n0+ar_r)*K + kt + ar_kh;
        CP_ASYNC16(sbuf + AH_OFF + swz(ar_r, g0),   aH);
        CP_ASYNC16(sbuf + AH_OFF + swz(ar_r, g0+1), aH+8);
        CP_ASYNC16(sbuf + BH_OFF + swz(ar_r, g0),   bH);
        CP_ASYNC16(sbuf + BH_OFF + swz(ar_r, g0+1), bH+8);
        CP_COMMIT();
    };

    float acc[4][4][4];
#pragma unroll
    for (int i=0;i<4;i++)
#pragma unroll
        for (int j=0;j<4;j++)
#pragma unroll
            for (int e=0;e<4;e++) acc[i][j][e]=0.f;

    stage(0, sb);

    for (int c=0; c<nch; c++){
        int b = c & 1;
        uint32_t sbuf = sb + b*BUF_SZ;
        if (c+1 < nch){ stage(c+1, sb + (b^1)*BUF_SZ); CP_WAIT1(); }
        else          { CP_WAIT0(); }
        __syncthreads();

        int lr = lane&15, lk = lane>>4;
#pragma unroll
        for (int ksI=0; ksI<2; ksI++){
            int gk = ksI*2;
            uint32_t aH[4][4];
#pragma unroll
            for (int mt=0;mt<4;mt++){
                int row = mbase + mt*16 + lr;
                ldsm_x4(aH[mt], sbuf + AH_OFF + swz(row, gk+lk));
            }
            uint32_t bHf[4][2];
#pragma unroll
            for (int j=0;j<2;j++){
                int n = nbase + j*16 + (lane>>4)*8 + (lane&7);
                int g = gk + ((lane>>3)&1);
                uint32_t tmp[4];
                ldsm_x4(tmp, sbuf + BH_OFF + swz(n, g));
                bHf[j*2][0]=tmp[0]; bHf[j*2][1]=tmp[1];
                bHf[j*2+1][0]=tmp[2]; bHf[j*2+1][1]=tmp[3];
            }
#pragma unroll
            for (int mt=0;mt<4;mt++)
#pragma unroll
                for (int nt=0;nt<4;nt++) mma16816(acc[mt][nt], aH[mt], bHf[nt]);
        }
        __syncthreads();
    }

    // ---- epilogue ----
    int actv = (mode==1 || mode==4);
#pragma unroll
    for (int mt=0;mt<4;mt++){
        int r0 = m0 + mbase + mt*16 + (lane>>2);
#pragma unroll
        for (int nt=0;nt<4;nt++){
            int cc = nbase + nt*8 + (lane&3)*2;
            float b0 = bias_s[cc], b1 = bias_s[cc+1];
            float v0 = acc[mt][nt][0] + b0;
            float v1 = acc[mt][nt][1] + b1;
            float v2 = acc[mt][nt][2] + b0;
            float v3 = acc[mt][nt][3] + b1;
            if (actv){ v0=gelu_exact(v0); v1=gelu_exact(v1); v2=gelu_exact(v2); v3=gelu_exact(v3); }
            if (mode <= 1){
                *(float2*)(C + (size_t)r0*ldc     + n0 + cc) = make_float2(v0,v1);
                *(float2*)(C + (size_t)(r0+8)*ldc + n0 + cc) = make_float2(v2,v3);
            } else {
                __half h0=__float2half(v0), h1=__float2half(v1);
                __half h2=__float2half(v2), h3=__float2half(v3);
                if (mode != 3){
                    *(__half2*)(Ch + (size_t)r0*ldc + n0+cc)     = __half2(h0,h1);
                    *(__half2*)(Ch + (size_t)(r0+8)*ldc + n0+cc) = __half2(h2,h3);
                } else { // VT[b][col][m]
                    int bb = r0>>9, m = r0&511, col = n0+cc;
                    Ch[((size_t)bb*Hh + col  )*Mm + m  ] = h0;
                    Ch[((size_t)bb*Hh + col+1)*Mm + m  ] = h1;
                    Ch[((size_t)bb*Hh + col  )*Mm + m+8] = h2;
                    Ch[((size_t)bb*Hh + col+1)*Mm + m+8] = h3;
                }
            }
        }
    }
}

// ================= MMA attention (fp16) =================
// Pf (fp16 P blocks) aliases the K staging buffers (free after QK^T of the head).
#define SA_LG   0          /* float [32][512]  65536 */
#define SA_MACC 65536      /* float [32][512]  65536 */
#define SA_MSK  131072     /* int [512]        2048  */
#define SA_Q    133120     /* 2 tiles [32][32] fp16 = 4096 */
#define SA_K    137216     /* 2 bufs x {2 tiles [128][32] fp16} = 2x16384 */
#define SA_P    SA_K       /* 16 blocks x [32][32] fp16 = 32768 (aliases K) */
#define SA_VT   169984     /* 2 bufs x {4 subtiles [64][32] fp16} = 2x16384 */
#define ATT_SMEM 202752

__global__ void __launch_bounds__(256,1) attn_mma(
    const __half* __restrict__ Qm, const __half* __restrict__ Km,
    const __half* __restrict__ VTm, const int* __restrict__ mask,
    __half* __restrict__ ATT, float* __restrict__ mem_attn)
{
    extern __shared__ __align__(128) char sm8[];
    uint32_t sb = smem_u32(sm8);
    float* lg   = (float*)(sm8 + SA_LG);
    float* macc = (float*)(sm8 + SA_MACC);
    int*   msk  = (int*)  (sm8 + SA_MSK);

    int b  = blockIdx.x >> 6;
    int s0 = (blockIdx.x & 63) * 32;
    int t  = threadIdx.x, lane = t&31, wid = t>>5;
    int q0 = (wid>>2)*16;
    int nbase = (wid&3)*32;
    int d0 = (wid&3)*16;
    int lr = lane&15, lk = lane>>4;

    for (int i=t;i<Mm;i+=256)     msk[i] = mask[b*Mm + i];
    for (int i=t;i<32*Mm;i+=256)  macc[i] = 0.f;

    auto loadK = [&](int head, int mc, int kb){
        uint32_t base = sb + SA_K + kb*16384;
#pragma unroll
        for (int i=0;i<4;i++){
            int j = t + i*256;          // 1024 jobs
            int tile = j>>9, rem = j&511;
            int row = rem>>2, g = rem&3;
            const __half* src = Km
                + (size_t)(b*Mm + mc*128 + row)*Hh + head*64 + tile*32 + g*8;
            CP_ASYNC16(base + tile*8192 + swz(row,g), src);
        }
        CP_COMMIT();
    };
    // load a [64 d][128 m] VT chunk as 4 subtiles of [64][32]
    auto loadVT4 = [&](int head, int mb, int vb){
        uint32_t base = sb + SA_VT + vb*16384;
#pragma unroll
        for (int i=0;i<4;i++){
            int j = t + i*256;          // 1024 jobs
            int sub = j>>8, rem = j&255;
            int row = rem>>2, g = rem&3;
            const __half* src = VTm
                + ((size_t)b*Hh + head*64 + row)*Mm + mb*128 + sub*32 + g*8;
            CP_ASYNC16(base + sub*4096 + swz(row,g), src);
        }
        CP_COMMIT();
    };

    for (int head=0; head<NHn; head++){
        __syncthreads();
        // Q tiles
        {
            int tile = t>>7, rem = t&127;
            int row = rem>>2, g = rem&3;
            const __half* src = Qm
                + (size_t)(b*Ss + s0 + row)*Hh + head*64 + tile*32 + g*8;
            CP_ASYNC16(sb + SA_Q + tile*2048 + swz(row,g), src);
        }
        CP_COMMIT();
        loadK(head, 0, 0);
        int kb = 0;
        // ---- QK^T ----
        for (int mc=0; mc<4; mc++){
            if (mc < 3){ loadK(head, mc+1, kb^1); CP_WAIT1(); } else { CP_WAIT0(); }
            __syncthreads();
            float acc[4][4];
#pragma unroll
            for (int i=0;i<4;i++)
#pragma unroll
                for (int e=0;e<4;e++) acc[i][e]=0.f;
            uint32_t kbase = sb + SA_K + kb*16384;
#pragma unroll
            for (int dc=0; dc<2; dc++){
                uint32_t Qhb = sb + SA_Q + dc*2048;
                uint32_t Khb = kbase + dc*8192;
#pragma unroll
                for (int ksI=0; ksI<2; ksI++){
                    int gk = ksI*2;
                    uint32_t aH[4];
                    ldsm_x4(aH, Qhb + swz(q0+lr, gk+lk));
                    uint32_t bHf[4][2];
#pragma unroll
                    for (int j=0;j<2;j++){
                        int n = nbase + j*16 + (lane>>4)*8 + (lane&7);
                        int g = gk + ((lane>>3)&1);
                        uint32_t tmp[4];
                        ldsm_x4(tmp, Khb + swz(n, g));
                        bHf[j*2][0]=tmp[0]; bHf[j*2][1]=tmp[1];
                        bHf[j*2+1][0]=tmp[2]; bHf[j*2+1][1]=tmp[3];
                    }
#pragma unroll
                    for (int nt=0;nt<4;nt++) mma16816(acc[nt], aH, bHf[nt]);
                }
            }
            {
                int row = q0 + (lane>>2);
#pragma unroll
                for (int nt=0;nt<4;nt++){
                    int col = mc*128 + nbase + nt*8 + (lane&3)*2;
                    lg[row*Mm + col]       = acc[nt][0]*0.125f;
                    lg[row*Mm + col+1]     = acc[nt][1]*0.125f;
                    lg[(row+8)*Mm + col]   = acc[nt][2]*0.125f;
                    lg[(row+8)*Mm + col+1] = acc[nt][3]*0.125f;
                }
            }
            kb ^= 1;
            __syncthreads();
        }
        // ---- masked softmax + head-mean ----
        {
            for (int q=wid; q<32; q+=8){
                float* row = &lg[q*Mm];
                float mx = -1e30f;
                for (int m=lane;m<Mm;m+=32) if (msk[m]!=0) mx = fmaxf(mx, row[m]);
#pragma unroll
                for (int o=16;o;o>>=1) mx = fmaxf(mx, __shfl_xor_sync(0xffffffffu,mx,o));
                float ssum = 0.f;
                for (int m=lane;m<Mm;m+=32){
                    float wv = (msk[m]!=0) ? expf(row[m]-mx) : 0.f;
                    row[m]=wv; ssum += wv;
                }
#pragma unroll
                for (int o=16;o;o>>=1) ssum += __shfl_xor_sync(0xffffffffu,ssum,o);
                float inv = 1.0f/ssum;
                for (int m=lane;m<Mm;m+=32){
                    float wv = row[m]*inv;
                    row[m]=wv;
                    macc[q*Mm+m] += wv;
                }
            }
        }
        __syncthreads();
        // ---- convert full P [32][512] -> fp16 blocks (aliases K bufs) ----
#pragma unroll
        for (int i=0;i<8;i++){
            int j = t + i*256;          // 2048 jobs: 32 rows x 64 groups-of-8
            int row = j>>6, gg8 = j&63;
            int blk = gg8>>2, g = gg8&3;
            const float* pl = &lg[row*Mm + gg8*8];
            float4 x0 = *(const float4*)pl, x1 = *(const float4*)(pl+4);
            *(uint4*)(sm8 + SA_P + blk*2048 + swz(row,g)) = cvt8(x0, x1);
        }
        loadVT4(head, 0, 0);
        __syncthreads();    // P visible to all warps
        // ---- P @ V: 4 chunks of 128 m ----
        float acc2[2][4];
#pragma unroll
        for (int i=0;i<2;i++)
#pragma unroll
            for (int e=0;e<4;e++) acc2[i][e]=0.f;
        int vb = 0;
        for (int mb=0; mb<4; mb++){
            if (mb < 3){ loadVT4(head, mb+1, vb^1); CP_WAIT1(); } else { CP_WAIT0(); }
            __syncthreads();
            uint32_t vbase = sb + SA_VT + vb*16384;
#pragma unroll
            for (int sub=0; sub<4; sub++){
                uint32_t Pb  = sb + SA_P + (mb*4+sub)*2048;
                uint32_t Vb2 = vbase + sub*4096;
#pragma unroll
                for (int ksI=0; ksI<2; ksI++){
                    int gk = ksI*2;
                    uint32_t aH[4];
                    ldsm_x4(aH, Pb + swz(q0+lr, gk+lk));
                    uint32_t bHf[2][2];
                    {
                        int n = d0 + (lane>>4)*8 + (lane&7);
                        int g = gk + ((lane>>3)&1);
                        uint32_t tmp[4];
                        ldsm_x4(tmp, Vb2 + swz(n, g));
                        bHf[0][0]=tmp[0]; bHf[0][1]=tmp[1];
                        bHf[1][0]=tmp[2]; bHf[1][1]=tmp[3];
                    }
#pragma unroll
                    for (int nt=0;nt<2;nt++) mma16816(acc2[nt], aH, bHf[nt]);
                }
            }
            vb ^= 1;
            __syncthreads();
        }
        // write attended (fp16)
        {
            int row = q0 + (lane>>2);
#pragma unroll
            for (int nt=0;nt<2;nt++){
                int col = d0 + nt*8 + (lane&3)*2;
                size_t o0 = (size_t)(b*Ss + s0 + row)*Hh + head*64 + col;
                size_t o1 = (size_t)(b*Ss + s0 + row + 8)*Hh + head*64 + col;
                *(__half2*)(ATT + o0) = __half2(__float2half(acc2[nt][0]), __float2half(acc2[nt][1]));
                *(__half2*)(ATT + o1) = __half2(__float2half(acc2[nt][2]), __float2half(acc2[nt][3]));
            }
        }
    }
    __syncthreads();
    for (int i=t;i<32*Mm;i+=256){
        int q = i>>9, m = i&511;
        mem_attn[((size_t)(b*Ss + s0 + q))*Mm + m] = macc[i]*(1.0f/16.0f);
    }
}

// ================= gate GEMV =================
__global__ void gate_kernel(const float* __restrict__ gg, const float* __restrict__ Wg2,
                            const float* __restrict__ bg2, float* __restrict__ gate)
{
    int r = blockIdx.x*8 + (threadIdx.x>>5);
    int lane = threadIdx.x & 31;
    const float* row = gg + (size_t)r*Hh;
    float s = 0.f;
    for (int i=lane;i<Hh;i+=32) s = fmaf(row[i], Wg2[i], s);
#pragma unroll
    for (int o=16;o;o>>=1) s += __shfl_xor_sync(0xffffffffu,s,o);
    if (lane==0) gate[r] = 1.0f/(1.0f + expf(-(s + bg2[0])));
}

// ================= layernorm + gated residual =================
__global__ void ln_combine_kernel(
    const float* __restrict__ t2, const float* __restrict__ lng, const float* __restrict__ lnb,
    const float* __restrict__ gate, const float* __restrict__ hidden, float* __restrict__ out)
{
    __shared__ float red[8];
    int r = blockIdx.x;
    int t = threadIdx.x;
    const float* row = t2 + (size_t)r*Hh;
    float x[4];
#pragma unroll
    for (int j=0;j<4;j++) x[j] = row[t + 256*j];
    float s = x[0]+x[1]+x[2]+x[3];
#pragma unroll
    for (int o=16;o;o>>=1) s += __shfl_xor_sync(0xffffffffu,s,o);
    if ((t&31)==0) red[t>>5] = s;
    __syncthreads();
    float mu = (red[0]+red[1]+red[2]+red[3]+red[4]+red[5]+red[6]+red[7]) * (1.0f/Hh);
    __syncthreads();
    float s2 = 0.f;
#pragma unroll
    for (int j=0;j<4;j++){ float d = x[j]-mu; s2 = fmaf(d,d,s2); }
#pragma unroll
    for (int o=16;o;o>>=1) s2 += __shfl_xor_sync(0xffffffffu,s2,o);
    if ((t&31)==0) red[t>>5] = s2;
    __syncthreads();
    float var = (red[0]+red[1]+red[2]+red[3]+red[4]+red[5]+red[6]+red[7]) * (1.0f/Hh);
    float rs = rsqrtf(var + 1e-5f);
    float gt = gate[r];
    const float* hrow = hidden + (size_t)r*Hh;
#pragma unroll
    for (int j=0;j<4;j++){
        int idx = t + 256*j;
        float f = (x[j]-mu)*rs*lng[idx] + lnb[idx];
        out[(size_t)r*Hh + idx] = gt*f + (1.0f-gt)*hrow[idx];
    }
}

// ================= launch =================
extern "C" void kernel_launch(void* const* d_in, const int* in_sizes, int n_in,
                              void* d_out, int out_size)
{
    (void)in_sizes; (void)n_in; (void)out_size;
    const float* hidden = (const float*)d_in[0];
    const float* memory = (const float*)d_in[1];
    const int*   mask   = (const int*)  d_in[2];
    /* d_in[3] surprise_score: exact algebraic no-op */
    const float* Wq  = (const float*)d_in[4];
    const float* bq  = (const float*)d_in[5];
    const float* Wk  = (const float*)d_in[6];
    const float* bk  = (const float*)d_in[7];
    const float* Wv  = (const float*)d_in[8];
    const float* bv  = (const float*)d_in[9];
    const float* W1  = (const float*)d_in[10];
    const float* b1  = (const float*)d_in[11];
    const float* W2  = (const float*)d_in[12];
    const float* b2  = (const float*)d_in[13];
    const float* lng = (const float*)d_in[14];
    const float* lnb = (const float*)d_in[15];
    const float* Wg1 = (const float*)d_in[16];
    const float* bg1 = (const float*)d_in[17];
    const float* Wg2 = (const float*)d_in[18];
    const float* bg2 = (const float*)d_in[19];

    float *pT2,*pGG,*pGate;
    cudaGetSymbolAddress((void**)&pT2,  g_t2);
    cudaGetSymbolAddress((void**)&pGG,  g_gg);
    cudaGetSymbolAddress((void**)&pGate,g_gate);

    __half *pHs,*pMs,*pQ,*pK,*pVT,*pATT,*pH1;
    cudaGetSymbolAddress((void**)&pHs,  g_Hs);
    cudaGetSymbolAddress((void**)&pMs,  g_Ms);
    cudaGetSymbolAddress((void**)&pQ,   g_Q);
    cudaGetSymbolAddress((void**)&pK,   g_K);
    cudaGetSymbolAddress((void**)&pVT,  g_VT);
    cudaGetSymbolAddress((void**)&pATT, g_ATT);
    cudaGetSymbolAddress((void**)&pH1,  g_H1);

    __half *wq,*wk,*wv,*w1,*w2,*wg1;
    cudaGetSymbolAddress((void**)&wq,  g_WqT);
    cudaGetSymbolAddress((void**)&wk,  g_WkT);
    cudaGetSymbolAddress((void**)&wv,  g_WvT);
    cudaGetSymbolAddress((void**)&w1,  g_W1T);
    cudaGetSymbolAddress((void**)&w2,  g_W2T);
    cudaGetSymbolAddress((void**)&wg1, g_Wg1T);

    float* out      = (float*)d_out;
    float* mem_attn = out + (size_t)ROWS*Hh;

    cudaFuncSetAttribute(gemm_mma, cudaFuncAttributeMaxDynamicSharedMemorySize, GEMM_SMEM);
    cudaFuncSetAttribute(attn_mma, cudaFuncAttributeMaxDynamicSharedMemorySize, ATT_SMEM);

    dim3 tb(32,8);
    // converts
    aconv<<<ROWS*Hh/2048, 256>>>((const float4*)hidden, pHs);
    aconv<<<KVROWS*HQq/2048, 256>>>((const float4*)memory, pMs);
    wconvT<<<dim3(32,32), tb>>>(Wq,  wq,  1024, 1024);
    wconvT<<<dim3(32, 8), tb>>>(Wk,  wk,   256, 1024);
    wconvT<<<dim3(32, 8), tb>>>(Wv,  wv,   256, 1024);
    wconvT<<<dim3(32,64), tb>>>(W1,  w1,  2048, 1024);
    wconvT<<<dim3(32,32), tb>>>(W2,  w2,  1024, 1024);
    wconvT<<<dim3(32,64), tb>>>(Wg1, wg1, 2048, 1024);

    const int BIG = 1<<30;
    // projections
    gemm_mma<<<dim3(8,64), 256, GEMM_SMEM>>>(pHs, Hh, (const __half*)0, 0, BIG,
        wq, bq, (float*)0, pQ, Hh, Hh, 2);
    gemm_mma<<<dim3(8,16), 256, GEMM_SMEM>>>(pMs, HQq, (const __half*)0, 0, BIG,
        wk, bk, (float*)0, pK, Hh, HQq, 2);
    gemm_mma<<<dim3(8,16), 256, GEMM_SMEM>>>(pMs, HQq, (const __half*)0, 0, BIG,
        wv, bv, (float*)0, pVT, Hh, HQq, 3);

    // MMA attention -> fp16 attended + mem_attn
    attn_mma<<<Bb*64, 256, ATT_SMEM>>>(pQ, pK, pVT, mask, pATT, mem_attn);

    // MLP: A = concat(hidden, att), pre-converted fp16
    gemm_mma<<<dim3(8,64), 256, GEMM_SMEM>>>(pHs, Hh, pATT, Hh, Hh,
        w1, b1, (float*)0, pH1, Hh, 2*Hh, 4);
    gemm_mma<<<dim3(8,64), 256, GEMM_SMEM>>>(pHs, Hh, pATT, Hh, Hh,
        wg1, bg1, pGG, (__half*)0, Hh, 2*Hh, 1);
    gemm_mma<<<dim3(8,64), 256, GEMM_SMEM>>>(pH1, Hh, (const __half*)0, 0, BIG,
        w2, b2, pT2, (__half*)0, Hh, Hh, 0);

    // gate + final layernorm/mix
    gate_kernel<<<1024, 256>>>(pGG, Wg2, bg2, pGate);
    ln_combine_kernel<<<ROWS, 256>>>(pT2, lng, lnb, pGate, hidden, out);
}

// round 13
// speedup vs baseline: 6.2295x; 1.0977x over previous
#include <cuda_runtime.h>
#include <cuda_fp16.h>
#include <math.h>
#include <stdint.h>

#define Bb   4
#define Ss   2048
#define Hh   1024
#define Mm   512
#define NHn  16
#define HDd  64
#define HQq  256
#define ROWS   (Bb*Ss)    /* 8192 */
#define KVROWS (Bb*Mm)    /* 2048 */
#define BIGK   (1<<30)

// ================= helpers =================
__device__ __forceinline__ uint32_t smem_u32(const void* p){
    uint32_t a;
    asm("{ .reg .u64 t; cvta.to.shared.u64 t, %1; cvt.u32.u64 %0, t; }" : "=r"(a) : "l"(p));
    return a;
}
#define CP_ASYNC16(dst, src) \
    asm volatile("cp.async.cg.shared.global [%0], [%1], 16;" :: "r"(dst), "l"(src))
#define CP_COMMIT() asm volatile("cp.async.commit_group;" ::: "memory")
#define CP_WAIT0()  asm volatile("cp.async.wait_group 0;" ::: "memory")
#define CP_WAIT1()  asm volatile("cp.async.wait_group 1;" ::: "memory")
#define CP_WAIT2()  asm volatile("cp.async.wait_group 2;" ::: "memory")

__device__ __forceinline__ void ldsm_x4(uint32_t* r, uint32_t addr){
    asm volatile("ldmatrix.sync.aligned.m8n8.x4.shared.b16 {%0,%1,%2,%3}, [%4];"
        : "=r"(r[0]),"=r"(r[1]),"=r"(r[2]),"=r"(r[3]) : "r"(addr));
}
__device__ __forceinline__ void mma16816(float* d, const uint32_t* a, const uint32_t* b){
    asm volatile("mma.sync.aligned.m16n8k16.row.col.f32.f16.f16.f32 "
        "{%0,%1,%2,%3}, {%4,%5,%6,%7}, {%8,%9}, {%0,%1,%2,%3};"
        : "+f"(d[0]),"+f"(d[1]),"+f"(d[2]),"+f"(d[3])
        : "r"(a[0]),"r"(a[1]),"r"(a[2]),"r"(a[3]), "r"(b[0]),"r"(b[1]));
}

__device__ __forceinline__ float gelu_exact(float x){
    return 0.5f*x*(1.0f + erff(x*0.70710678118654752f));
}

__device__ __forceinline__ uint4 cvt8(float4 x0, float4 x1){
    float f[8] = {x0.x,x0.y,x0.z,x0.w,x1.x,x1.y,x1.z,x1.w};
    uint32_t h[8];
#pragma unroll
    for (int j=0;j<8;j++) h[j] = (uint32_t)__half_as_ushort(__float2half(f[j]));
    return make_uint4(h[0]|(h[1]<<16), h[2]|(h[3]<<16), h[4]|(h[5]<<16), h[6]|(h[7]<<16));
}

// ================= scratch (device globals) =================
__device__ float g_t2 [ROWS*Hh];
__device__ float g_gg [ROWS*Hh];
__device__ __half g_Hs [ROWS*Hh];
__device__ __half g_Ms [KVROWS*HQq];
__device__ __half g_Q  [ROWS*Hh];
__device__ __half g_K  [KVROWS*Hh];
__device__ __half g_VT [Bb*Hh*Mm];
__device__ __half g_ATT[ROWS*Hh];
__device__ __half g_H1 [ROWS*Hh];
__device__ __half g_WqT [1024*1024];
__device__ __half g_WkT [1024*256];
__device__ __half g_WvT [1024*256];
__device__ __half g_W1T [1024*2048];
__device__ __half g_W2T [1024*1024];
__device__ __half g_Wg1T[1024*2048];

// ========== merged activation converts ==========
__global__ void aconv2(const float4* __restrict__ H, __half* __restrict__ Ho,
                       const float4* __restrict__ Mi, __half* __restrict__ Mo)
{
    int bid = blockIdx.x;                   // 0..4095 hidden, 4096..4351 memory
    const float4* X; __half* Xh; size_t i;
    if (bid < 4096){ X = H;  Xh = Ho; i = (size_t)bid*256 + threadIdx.x; }
    else           { X = Mi; Xh = Mo; i = (size_t)(bid-4096)*256 + threadIdx.x; }
    *(uint4*)(Xh + 8*i) = cvt8(X[2*i], X[2*i+1]);
}

// ========== merged weight transpose: 6 weights, one launch ==========
__global__ void wconvT6(
    const float* __restrict__ Wq,  __half* __restrict__ Tq,
    const float* __restrict__ Wk,  __half* __restrict__ Tk,
    const float* __restrict__ Wv,  __half* __restrict__ Tv,
    const float* __restrict__ W1,  __half* __restrict__ T1,
    const float* __restrict__ W2,  __half* __restrict__ T2,
    const float* __restrict__ Wg1, __half* __restrict__ Tg1)
{
    __shared__ float s[32][33];
    int bid = blockIdx.x;
    const float* W; __half* Th; int K, N, local;
    if      (bid < 1024){ W=Wq;  Th=Tq;  K=1024; N=1024; local=bid; }
    else if (bid < 1280){ W=Wk;  Th=Tk;  K=256;  N=1024; local=bid-1024; }
    else if (bid < 1536){ W=Wv;  Th=Tv;  K=256;  N=1024; local=bid-1280; }
    else if (bid < 3584){ W=W1;  Th=T1;  K=2048; N=1024; local=bid-1536; }
    else if (bid < 4608){ W=W2;  Th=T2;  K=1024; N=1024; local=bid-3584; }
    else               { W=Wg1; Th=Tg1; K=2048; N=1024; local=bid-4608; }
    int nb = N>>5;
    int n0 = (local % nb)*32, k0 = (local / nb)*32;
    int tx = threadIdx.x, ty = threadIdx.y; // 32x8
#pragma unroll
    for (int i=0;i<4;i++)
        s[ty+i*8][tx] = W[(size_t)(k0+ty+i*8)*N + n0+tx];
    __syncthreads();
#pragma unroll
    for (int i=0;i<4;i++){
        int n = ty + i*8;
        Th[(size_t)(n0+n)*K + k0 + tx] = __float2half(s[tx][n]);
    }
}

// ========== warp-MMA fp16 GEMM body (3-stage pipeline, 2 CTAs/SM) ==========
// modes: 0 fp32 C; 1 fp32+gelu C; 2 fp16 C; 3 fp16 VT[b][col][m]; 4 gelu + fp16 C
#define AH_OFF 0
#define BH_OFF 8192
#define BUF_SZ 16384
#define GEMM_SMEM (3*BUF_SZ + 512)

__device__ __forceinline__ uint32_t swz(int row, int g){
    return (uint32_t)(row*64 + ((g ^ ((row>>1)&3))<<4));
}

__device__ __forceinline__ void gemm_body(
    int bm, int bn,
    const __half* __restrict__ A0, int lda0,
    const __half* __restrict__ A1, int lda1, int ks,
    const __half* __restrict__ Bm,
    const float* __restrict__ bias, float* __restrict__ C,
    __half* __restrict__ Ch, int ldc, int K, int mode, char* smem)
{
    uint32_t sb = smem_u32(smem);
    float* bias_s = (float*)(smem + 3*BUF_SZ);

    int t = threadIdx.x, lane = t&31, wid = t>>5;
    int m0 = bm*128, n0 = bn*128;
    int mbase = (wid>>2)*64, nbase = (wid&3)*32;

    if (t < 128) bias_s[t] = bias[n0 + t];

    int nch = K >> 5;
    int ar_r  = t>>1;
    int ar_kh = (t&1)*16;
    int g0    = ar_kh>>3;

    auto stage = [&](int c, uint32_t sbuf){
        int kt = c*32;
        const __half* Ap; int lda, ko;
        if (kt < ks){ Ap = A0; lda = lda0; ko = kt; }
        else        { Ap = A1; lda = lda1; ko = kt - ks; }
        const __half* aH = Ap + (size_t)(m0+ar_r)*lda + ko + ar_kh;
        const __half* bH = Bm + (size_t)(n0+ar_r)*K + kt + ar_kh;
        CP_ASYNC16(sbuf + AH_OFF + swz(ar_r, g0),   aH);
        CP_ASYNC16(sbuf + AH_OFF + swz(ar_r, g0+1), aH+8);
        CP_ASYNC16(sbuf + BH_OFF + swz(ar_r, g0),   bH);
        CP_ASYNC16(sbuf + BH_OFF + swz(ar_r, g0+1), bH+8);
        CP_COMMIT();
    };

    float acc[4][4][4];
#pragma unroll
    for (int i=0;i<4;i++)
#pragma unroll
        for (int j=0;j<4;j++)
#pragma unroll
            for (int e=0;e<4;e++) acc[i][j][e]=0.f;

    stage(0, sb);
    if (nch > 1) stage(1, sb + BUF_SZ);

    int bsel = 0;
    for (int c=0; c<nch; c++){
        uint32_t sbuf = sb + bsel*BUF_SZ;
        if (c+2 < nch){
            int nb = bsel+2; if (nb>=3) nb-=3;
            stage(c+2, sb + nb*BUF_SZ);
            CP_WAIT2();
        } else if (c+1 < nch){
            CP_WAIT1();
        } else {
            CP_WAIT0();
        }
        __syncthreads();

        int lr = lane&15, lk = lane>>4;
#pragma unroll
        for (int ksI=0; ksI<2; ksI++){
            int gk = ksI*2;
            uint32_t aH[4][4];
#pragma unroll
            for (int mt=0;mt<4;mt++){
                int row = mbase + mt*16 + lr;
                ldsm_x4(aH[mt], sbuf + AH_OFF + swz(row, gk+lk));
            }
            uint32_t bHf[4][2];
#pragma unroll
            for (int j=0;j<2;j++){
                int n = nbase + j*16 + (lane>>4)*8 + (lane&7);
                int g = gk + ((lane>>3)&1);
                uint32_t tmp[4];
                ldsm_x4(tmp, sbuf + BH_OFF + swz(n, g));
                bHf[j*2][0]=tmp[0]; bHf[j*2][1]=tmp[1];
                bHf[j*2+1][0]=tmp[2]; bHf[j*2+1][1]=tmp[3];
            }
#pragma unroll
            for (int mt=0;mt<4;mt++)
#pragma unroll
                for (int nt=0;nt<4;nt++) mma16816(acc[mt][nt], aH[mt], bHf[nt]);
        }
        __syncthreads();
        bsel++; if (bsel>=3) bsel=0;
    }

    // ---- epilogue ----
    int actv = (mode==1 || mode==4);
#pragma unroll
    for (int mt=0;mt<4;mt++){
        int r0 = m0 + mbase + mt*16 + (lane>>2);
#pragma unroll
        for (int nt=0;nt<4;nt++){
            int cc = nbase + nt*8 + (lane&3)*2;
            float b0 = bias_s[cc], b1 = bias_s[cc+1];
            float v0 = acc[mt][nt][0] + b0;
            float v1 = acc[mt][nt][1] + b1;
            float v2 = acc[mt][nt][2] + b0;
            float v3 = acc[mt][nt][3] + b1;
            if (actv){ v0=gelu_exact(v0); v1=gelu_exact(v1); v2=gelu_exact(v2); v3=gelu_exact(v3); }
            if (mode <= 1){
                *(float2*)(C + (size_t)r0*ldc     + n0 + cc) = make_float2(v0,v1);
                *(float2*)(C + (size_t)(r0+8)*ldc + n0 + cc) = make_float2(v2,v3);
            } else {
                __half h0=__float2half(v0), h1=__float2half(v1);
                __half h2=__float2half(v2), h3=__float2half(v3);
                if (mode != 3){
                    *(__half2*)(Ch + (size_t)r0*ldc + n0+cc)     = __half2(h0,h1);
                    *(__half2*)(Ch + (size_t)(r0+8)*ldc + n0+cc) = __half2(h2,h3);
                } else { // VT[b][col][m]
                    int bb = r0>>9, m = r0&511, col = n0+cc;
                    Ch[((size_t)bb*Hh + col  )*Mm + m  ] = h0;
                    Ch[((size_t)bb*Hh + col+1)*Mm + m  ] = h1;
                    Ch[((size_t)bb*Hh + col  )*Mm + m+8] = h2;
                    Ch[((size_t)bb*Hh + col+1)*Mm + m+8] = h3;
                }
            }
        }
    }
}

// ---- merged QKV projection: 768 CTAs (512 Q, 128 K, 128 V) ----
__global__ void __launch_bounds__(256,2) gemm_qkv(
    const __half* __restrict__ Hs, const __half* __restrict__ Ms,
    const __half* __restrict__ wq, const __half* __restrict__ wk, const __half* __restrict__ wv,
    const float* __restrict__ bq, const float* __restrict__ bk, const float* __restrict__ bv,
    __half* __restrict__ pQ, __half* __restrict__ pK, __half* __restrict__ pVT)
{
    extern __shared__ __align__(128) char smem[];
    int bid = blockIdx.x;
    const __half *A, *B; const float* bias; __half* Ch;
    int lda, K, mode, bm, bn;
    if (bid < 512){      A=Hs; lda=Hh;  B=wq; bias=bq; Ch=pQ;  K=Hh;  mode=2; bn=bid&7;        bm=bid>>3; }
    else if (bid < 640){ A=Ms; lda=HQq; B=wk; bias=bk; Ch=pK;  K=HQq; mode=2; bn=(bid-512)&7;  bm=(bid-512)>>3; }
    else {               A=Ms; lda=HQq; B=wv; bias=bv; Ch=pVT; K=HQq; mode=3; bn=(bid-640)&7;  bm=(bid-640)>>3; }
    gemm_body(bm, bn, A, lda, (const __half*)0, 0, BIGK, B, bias, (float*)0, Ch, Hh, K, mode, smem);
}

// ---- merged W1 + Wg1: 1024 CTAs ----
__global__ void __launch_bounds__(256,2) gemm_w1g1(
    const __half* __restrict__ Hs, const __half* __restrict__ ATT,
    const __half* __restrict__ w1, const __half* __restrict__ wg1,
    const float* __restrict__ b1, const float* __restrict__ bg1,
    __half* __restrict__ pH1, float* __restrict__ pGG)
{
    extern __shared__ __align__(128) char smem[];
    int bid = blockIdx.x;
    const __half* B; const float* bias; __half* Ch; float* C; int mode, bm, bn;
    if (bid < 512){ B=w1;  bias=b1;  Ch=pH1; C=(float*)0; mode=4; bn=bid&7;       bm=bid>>3; }
    else          { B=wg1; bias=bg1; Ch=(__half*)0; C=pGG; mode=1; bn=(bid-512)&7; bm=(bid-512)>>3; }
    gemm_body(bm, bn, Hs, Hh, ATT, Hh, Hh, B, bias, C, Ch, Hh, 2*Hh, mode, smem);
}

// ---- single GEMM (W2) ----
__global__ void __launch_bounds__(256,2) gemm_one(
    const __half* __restrict__ A0, int lda0,
    const __half* __restrict__ Bm, const float* __restrict__ bias,
    float* __restrict__ C, __half* __restrict__ Ch, int ldc, int K, int mode)
{
    extern __shared__ __align__(128) char smem[];
    gemm_body(blockIdx.y, blockIdx.x, A0, lda0, (const __half*)0, 0, BIGK,
              Bm, bias, C, Ch, ldc, K, mode, smem);
}

// ================= MMA attention (fp16) =================
#define SA_LG   0
#define SA_MACC 65536
#define SA_MSK  131072
#define SA_Q    133120
#define SA_K    137216
#define SA_P    SA_K
#define SA_VT   169984
#define ATT_SMEM 202752

__global__ void __launch_bounds__(256,1) attn_mma(
    const __half* __restrict__ Qm, const __half* __restrict__ Km,
    const __half* __restrict__ VTm, const int* __restrict__ mask,
    __half* __restrict__ ATT, float* __restrict__ mem_attn)
{
    extern __shared__ __align__(128) char sm8[];
    uint32_t sb = smem_u32(sm8);
    float* lg   = (float*)(sm8 + SA_LG);
    float* macc = (float*)(sm8 + SA_MACC);
    int*   msk  = (int*)  (sm8 + SA_MSK);

    int b  = blockIdx.x >> 6;
    int s0 = (blockIdx.x & 63) * 32;
    int t  = threadIdx.x, lane = t&31, wid = t>>5;
    int q0 = (wid>>2)*16;
    int nbase = (wid&3)*32;
    int d0 = (wid&3)*16;
    int lr = lane&15, lk = lane>>4;

    for (int i=t;i<Mm;i+=256)     msk[i] = mask[b*Mm + i];
    for (int i=t;i<32*Mm;i+=256)  macc[i] = 0.f;

    auto loadK = [&](int head, int mc, int kb){
        uint32_t base = sb + SA_K + kb*16384;
#pragma unroll
        for (int i=0;i<4;i++){
            int j = t + i*256;
            int tile = j>>9, rem = j&511;
            int row = rem>>2, g = rem&3;
            const __half* src = Km
                + (size_t)(b*Mm + mc*128 + row)*Hh + head*64 + tile*32 + g*8;
            CP_ASYNC16(base + tile*8192 + swz(row,g), src);
        }
        CP_COMMIT();
    };
    auto loadVT4 = [&](int head, int mb, int vb){
        uint32_t base = sb + SA_VT + vb*16384;
#pragma unroll
        for (int i=0;i<4;i++){
            int j = t + i*256;
            int sub = j>>8, rem = j&255;
            int row = rem>>2, g = rem&3;
            const __half* src = VTm
                + ((size_t)b*Hh + head*64 + row)*Mm + mb*128 + sub*32 + g*8;
            CP_ASYNC16(base + sub*4096 + swz(row,g), src);
        }
        CP_COMMIT();
    };

    for (int head=0; head<NHn; head++){
        __syncthreads();
        {
            int tile = t>>7, rem = t&127;
            int row = rem>>2, g = rem&3;
            const __half* src = Qm
                + (size_t)(b*Ss + s0 + row)*Hh + head*64 + tile*32 + g*8;
            CP_ASYNC16(sb + SA_Q + tile*2048 + swz(row,g), src);
        }
        CP_COMMIT();
        loadK(head, 0, 0);
        int kb = 0;
        for (int mc=0; mc<4; mc++){
            if (mc < 3){ loadK(head, mc+1, kb^1); CP_WAIT1(); } else { CP_WAIT0(); }
            __syncthreads();
            float acc[4][4];
#pragma unroll
            for (int i=0;i<4;i++)
#pragma unroll
                for (int e=0;e<4;e++) acc[i][e]=0.f;
            uint32_t kbase = sb + SA_K + kb*16384;
#pragma unroll
            for (int dc=0; dc<2; dc++){
                uint32_t Qhb = sb + SA_Q + dc*2048;
                uint32_t Khb = kbase + dc*8192;
#pragma unroll
                for (int ksI=0; ksI<2; ksI++){
                    int gk = ksI*2;
                    uint32_t aH[4];
                    ldsm_x4(aH, Qhb + swz(q0+lr, gk+lk));
                    uint32_t bHf[4][2];
#pragma unroll
                    for (int j=0;j<2;j++){
                        int n = nbase + j*16 + (lane>>4)*8 + (lane&7);
                        int g = gk + ((lane>>3)&1);
                        uint32_t tmp[4];
                        ldsm_x4(tmp, Khb + swz(n, g));
                        bHf[j*2][0]=tmp[0]; bHf[j*2][1]=tmp[1];
                        bHf[j*2+1][0]=tmp[2]; bHf[j*2+1][1]=tmp[3];
                    }
#pragma unroll
                    for (int nt=0;nt<4;nt++) mma16816(acc[nt], aH, bHf[nt]);
                }
            }
            {
                int row = q0 + (lane>>2);
#pragma unroll
                for (int nt=0;nt<4;nt++){
                    int col = mc*128 + nbase + nt*8 + (lane&3)*2;
                    lg[row*Mm + col]       = acc[nt][0]*0.125f;
                    lg[row*Mm + col+1]     = acc[nt][1]*0.125f;
                    lg[(row+8)*Mm + col]   = acc[nt][2]*0.125f;
                    lg[(row+8)*Mm + col+1] = acc[nt][3]*0.125f;
                }
            }
            kb ^= 1;
            __syncthreads();
        }
        // ---- masked softmax + head-mean ----
        {
            for (int q=wid; q<32; q+=8){
                float* row = &lg[q*Mm];
                float mx = -1e30f;
                for (int m=lane;m<Mm;m+=32) if (msk[m]!=0) mx = fmaxf(mx, row[m]);
#pragma unroll
                for (int o=16;o;o>>=1) mx = fmaxf(mx, __shfl_xor_sync(0xffffffffu,mx,o));
                float ssum = 0.f;
                for (int m=lane;m<Mm;m+=32){
                    float wv = (msk[m]!=0) ? expf(row[m]-mx) : 0.f;
                    row[m]=wv; ssum += wv;
                }
#pragma unroll
                for (int o=16;o;o>>=1) ssum += __shfl_xor_sync(0xffffffffu,ssum,o);
                float inv = 1.0f/ssum;
                for (int m=lane;m<Mm;m+=32){
                    float wv = row[m]*inv;
                    row[m]=wv;
                    macc[q*Mm+m] += wv;
                }
            }
        }
        __syncthreads();
        // ---- convert P [32][512] -> fp16 blocks (aliases K bufs) ----
#pragma unroll
        for (int i=0;i<8;i++){
            int j = t + i*256;
            int row = j>>6, gg8 = j&63;
            int blk = gg8>>2, g = gg8&3;
            const float* pl = &lg[row*Mm + gg8*8];
            float4 x0 = *(const float4*)pl, x1 = *(const float4*)(pl+4);
            *(uint4*)(sm8 + SA_P + blk*2048 + swz(row,g)) = cvt8(x0, x1);
        }
        loadVT4(head, 0, 0);
        __syncthreads();
        // ---- P @ V ----
        float acc2[2][4];
#pragma unroll
        for (int i=0;i<2;i++)
#pragma unroll
            for (int e=0;e<4;e++) acc2[i][e]=0.f;
        int vb = 0;
        for (int mb=0; mb<4; mb++){
            if (mb < 3){ loadVT4(head, mb+1, vb^1); CP_WAIT1(); } else { CP_WAIT0(); }
            __syncthreads();
            uint32_t vbase = sb + SA_VT + vb*16384;
#pragma unroll
            for (int sub=0; sub<4; sub++){
                uint32_t Pb  = sb + SA_P + (mb*4+sub)*2048;
                uint32_t Vb2 = vbase + sub*4096;
#pragma unroll
                for (int ksI=0; ksI<2; ksI++){
                    int gk = ksI*2;
                    uint32_t aH[4];
                    ldsm_x4(aH, Pb + swz(q0+lr, gk+lk));
                    uint32_t bHf[2][2];
                    {
                        int n = d0 + (lane>>4)*8 + (lane&7);
                        int g = gk + ((lane>>3)&1);
                        uint32_t tmp[4];
                        ldsm_x4(tmp, Vb2 + swz(n, g));
                        bHf[0][0]=tmp[0]; bHf[0][1]=tmp[1];
                        bHf[1][0]=tmp[2]; bHf[1][1]=tmp[3];
                    }
#pragma unroll
                    for (int nt=0;nt<2;nt++) mma16816(acc2[nt], aH, bHf[nt]);
                }
            }
            vb ^= 1;
            __syncthreads();
        }
        // write attended (fp16)
        {
            int row = q0 + (lane>>2);
#pragma unroll
            for (int nt=0;nt<2;nt++){
                int col = d0 + nt*8 + (lane&3)*2;
                size_t o0 = (size_t)(b*Ss + s0 + row)*Hh + head*64 + col;
                size_t o1 = (size_t)(b*Ss + s0 + row + 8)*Hh + head*64 + col;
                *(__half2*)(ATT + o0) = __half2(__float2half(acc2[nt][0]), __float2half(acc2[nt][1]));
                *(__half2*)(ATT + o1) = __half2(__float2half(acc2[nt][2]), __float2half(acc2[nt][3]));
            }
        }
    }
    __syncthreads();
    for (int i=t;i<32*Mm;i+=256){
        int q = i>>9, m = i&511;
        mem_attn[((size_t)(b*Ss + s0 + q))*Mm + m] = macc[i]*(1.0f/16.0f);
    }
}

// ================= fused gate + layernorm + gated residual =================
__global__ void ln_gate_kernel(
    const float* __restrict__ t2, const float* __restrict__ lng, const float* __restrict__ lnb,
    const float* __restrict__ gg, const float* __restrict__ Wg2, const float* __restrict__ bg2,
    const float* __restrict__ hidden, float* __restrict__ out)
{
    __shared__ float red[8];
    __shared__ float gshare;
    int r = blockIdx.x;
    int t = threadIdx.x;
    const float* row = t2 + (size_t)r*Hh;
    const float* grow = gg + (size_t)r*Hh;
    float x[4];
    float gs = 0.f;
#pragma unroll
    for (int j=0;j<4;j++){
        int idx = t + 256*j;
        x[j] = row[idx];
        gs = fmaf(grow[idx], Wg2[idx], gs);
    }
    // gate reduction
#pragma unroll
    for (int o=16;o;o>>=1) gs += __shfl_xor_sync(0xffffffffu,gs,o);
    if ((t&31)==0) red[t>>5] = gs;
    __syncthreads();
    if (t==0){
        float s = red[0]+red[1]+red[2]+red[3]+red[4]+red[5]+red[6]+red[7];
        gshare = 1.0f/(1.0f + expf(-(s + bg2[0])));
    }
    __syncthreads();
    float gt = gshare;
    // mean
    float s = x[0]+x[1]+x[2]+x[3];
#pragma unroll
    for (int o=16;o;o>>=1) s += __shfl_xor_sync(0xffffffffu,s,o);
    if ((t&31)==0) red[t>>5] = s;
    __syncthreads();
    float mu = (red[0]+red[1]+red[2]+red[3]+red[4]+red[5]+red[6]+red[7]) * (1.0f/Hh);
    __syncthreads();
    float s2 = 0.f;
#pragma unroll
    for (int j=0;j<4;j++){ float d = x[j]-mu; s2 = fmaf(d,d,s2); }
#pragma unroll
    for (int o=16;o;o>>=1) s2 += __shfl_xor_sync(0xffffffffu,s2,o);
    if ((t&31)==0) red[t>>5] = s2;
    __syncthreads();
    float var = (red[0]+red[1]+red[2]+red[3]+red[4]+red[5]+red[6]+red[7]) * (1.0f/Hh);
    float rs = rsqrtf(var + 1e-5f);
    const float* hrow = hidden + (size_t)r*Hh;
#pragma unroll
    for (int j=0;j<4;j++){
        int idx = t + 256*j;
        float f = (x[j]-mu)*rs*lng[idx] + lnb[idx];
        out[(size_t)r*Hh + idx] = gt*f + (1.0f-gt)*hrow[idx];
    }
}

// ================= launch =================
extern "C" void kernel_launch(void* const* d_in, const int* in_sizes, int n_in,
                              void* d_out, int out_size)
{
    (void)in_sizes; (void)n_in; (void)out_size;
    const float* hidden = (const float*)d_in[0];
    const float* memory = (const float*)d_in[1];
    const int*   mask   = (const int*)  d_in[2];
    /* d_in[3] surprise_score: exact algebraic no-op */
    const float* Wq  = (const float*)d_in[4];
    const float* bq  = (const float*)d_in[5];
    const float* Wk  = (const float*)d_in[6];
    const float* bk  = (const float*)d_in[7];
    const float* Wv  = (const float*)d_in[8];
    const float* bv  = (const float*)d_in[9];
    const float* W1  = (const float*)d_in[10];
    const float* b1  = (const float*)d_in[11];
    const float* W2  = (const float*)d_in[12];
    const float* b2  = (const float*)d_in[13];
    const float* lng = (const float*)d_in[14];
    const float* lnb = (const float*)d_in[15];
    const float* Wg1 = (const float*)d_in[16];
    const float* bg1 = (const float*)d_in[17];
    const float* Wg2 = (const float*)d_in[18];
    const float* bg2 = (const float*)d_in[19];

    float *pT2,*pGG;
    cudaGetSymbolAddress((void**)&pT2,  g_t2);
    cudaGetSymbolAddress((void**)&pGG,  g_gg);

    __half *pHs,*pMs,*pQ,*pK,*pVT,*pATT,*pH1;
    cudaGetSymbolAddress((void**)&pHs,  g_Hs);
    cudaGetSymbolAddress((void**)&pMs,  g_Ms);
    cudaGetSymbolAddress((void**)&pQ,   g_Q);
    cudaGetSymbolAddress((void**)&pK,   g_K);
    cudaGetSymbolAddress((void**)&pVT,  g_VT);
    cudaGetSymbolAddress((void**)&pATT, g_ATT);
    cudaGetSymbolAddress((void**)&pH1,  g_H1);

    __half *wq,*wk,*wv,*w1,*w2,*wg1;
    cudaGetSymbolAddress((void**)&wq,  g_WqT);
    cudaGetSymbolAddress((void**)&wk,  g_WkT);
    cudaGetSymbolAddress((void**)&wv,  g_WvT);
    cudaGetSymbolAddress((void**)&w1,  g_W1T);
    cudaGetSymbolAddress((void**)&w2,  g_W2T);
    cudaGetSymbolAddress((void**)&wg1, g_Wg1T);

    float* out      = (float*)d_out;
    float* mem_attn = out + (size_t)ROWS*Hh;

    cudaFuncSetAttribute(gemm_qkv,  cudaFuncAttributeMaxDynamicSharedMemorySize, GEMM_SMEM);
    cudaFuncSetAttribute(gemm_w1g1, cudaFuncAttributeMaxDynamicSharedMemorySize, GEMM_SMEM);
    cudaFuncSetAttribute(gemm_one,  cudaFuncAttributeMaxDynamicSharedMemorySize, GEMM_SMEM);
    cudaFuncSetAttribute(attn_mma,  cudaFuncAttributeMaxDynamicSharedMemorySize, ATT_SMEM);

    // converts (2 launches)
    aconv2<<<4096+256, 256>>>((const float4*)hidden, pHs, (const float4*)memory, pMs);
    wconvT6<<<6656, dim3(32,8)>>>(Wq, wq, Wk, wk, Wv, wv, W1, w1, W2, w2, Wg1, wg1);

    // merged Q/K/V projections (1 launch)
    gemm_qkv<<<768, 256, GEMM_SMEM>>>(pHs, pMs, wq, wk, wv, bq, bk, bv, pQ, pK, pVT);

    // MMA attention
    attn_mma<<<Bb*64, 256, ATT_SMEM>>>(pQ, pK, pVT, mask, pATT, mem_attn);

    // merged W1 + Wg1 (1 launch), then W2
    gemm_w1g1<<<1024, 256, GEMM_SMEM>>>(pHs, pATT, w1, wg1, b1, bg1, pH1, pGG);
    gemm_one<<<dim3(8,64), 256, GEMM_SMEM>>>(pH1, Hh, w2, b2, pT2, (__half*)0, Hh, Hh, 0);

    // fused gate + layernorm + residual mix
    ln_gate_kernel<<<ROWS, 256>>>(pT2, lng, lnb, pGG, Wg2, bg2, hidden, out);
}

// round 14
// speedup vs baseline: 8.8912x; 1.4273x over previous
#include <cuda_runtime.h>
#include <cuda_fp16.h>
#include <math.h>
#include <stdint.h>

#define Bb   4
#define Ss   2048
#define Hh   1024
#define Mm   512
#define NHn  16
#define HDd  64
#define HQq  256
#define ROWS   (Bb*Ss)    /* 8192 */
#define KVROWS (Bb*Mm)    /* 2048 */
#define BIGK   (1<<30)

// ================= helpers =================
__device__ __forceinline__ uint32_t smem_u32(const void* p){
    uint32_t a;
    asm("{ .reg .u64 t; cvta.to.shared.u64 t, %1; cvt.u32.u64 %0, t; }" : "=r"(a) : "l"(p));
    return a;
}
#define CP_ASYNC16(dst, src) \
    asm volatile("cp.async.cg.shared.global [%0], [%1], 16;" :: "r"(dst), "l"(src))
#define CP_COMMIT() asm volatile("cp.async.commit_group;" ::: "memory")
#define CP_WAIT0()  asm volatile("cp.async.wait_group 0;" ::: "memory")
#define CP_WAIT1()  asm volatile("cp.async.wait_group 1;" ::: "memory")
#define CP_WAIT2()  asm volatile("cp.async.wait_group 2;" ::: "memory")

__device__ __forceinline__ void ldsm_x4(uint32_t* r, uint32_t addr){
    asm volatile("ldmatrix.sync.aligned.m8n8.x4.shared.b16 {%0,%1,%2,%3}, [%4];"
        : "=r"(r[0]),"=r"(r[1]),"=r"(r[2]),"=r"(r[3]) : "r"(addr));
}
__device__ __forceinline__ void mma16816(float* d, const uint32_t* a, const uint32_t* b){
    asm volatile("mma.sync.aligned.m16n8k16.row.col.f32.f16.f16.f32 "
        "{%0,%1,%2,%3}, {%4,%5,%6,%7}, {%8,%9}, {%0,%1,%2,%3};"
        : "+f"(d[0]),"+f"(d[1]),"+f"(d[2]),"+f"(d[3])
        : "r"(a[0]),"r"(a[1]),"r"(a[2]),"r"(a[3]), "r"(b[0]),"r"(b[1]));
}

__device__ __forceinline__ float gelu_exact(float x){
    return 0.5f*x*(1.0f + erff(x*0.70710678118654752f));
}

__device__ __forceinline__ uint4 cvt8(float4 x0, float4 x1){
    float f[8] = {x0.x,x0.y,x0.z,x0.w,x1.x,x1.y,x1.z,x1.w};
    uint32_t h[8];
#pragma unroll
    for (int j=0;j<8;j++) h[j] = (uint32_t)__half_as_ushort(__float2half(f[j]));
    return make_uint4(h[0]|(h[1]<<16), h[2]|(h[3]<<16), h[4]|(h[5]<<16), h[6]|(h[7]<<16));
}

// ================= scratch (device globals) =================
__device__ float g_t2 [ROWS*Hh];
__device__ float g_gg [ROWS*Hh];
__device__ __half g_Hs [ROWS*Hh];
__device__ __half g_Ms [KVROWS*HQq];
__device__ __half g_Q  [ROWS*Hh];
__device__ __half g_K  [KVROWS*Hh];
__device__ __half g_VT [Bb*Hh*Mm];
__device__ __half g_ATT[ROWS*Hh];
__device__ __half g_H1 [ROWS*Hh];
__device__ __half g_WqT [1024*1024];
__device__ __half g_WkT [1024*256];
__device__ __half g_WvT [1024*256];
__device__ __half g_W1T [1024*2048];
__device__ __half g_W2T [1024*1024];
__device__ __half g_Wg1T[1024*2048];

// ========== merged activation converts ==========
__global__ void aconv2(const float4* __restrict__ H, __half* __restrict__ Ho,
                       const float4* __restrict__ Mi, __half* __restrict__ Mo)
{
    int bid = blockIdx.x;
    const float4* X; __half* Xh; size_t i;
    if (bid < 4096){ X = H;  Xh = Ho; i = (size_t)bid*256 + threadIdx.x; }
    else           { X = Mi; Xh = Mo; i = (size_t)(bid-4096)*256 + threadIdx.x; }
    *(uint4*)(Xh + 8*i) = cvt8(X[2*i], X[2*i+1]);
}

// ========== merged weight transpose ==========
__global__ void wconvT6(
    const float* __restrict__ Wq,  __half* __restrict__ Tq,
    const float* __restrict__ Wk,  __half* __restrict__ Tk,
    const float* __restrict__ Wv,  __half* __restrict__ Tv,
    const float* __restrict__ W1,  __half* __restrict__ T1,
    const float* __restrict__ W2,  __half* __restrict__ T2,
    const float* __restrict__ Wg1, __half* __restrict__ Tg1)
{
    __shared__ float s[32][33];
    int bid = blockIdx.x;
    const float* W; __half* Th; int K, N, local;
    if      (bid < 1024){ W=Wq;  Th=Tq;  K=1024; N=1024; local=bid; }
    else if (bid < 1280){ W=Wk;  Th=Tk;  K=256;  N=1024; local=bid-1024; }
    else if (bid < 1536){ W=Wv;  Th=Tv;  K=256;  N=1024; local=bid-1280; }
    else if (bid < 3584){ W=W1;  Th=T1;  K=2048; N=1024; local=bid-1536; }
    else if (bid < 4608){ W=W2;  Th=T2;  K=1024; N=1024; local=bid-3584; }
    else               { W=Wg1; Th=Tg1; K=2048; N=1024; local=bid-4608; }
    int nb = N>>5;
    int n0 = (local % nb)*32, k0 = (local / nb)*32;
    int tx = threadIdx.x, ty = threadIdx.y;
#pragma unroll
    for (int i=0;i<4;i++)
        s[ty+i*8][tx] = W[(size_t)(k0+ty+i*8)*N + n0+tx];
    __syncthreads();
#pragma unroll
    for (int i=0;i<4;i++){
        int n = ty + i*8;
        Th[(size_t)(n0+n)*K + k0 + tx] = __float2half(s[tx][n]);
    }
}

// ========== warp-MMA fp16 GEMM body (3-stage pipeline, 2 CTAs/SM) ==========
#define AH_OFF 0
#define BH_OFF 8192
#define BUF_SZ 16384
#define GEMM_SMEM (3*BUF_SZ + 512)

__device__ __forceinline__ uint32_t swz(int row, int g){
    return (uint32_t)(row*64 + ((g ^ ((row>>1)&3))<<4));
}

__device__ __forceinline__ void gemm_body(
    int bm, int bn,
    const __half* __restrict__ A0, int lda0,
    const __half* __restrict__ A1, int lda1, int ks,
    const __half* __restrict__ Bm,
    const float* __restrict__ bias, float* __restrict__ C,
    __half* __restrict__ Ch, int ldc, int K, int mode, char* smem)
{
    uint32_t sb = smem_u32(smem);
    float* bias_s = (float*)(smem + 3*BUF_SZ);

    int t = threadIdx.x, lane = t&31, wid = t>>5;
    int m0 = bm*128, n0 = bn*128;
    int mbase = (wid>>2)*64, nbase = (wid&3)*32;

    if (t < 128) bias_s[t] = bias[n0 + t];

    int nch = K >> 5;
    int ar_r  = t>>1;
    int ar_kh = (t&1)*16;
    int g0    = ar_kh>>3;

    auto stage = [&](int c, uint32_t sbuf){
        int kt = c*32;
        const __half* Ap; int lda, ko;
        if (kt < ks){ Ap = A0; lda = lda0; ko = kt; }
        else        { Ap = A1; lda = lda1; ko = kt - ks; }
        const __half* aH = Ap + (size_t)(m0+ar_r)*lda + ko + ar_kh;
        const __half* bH = Bm + (size_t)(n0+ar_r)*K + kt + ar_kh;
        CP_ASYNC16(sbuf + AH_OFF + swz(ar_r, g0),   aH);
        CP_ASYNC16(sbuf + AH_OFF + swz(ar_r, g0+1), aH+8);
        CP_ASYNC16(sbuf + BH_OFF + swz(ar_r, g0),   bH);
        CP_ASYNC16(sbuf + BH_OFF + swz(ar_r, g0+1), bH+8);
        CP_COMMIT();
    };

    float acc[4][4][4];
#pragma unroll
    for (int i=0;i<4;i++)
#pragma unroll
        for (int j=0;j<4;j++)
#pragma unroll
            for (int e=0;e<4;e++) acc[i][j][e]=0.f;

    stage(0, sb);
    if (nch > 1) stage(1, sb + BUF_SZ);

    int bsel = 0;
    for (int c=0; c<nch; c++){
        uint32_t sbuf = sb + bsel*BUF_SZ;
        if (c+2 < nch){
            int nb = bsel+2; if (nb>=3) nb-=3;
            stage(c+2, sb + nb*BUF_SZ);
            CP_WAIT2();
        } else if (c+1 < nch){
            CP_WAIT1();
        } else {
            CP_WAIT0();
        }
        __syncthreads();

        int lr = lane&15, lk = lane>>4;
#pragma unroll
        for (int ksI=0; ksI<2; ksI++){
            int gk = ksI*2;
            uint32_t aH[4][4];
#pragma unroll
            for (int mt=0;mt<4;mt++){
                int row = mbase + mt*16 + lr;
                ldsm_x4(aH[mt], sbuf + AH_OFF + swz(row, gk+lk));
            }
            uint32_t bHf[4][2];
#pragma unroll
            for (int j=0;j<2;j++){
                int n = nbase + j*16 + (lane>>4)*8 + (lane&7);
                int g = gk + ((lane>>3)&1);
                uint32_t tmp[4];
                ldsm_x4(tmp, sbuf + BH_OFF + swz(n, g));
                bHf[j*2][0]=tmp[0]; bHf[j*2][1]=tmp[1];
                bHf[j*2+1][0]=tmp[2]; bHf[j*2+1][1]=tmp[3];
            }
#pragma unroll
            for (int mt=0;mt<4;mt++)
#pragma unroll
                for (int nt=0;nt<4;nt++) mma16816(acc[mt][nt], aH[mt], bHf[nt]);
        }
        __syncthreads();
        bsel++; if (bsel>=3) bsel=0;
    }

    int actv = (mode==1 || mode==4);
#pragma unroll
    for (int mt=0;mt<4;mt++){
        int r0 = m0 + mbase + mt*16 + (lane>>2);
#pragma unroll
        for (int nt=0;nt<4;nt++){
            int cc = nbase + nt*8 + (lane&3)*2;
            float b0 = bias_s[cc], b1 = bias_s[cc+1];
            float v0 = acc[mt][nt][0] + b0;
            float v1 = acc[mt][nt][1] + b1;
            float v2 = acc[mt][nt][2] + b0;
            float v3 = acc[mt][nt][3] + b1;
            if (actv){ v0=gelu_exact(v0); v1=gelu_exact(v1); v2=gelu_exact(v2); v3=gelu_exact(v3); }
            if (mode <= 1){
                *(float2*)(C + (size_t)r0*ldc     + n0 + cc) = make_float2(v0,v1);
                *(float2*)(C + (size_t)(r0+8)*ldc + n0 + cc) = make_float2(v2,v3);
            } else {
                __half h0=__float2half(v0), h1=__float2half(v1);
                __half h2=__float2half(v2), h3=__float2half(v3);
                if (mode != 3){
                    *(__half2*)(Ch + (size_t)r0*ldc + n0+cc)     = __half2(h0,h1);
                    *(__half2*)(Ch + (size_t)(r0+8)*ldc + n0+cc) = __half2(h2,h3);
                } else {
                    int bb = r0>>9, m = r0&511, col = n0+cc;
                    Ch[((size_t)bb*Hh + col  )*Mm + m  ] = h0;
                    Ch[((size_t)bb*Hh + col+1)*Mm + m  ] = h1;
                    Ch[((size_t)bb*Hh + col  )*Mm + m+8] = h2;
                    Ch[((size_t)bb*Hh + col+1)*Mm + m+8] = h3;
                }
            }
        }
    }
}

__global__ void __launch_bounds__(256,2) gemm_qkv(
    const __half* __restrict__ Hs, const __half* __restrict__ Ms,
    const __half* __restrict__ wq, const __half* __restrict__ wk, const __half* __restrict__ wv,
    const float* __restrict__ bq, const float* __restrict__ bk, const float* __restrict__ bv,
    __half* __restrict__ pQ, __half* __restrict__ pK, __half* __restrict__ pVT)
{
    extern __shared__ __align__(128) char smem[];
    int bid = blockIdx.x;
    const __half *A, *B; const float* bias; __half* Ch;
    int lda, K, mode, bm, bn;
    if (bid < 512){      A=Hs; lda=Hh;  B=wq; bias=bq; Ch=pQ;  K=Hh;  mode=2; bn=bid&7;        bm=bid>>3; }
    else if (bid < 640){ A=Ms; lda=HQq; B=wk; bias=bk; Ch=pK;  K=HQq; mode=2; bn=(bid-512)&7;  bm=(bid-512)>>3; }
    else {               A=Ms; lda=HQq; B=wv; bias=bv; Ch=pVT; K=HQq; mode=3; bn=(bid-640)&7;  bm=(bid-640)>>3; }
    gemm_body(bm, bn, A, lda, (const __half*)0, 0, BIGK, B, bias, (float*)0, Ch, Hh, K, mode, smem);
}

__global__ void __launch_bounds__(256,2) gemm_w1g1(
    const __half* __restrict__ Hs, const __half* __restrict__ ATT,
    const __half* __restrict__ w1, const __half* __restrict__ wg1,
    const float* __restrict__ b1, const float* __restrict__ bg1,
    __half* __restrict__ pH1, float* __restrict__ pGG)
{
    extern __shared__ __align__(128) char smem[];
    int bid = blockIdx.x;
    const __half* B; const float* bias; __half* Ch; float* C; int mode, bm, bn;
    if (bid < 512){ B=w1;  bias=b1;  Ch=pH1; C=(float*)0; mode=4; bn=bid&7;       bm=bid>>3; }
    else          { B=wg1; bias=bg1; Ch=(__half*)0; C=pGG; mode=1; bn=(bid-512)&7; bm=(bid-512)>>3; }
    gemm_body(bm, bn, Hs, Hh, ATT, Hh, Hh, B, bias, C, Ch, Hh, 2*Hh, mode, smem);
}

__global__ void __launch_bounds__(256,2) gemm_one(
    const __half* __restrict__ A0, int lda0,
    const __half* __restrict__ Bm, const float* __restrict__ bias,
    float* __restrict__ C, __half* __restrict__ Ch, int ldc, int K, int mode)
{
    extern __shared__ __align__(128) char smem[];
    gemm_body(blockIdx.y, blockIdx.x, A0, lda0, (const __half*)0, 0, BIGK,
              Bm, bias, C, Ch, ldc, K, mode, smem);
}

// ================= MMA attention (fp16, occ-2, P-in-place) =================
// P: 16 blocks of [32 rows][32 cols] fp16 in ldmatrix-swizzled layout.
// Logits written fp16 by QK epilogue; exp in place (unnormalized); PV consumes
// directly; attended scaled by inv at write; head-mean accumulated straight
// into mem_attn (exclusive per-CTA rows, fp32 rmw, L2-resident).
#define SA_P    0        /* 16*2048 = 32768 */
#define SA_Q    32768    /* 4096 */
#define SA_K    36864    /* 2*16384 = 32768 */
#define SA_VT   69632    /* 2*16384 = 32768 */
#define SA_MSKF 102400   /* 512 floats = 2048 */
#define SA_INV  104448   /* 32 floats = 128 */
#define ATT_SMEM 104960

__global__ void __launch_bounds__(256,2) attn_mma(
    const __half* __restrict__ Qm, const __half* __restrict__ Km,
    const __half* __restrict__ VTm, const int* __restrict__ mask,
    __half* __restrict__ ATT, float* __restrict__ mem_attn)
{
    extern __shared__ __align__(128) char sm8[];
    uint32_t sb = smem_u32(sm8);
    float* mskf = (float*)(sm8 + SA_MSKF);
    float* invs = (float*)(sm8 + SA_INV);

    int b  = blockIdx.x >> 6;
    int s0 = (blockIdx.x & 63) * 32;
    int t  = threadIdx.x, lane = t&31, wid = t>>5;
    int q0 = (wid>>2)*16;
    int nbase = (wid&3)*32;
    int d0 = (wid&3)*16;
    int lr = lane&15, lk = lane>>4;

    for (int i=t;i<Mm;i+=256) mskf[i] = mask[b*Mm + i] ? 1.0f : 0.0f;

    float* maccg = mem_attn + (size_t)(b*Ss + s0)*Mm;   // exclusive [32][512]

    auto loadK = [&](int head, int mc, int kb){
        uint32_t base = sb + SA_K + kb*16384;
#pragma unroll
        for (int i=0;i<4;i++){
            int j = t + i*256;
            int tile = j>>9, rem = j&511;
            int row = rem>>2, g = rem&3;
            const __half* src = Km
                + (size_t)(b*Mm + mc*128 + row)*Hh + head*64 + tile*32 + g*8;
            CP_ASYNC16(base + tile*8192 + swz(row,g), src);
        }
        CP_COMMIT();
    };
    auto loadVT4 = [&](int head, int mb, int vb){
        uint32_t base = sb + SA_VT + vb*16384;
#pragma unroll
        for (int i=0;i<4;i++){
            int j = t + i*256;
            int sub = j>>8, rem = j&255;
            int row = rem>>2, g = rem&3;
            const __half* src = VTm
                + ((size_t)b*Hh + head*64 + row)*Mm + mb*128 + sub*32 + g*8;
            CP_ASYNC16(base + sub*4096 + swz(row,g), src);
        }
        CP_COMMIT();
    };

    for (int head=0; head<NHn; head++){
        __syncthreads();   // P/Q free from previous head
        // Q tiles
        {
            int tile = t>>7, rem = t&127;
            int row = rem>>2, g = rem&3;
            const __half* src = Qm
                + (size_t)(b*Ss + s0 + row)*Hh + head*64 + tile*32 + g*8;
            CP_ASYNC16(sb + SA_Q + tile*2048 + swz(row,g), src);
        }
        CP_COMMIT();
        loadK(head, 0, 0);
        int kb = 0;
        // ---- QK^T -> logits fp16 straight into P layout ----
        for (int mc=0; mc<4; mc++){
            if (mc < 3){ loadK(head, mc+1, kb^1); CP_WAIT1(); } else { CP_WAIT0(); }
            __syncthreads();
            float acc[4][4];
#pragma unroll
            for (int i=0;i<4;i++)
#pragma unroll
                for (int e=0;e<4;e++) acc[i][e]=0.f;
            uint32_t kbase = sb + SA_K + kb*16384;
#pragma unroll
            for (int dc=0; dc<2; dc++){
                uint32_t Qhb = sb + SA_Q + dc*2048;
                uint32_t Khb = kbase + dc*8192;
#pragma unroll
                for (int ksI=0; ksI<2; ksI++){
                    int gk = ksI*2;
                    uint32_t aH[4];
                    ldsm_x4(aH, Qhb + swz(q0+lr, gk+lk));
                    uint32_t bHf[4][2];
#pragma unroll
                    for (int j=0;j<2;j++){
                        int n = nbase + j*16 + (lane>>4)*8 + (lane&7);
                        int g = gk + ((lane>>3)&1);
                        uint32_t tmp[4];
                        ldsm_x4(tmp, Khb + swz(n, g));
                        bHf[j*2][0]=tmp[0]; bHf[j*2][1]=tmp[1];
                        bHf[j*2+1][0]=tmp[2]; bHf[j*2+1][1]=tmp[3];
                    }
#pragma unroll
                    for (int nt=0;nt<4;nt++) mma16816(acc[nt], aH, bHf[nt]);
                }
            }
            // store logits as fp16 into swizzled P blocks
            {
                int row0 = q0 + (lane>>2);
                int row1 = row0 + 8;
                uint32_t base = SA_P + (uint32_t)(mc*4 + (wid&3))*2048 + (lane&3)*4;
#pragma unroll
                for (int nt=0;nt<4;nt++){
                    uint32_t a0 = base + row0*64 + (uint32_t)((nt ^ ((row0>>1)&3))<<4);
                    uint32_t a1 = base + row1*64 + (uint32_t)((nt ^ ((row1>>1)&3))<<4);
                    *(__half2*)(sm8 + a0) = __floats2half2_rn(acc[nt][0]*0.125f, acc[nt][1]*0.125f);
                    *(__half2*)(sm8 + a1) = __floats2half2_rn(acc[nt][2]*0.125f, acc[nt][3]*0.125f);
                }
            }
            kb ^= 1;
            __syncthreads();
        }
        // start VT chunk 0 load; overlaps softmax
        loadVT4(head, 0, 0);
        // ---- softmax: in-place exp (logits bounded, shift-free), warp owns 4 rows ----
#pragma unroll
        for (int rr=0; rr<4; rr++){
            int r = wid*4 + rr;
            float ssum = 0.f;
#pragma unroll
            for (int it=0; it<8; it++){
                int j = lane + it*32;
                uint32_t addr = (uint32_t)SA_P + (uint32_t)(j>>4)*2048 + r*64
                              + (uint32_t)((((j>>2)&3) ^ ((r>>1)&3))<<4) + ((2*j)&7)*2;
                __half2 hv = *(__half2*)(sm8 + addr);
                float e0 = __expf(__low2float(hv))  * mskf[2*j];
                float e1 = __expf(__high2float(hv)) * mskf[2*j+1];
                ssum += e0 + e1;
                *(__half2*)(sm8 + addr) = __floats2half2_rn(e0, e1);
            }
#pragma unroll
            for (int o=16;o;o>>=1) ssum += __shfl_xor_sync(0xffffffffu, ssum, o);
            if (lane==0) invs[r] = 1.0f/ssum;
        }
        __syncthreads();   // exp + inv visible to all warps
        // ---- head-mean accumulate into mem_attn (exclusive fp32 rmw) ----
#pragma unroll
        for (int rr=0; rr<4; rr++){
            int r = wid*4 + rr;
            float inv = invs[r];
            float2* mrow = (float2*)(maccg + (size_t)r*Mm);
#pragma unroll
            for (int it=0; it<8; it++){
                int j = lane + it*32;
                uint32_t addr = (uint32_t)SA_P + (uint32_t)(j>>4)*2048 + r*64
                              + (uint32_t)((((j>>2)&3) ^ ((r>>1)&3))<<4) + ((2*j)&7)*2;
                __half2 hv = *(__half2*)(sm8 + addr);
                float p0 = __low2float(hv)*inv, p1 = __high2float(hv)*inv;
                if (head==0){
                    mrow[j] = make_float2(p0, p1);
                } else if (head==NHn-1){
                    float2 o2 = mrow[j];
                    mrow[j] = make_float2((o2.x+p0)*(1.0f/16.0f), (o2.y+p1)*(1.0f/16.0f));
                } else {
                    float2 o2 = mrow[j];
                    mrow[j] = make_float2(o2.x+p0, o2.y+p1);
                }
            }
        }
        // ---- P @ V (P = unnormalized exp, fp16, already in ldmatrix layout) ----
        float acc2[2][4];
#pragma unroll
        for (int i=0;i<2;i++)
#pragma unroll
            for (int e=0;e<4;e++) acc2[i][e]=0.f;
        int vb = 0;
        for (int mb=0; mb<4; mb++){
            if (mb < 3){ loadVT4(head, mb+1, vb^1); CP_WAIT1(); } else { CP_WAIT0(); }
            __syncthreads();
            uint32_t vbase = sb + SA_VT + vb*16384;
#pragma unroll
            for (int sub=0; sub<4; sub++){
                uint32_t Pb  = sb + SA_P + (mb*4+sub)*2048;
                uint32_t Vb2 = vbase + sub*4096;
#pragma unroll
                for (int ksI=0; ksI<2; ksI++){
                    int gk = ksI*2;
                    uint32_t aH[4];
                    ldsm_x4(aH, Pb + swz(q0+lr, gk+lk));
                    uint32_t bHf[2][2];
                    {
                        int n = d0 + (lane>>4)*8 + (lane&7);
                        int g = gk + ((lane>>3)&1);
                        uint32_t tmp[4];
                        ldsm_x4(tmp, Vb2 + swz(n, g));
                        bHf[0][0]=tmp[0]; bHf[0][1]=tmp[1];
                        bHf[1][0]=tmp[2]; bHf[1][1]=tmp[3];
                    }
#pragma unroll
                    for (int nt=0;nt<2;nt++) mma16816(acc2[nt], aH, bHf[nt]);
                }
            }
            vb ^= 1;
            __syncthreads();
        }
        // write attended (scaled by row inverse), fp16
        {
            int row = q0 + (lane>>2);
            float i0 = invs[row], i1 = invs[row+8];
#pragma unroll
            for (int nt=0;nt<2;nt++){
                int col = d0 + nt*8 + (lane&3)*2;
                size_t o0 = (size_t)(b*Ss + s0 + row)*Hh + head*64 + col;
                size_t o1 = (size_t)(b*Ss + s0 + row + 8)*Hh + head*64 + col;
                *(__half2*)(ATT + o0) = __floats2half2_rn(acc2[nt][0]*i0, acc2[nt][1]*i0);
                *(__half2*)(ATT + o1) = __floats2half2_rn(acc2[nt][2]*i1, acc2[nt][3]*i1);
            }
        }
    }
}

// ================= fused gate + layernorm + gated residual =================
__global__ void ln_gate_kernel(
    const float* __restrict__ t2, const float* __restrict__ lng, const float* __restrict__ lnb,
    const float* __restrict__ gg, const float* __restrict__ Wg2, const float* __restrict__ bg2,
    const float* __restrict__ hidden, float* __restrict__ out)
{
    __shared__ float red[8];
    __shared__ float gshare;
    int r = blockIdx.x;
    int t = threadIdx.x;
    const float* row = t2 + (size_t)r*Hh;
    const float* grow = gg + (size_t)r*Hh;
    float x[4];
    float gs = 0.f;
#pragma unroll
    for (int j=0;j<4;j++){
        int idx = t + 256*j;
        x[j] = row[idx];
        gs = fmaf(grow[idx], Wg2[idx], gs);
    }
#pragma unroll
    for (int o=16;o;o>>=1) gs += __shfl_xor_sync(0xffffffffu,gs,o);
    if ((t&31)==0) red[t>>5] = gs;
    __syncthreads();
    if (t==0){
        float s = red[0]+red[1]+red[2]+red[3]+red[4]+red[5]+red[6]+red[7];
        gshare = 1.0f/(1.0f + expf(-(s + bg2[0])));
    }
    __syncthreads();
    float gt = gshare;
    float s = x[0]+x[1]+x[2]+x[3];
#pragma unroll
    for (int o=16;o;o>>=1) s += __shfl_xor_sync(0xffffffffu,s,o);
    if ((t&31)==0) red[t>>5] = s;
    __syncthreads();
    float mu = (red[0]+red[1]+red[2]+red[3]+red[4]+red[5]+red[6]+red[7]) * (1.0f/Hh);
    __syncthreads();
    float s2 = 0.f;
#pragma unroll
    for (int j=0;j<4;j++){ float d = x[j]-mu; s2 = fmaf(d,d,s2); }
#pragma unroll
    for (int o=16;o;o>>=1) s2 += __shfl_xor_sync(0xffffffffu,s2,o);
    if ((t&31)==0) red[t>>5] = s2;
    __syncthreads();
    float var = (red[0]+red[1]+red[2]+red[3]+red[4]+red[5]+red[6]+red[7]) * (1.0f/Hh);
    float rs = rsqrtf(var + 1e-5f);
    const float* hrow = hidden + (size_t)r*Hh;
#pragma unroll
    for (int j=0;j<4;j++){
        int idx = t + 256*j;
        float f = (x[j]-mu)*rs*lng[idx] + lnb[idx];
        out[(size_t)r*Hh + idx] = gt*f + (1.0f-gt)*hrow[idx];
    }
}

// ================= launch =================
extern "C" void kernel_launch(void* const* d_in, const int* in_sizes, int n_in,
                              void* d_out, int out_size)
{
    (void)in_sizes; (void)n_in; (void)out_size;
    const float* hidden = (const float*)d_in[0];
    const float* memory = (const float*)d_in[1];
    const int*   mask   = (const int*)  d_in[2];
    /* d_in[3] surprise_score: exact algebraic no-op */
    const float* Wq  = (const float*)d_in[4];
    const float* bq  = (const float*)d_in[5];
    const float* Wk  = (const float*)d_in[6];
    const float* bk  = (const float*)d_in[7];
    const float* Wv  = (const float*)d_in[8];
    const float* bv  = (const float*)d_in[9];
    const float* W1  = (const float*)d_in[10];
    const float* b1  = (const float*)d_in[11];
    const float* W2  = (const float*)d_in[12];
    const float* b2  = (const float*)d_in[13];
    const float* lng = (const float*)d_in[14];
    const float* lnb = (const float*)d_in[15];
    const float* Wg1 = (const float*)d_in[16];
    const float* bg1 = (const float*)d_in[17];
    const float* Wg2 = (const float*)d_in[18];
    const float* bg2 = (const float*)d_in[19];

    float *pT2,*pGG;
    cudaGetSymbolAddress((void**)&pT2,  g_t2);
    cudaGetSymbolAddress((void**)&pGG,  g_gg);

    __half *pHs,*pMs,*pQ,*pK,*pVT,*pATT,*pH1;
    cudaGetSymbolAddress((void**)&pHs,  g_Hs);
    cudaGetSymbolAddress((void**)&pMs,  g_Ms);
    cudaGetSymbolAddress((void**)&pQ,   g_Q);
    cudaGetSymbolAddress((void**)&pK,   g_K);
    cudaGetSymbolAddress((void**)&pVT,  g_VT);
    cudaGetSymbolAddress((void**)&pATT, g_ATT);
    cudaGetSymbolAddress((void**)&pH1,  g_H1);

    __half *wq,*wk,*wv,*w1,*w2,*wg1;
    cudaGetSymbolAddress((void**)&wq,  g_WqT);
    cudaGetSymbolAddress((void**)&wk,  g_WkT);
    cudaGetSymbolAddress((void**)&wv,  g_WvT);
    cudaGetSymbolAddress((void**)&w1,  g_W1T);
    cudaGetSymbolAddress((void**)&w2,  g_W2T);
    cudaGetSymbolAddress((void**)&wg1, g_Wg1T);

    float* out      = (float*)d_out;
    float* mem_attn = out + (size_t)ROWS*Hh;

    cudaFuncSetAttribute(gemm_qkv,  cudaFuncAttributeMaxDynamicSharedMemorySize, GEMM_SMEM);
    cudaFuncSetAttribute(gemm_w1g1, cudaFuncAttributeMaxDynamicSharedMemorySize, GEMM_SMEM);
    cudaFuncSetAttribute(gemm_one,  cudaFuncAttributeMaxDynamicSharedMemorySize, GEMM_SMEM);
    cudaFuncSetAttribute(attn_mma,  cudaFuncAttributeMaxDynamicSharedMemorySize, ATT_SMEM);

    aconv2<<<4096+256, 256>>>((const float4*)hidden, pHs, (const float4*)memory, pMs);
    wconvT6<<<6656, dim3(32,8)>>>(Wq, wq, Wk, wk, Wv, wv, W1, w1, W2, w2, Wg1, wg1);

    gemm_qkv<<<768, 256, GEMM_SMEM>>>(pHs, pMs, wq, wk, wv, bq, bk, bv, pQ, pK, pVT);

    attn_mma<<<Bb*64, 256, ATT_SMEM>>>(pQ, pK, pVT, mask, pATT, mem_attn);

    gemm_w1g1<<<1024, 256, GEMM_SMEM>>>(pHs, pATT, w1, wg1, b1, bg1, pH1, pGG);
    gemm_one<<<dim3(8,64), 256, GEMM_SMEM>>>(pH1, Hh, w2, b2, pT2, (__half*)0, Hh, Hh, 0);

    ln_gate_kernel<<<ROWS, 256>>>(pT2, lng, lnb, pGG, Wg2, bg2, hidden, out);
}